// round 12
// baseline (speedup 1.0000x reference)
#include <cuda_runtime.h>
#include <cstdint>
#include <math.h>

#define DIM       1024
#define NHEADS    16
#define HDIM      64
#define BATCH     4
#define SEQ       8192
#define LAT       512
#define SCALE     0.125f   // 64^-0.5

#if defined(__CUDA_ARCH_FEAT_SM103_ALL) || defined(__CUDA_ARCH_FEAT_SM100_ALL) || \
    (defined(__CUDA_ARCH_SPECIFIC__) && (__CUDA_ARCH_SPECIFIC__ >= 1000))
#define HAS_TCGEN05 1
#else
#define HAS_TCGEN05 0
#endif

// -------- scratch (device globals; no allocation allowed) --------
__device__ float g_q  [(size_t)BATCH * LAT * DIM];                    // 8 MB
__device__ float g_kv [(size_t)BATCH * SEQ * 2 * DIM];                // 268 MB (V half unused)
__device__ float g_att[(size_t)BATCH * LAT * DIM];                    // 8 MB
__device__ float g_vt [(size_t)BATCH * NHEADS * HDIM * SEQ];          // 134 MB (V^T, tf32)

// ================= helpers =================
__device__ __forceinline__ uint32_t smem_u32(const void* p) {
    uint32_t a;
    asm("{ .reg .u64 t; cvta.to.shared.u64 t, %1; cvt.u32.u64 %0, t; }"
        : "=r"(a) : "l"(p));
    return a;
}
__device__ __forceinline__ uint32_t f2tf32(float f) {
    uint32_t r;
    asm("cvt.rna.tf32.f32 %0, %1;" : "=r"(r) : "f"(f));
    return r;
}

#if HAS_TCGEN05
__device__ __forceinline__ uint32_t elect_one() {
    uint32_t p;
    asm volatile("{ .reg .pred p; elect.sync _|p, 0xFFFFFFFF; selp.b32 %0,1,0,p; }"
                 : "=r"(p));
    return p;
}

#define MBARRIER_INIT(addr, cnt) \
    asm volatile("mbarrier.init.shared.b64 [%0], %1;" :: "r"(addr), "r"(cnt) : "memory")

#define MBARRIER_WAIT_PARITY(mbar, par) do {                                   \
    uint32_t _m = (mbar); uint32_t _p = (par); uint32_t _done;                 \
    asm volatile("{\n\t.reg .pred p;\n\t"                                      \
        "mbarrier.try_wait.parity.acquire.cta.shared::cta.b64 p, [%1], %2;\n\t"\
        "selp.b32 %0, 1, 0, p;\n\t}"                                           \
        : "=r"(_done) : "r"(_m), "r"(_p) : "memory");                          \
    if (!_done) {                                                              \
        asm volatile("{\n\t.reg .pred P1;\n\t"                                 \
            "WL_%=:\n\t"                                                       \
            "mbarrier.try_wait.parity.acquire.cta.shared::cta.b64 P1, [%0], %1, 0x989680;\n\t" \
            "@P1 bra.uni WD_%=;\n\t"                                           \
            "bra.uni WL_%=;\n\t"                                               \
            "WD_%=:\n\t}"                                                      \
            :: "r"(_m), "r"(_p) : "memory");                                   \
    }                                                                          \
} while (0)

#define TCGEN05_ALLOC(slot, n) \
    asm volatile("tcgen05.alloc.cta_group::1.sync.aligned.shared::cta.b32 [%0], %1;" \
                 :: "r"(slot), "r"(n) : "memory")
#define TCGEN05_DEALLOC(tm, n) \
    asm volatile("tcgen05.dealloc.cta_group::1.sync.aligned.b32 %0, %1;" :: "r"(tm), "r"(n))
#define TCGEN05_RELINQ() \
    asm volatile("tcgen05.relinquish_alloc_permit.cta_group::1.sync.aligned;")
#define TCGEN05_COMMIT(mbar) \
    asm volatile("tcgen05.commit.cta_group::1.mbarrier::arrive::one.shared::cluster.b64 [%0];" \
                 :: "r"(mbar) : "memory")
#define TCGEN05_WAIT_LD() asm volatile("tcgen05.wait::ld.sync.aligned;" ::: "memory")
#define TCGEN05_WAIT_ST() asm volatile("tcgen05.wait::st.sync.aligned;" ::: "memory")
#define TCGEN05_FENCE_AFTER() asm volatile("tcgen05.fence::after_thread_sync;" ::: "memory")
#define TCGEN05_FENCE_BEFORE() asm volatile("tcgen05.fence::before_thread_sync;" ::: "memory")
#define FENCE_ASYNC() asm volatile("fence.proxy.async.shared::cta;" ::: "memory")

#define TCGEN05_LD_X32(r, addr)                                                \
    asm volatile("tcgen05.ld.sync.aligned.32x32b.x32.b32 "                     \
        "{%0,%1,%2,%3,%4,%5,%6,%7,%8,%9,%10,%11,%12,%13,%14,%15,"              \
        "%16,%17,%18,%19,%20,%21,%22,%23,%24,%25,%26,%27,%28,%29,%30,%31}, [%32];" \
        : "=r"((r)[0]),"=r"((r)[1]),"=r"((r)[2]),"=r"((r)[3]),                 \
          "=r"((r)[4]),"=r"((r)[5]),"=r"((r)[6]),"=r"((r)[7]),                 \
          "=r"((r)[8]),"=r"((r)[9]),"=r"((r)[10]),"=r"((r)[11]),               \
          "=r"((r)[12]),"=r"((r)[13]),"=r"((r)[14]),"=r"((r)[15]),             \
          "=r"((r)[16]),"=r"((r)[17]),"=r"((r)[18]),"=r"((r)[19]),             \
          "=r"((r)[20]),"=r"((r)[21]),"=r"((r)[22]),"=r"((r)[23]),             \
          "=r"((r)[24]),"=r"((r)[25]),"=r"((r)[26]),"=r"((r)[27]),             \
          "=r"((r)[28]),"=r"((r)[29]),"=r"((r)[30]),"=r"((r)[31])              \
        : "r"(addr))

#define TCGEN05_ST_X32(addr, r)                                                \
    asm volatile("tcgen05.st.sync.aligned.32x32b.x32.b32 [%0], "               \
        "{%1,%2,%3,%4,%5,%6,%7,%8,%9,%10,%11,%12,%13,%14,%15,%16,"             \
        "%17,%18,%19,%20,%21,%22,%23,%24,%25,%26,%27,%28,%29,%30,%31,%32};"    \
        :: "r"(addr),                                                          \
           "r"((r)[0]),"r"((r)[1]),"r"((r)[2]),"r"((r)[3]),                    \
           "r"((r)[4]),"r"((r)[5]),"r"((r)[6]),"r"((r)[7]),                    \
           "r"((r)[8]),"r"((r)[9]),"r"((r)[10]),"r"((r)[11]),                  \
           "r"((r)[12]),"r"((r)[13]),"r"((r)[14]),"r"((r)[15]),                \
           "r"((r)[16]),"r"((r)[17]),"r"((r)[18]),"r"((r)[19]),                \
           "r"((r)[20]),"r"((r)[21]),"r"((r)[22]),"r"((r)[23]),                \
           "r"((r)[24]),"r"((r)[25]),"r"((r)[26]),"r"((r)[27]),                \
           "r"((r)[28]),"r"((r)[29]),"r"((r)[30]),"r"((r)[31])                 \
        : "memory")

__device__ __forceinline__ void mma_tf32_ss(uint32_t d_tmem, uint64_t a_desc,
                                            uint64_t b_desc, uint32_t idesc,
                                            uint32_t enable) {
    asm volatile(
        "{\n\t.reg .pred p;\n\t"
        "setp.ne.u32 p, %4, 0;\n\t"
        "tcgen05.mma.cta_group::1.kind::tf32 [%0], %1, %2, %3, {%5,%5,%5,%5}, p;\n\t}"
        :: "r"(d_tmem), "l"(a_desc), "l"(b_desc), "r"(idesc), "r"(enable), "r"(0u)
        : "memory");
}
__device__ __forceinline__ void mma_tf32_ts(uint32_t d_tmem, uint32_t a_tmem,
                                            uint64_t b_desc, uint32_t idesc,
                                            uint32_t enable) {
    asm volatile(
        "{\n\t.reg .pred p;\n\t"
        "setp.ne.u32 p, %4, 0;\n\t"
        "tcgen05.mma.cta_group::1.kind::tf32 [%0], [%1], %2, %3, {%5,%5,%5,%5}, p;\n\t}"
        :: "r"(d_tmem), "r"(a_tmem), "l"(b_desc), "r"(idesc), "r"(enable), "r"(0u)
        : "memory");
}
#endif  // HAS_TCGEN05

// SW128 K-major descriptor base: layout=SW128(2), version=1, SBO=64, LBO=1
static constexpr uint64_t DESC_BASE =
    (2ull << 61) | (1ull << 46) | (64ull << 32) | (1ull << 16);

__device__ __forceinline__ uint32_t sw128(uint32_t off) {
    return off ^ ((off >> 3) & 0x70);
}

#define GK 32

// =================================================================
// GEMM (128x128 tile) — small projections. 2 CTAs/SM.
// grid (N/128, M/128). Round-3-proven body + bias.
// =================================================================
#define G128_STAGE 32768                      // A 16K + B 16K
#define GEMM128_SMEM (2 * G128_STAGE + 1024)  // 66.5KB

__global__ __launch_bounds__(256, 2)
void gemm_tc128(const float* __restrict__ A, const float* __restrict__ W,
                float* __restrict__ C, const float* __restrict__ bias,
                int M, int N, int K)
{
#if HAS_TCGEN05
    extern __shared__ char smraw[];
    __shared__ uint64_t mbar[2];
    __shared__ uint32_t tmem_slot;

    const uint32_t smbase = (smem_u32(smraw) + 1023u) & ~1023u;
    const uint32_t bar0 = smem_u32(&mbar[0]);
    const uint32_t bar1 = smem_u32(&mbar[1]);
    const uint32_t slot = smem_u32(&tmem_slot);

    const int tid = threadIdx.x;
    const int wid = tid >> 5;
    const int lid = tid & 31;
    const int m0 = blockIdx.y * 128;
    const int n0 = blockIdx.x * 128;

    if (wid == 0) TCGEN05_ALLOC(slot, 128);
    if (tid == 0) { MBARRIER_INIT(bar0, 1); MBARRIER_INIT(bar1, 1); }
    __syncthreads();
    uint32_t tmem;
    asm volatile("ld.shared.b32 %0, [%1];" : "=r"(tmem) : "r"(slot));
    if (wid == 0) TCGEN05_RELINQ();

    const uint32_t IDESC = (1u << 4) | (2u << 7) | (2u << 10)
                         | ((128u / 8) << 17) | ((128u / 16) << 24);

    const int NC = K / GK;
    int ph0 = 0, ph1 = 0;

    for (int c = 0; c < NC; c++) {
        const int buf = c & 1;
        const uint32_t barb = buf ? bar1 : bar0;
        if (c >= 2) {
            MBARRIER_WAIT_PARITY(barb, (buf ? ph1 : ph0));
            if (buf) ph1 ^= 1; else ph0 ^= 1;
        }
        const uint32_t sb = smbase + buf * G128_STAGE;
        const float* Ap = A + (size_t)m0 * K + c * GK;
        const float* Wp = W + (size_t)n0 * K + c * GK;

#pragma unroll
        for (int it = 0; it < 4; it++) {
            int i = tid + it * 256;            // 0..1023
            int row = i >> 3, fo = i & 7;
            float4 v = *(const float4*)(Ap + (size_t)row * K + fo * 4);
            uint32_t r0 = f2tf32(v.x), r1 = f2tf32(v.y),
                     r2 = f2tf32(v.z), r3 = f2tf32(v.w);
            uint32_t dst = sb + sw128((uint32_t)(row * 128 + fo * 16));
            asm volatile("st.shared.v4.b32 [%0], {%1,%2,%3,%4};"
                         :: "r"(dst), "r"(r0), "r"(r1), "r"(r2), "r"(r3) : "memory");
        }
#pragma unroll
        for (int it = 0; it < 4; it++) {
            int i = tid + it * 256;
            int row = i >> 3, fo = i & 7;
            float4 v = *(const float4*)(Wp + (size_t)row * K + fo * 4);
            uint32_t r0 = f2tf32(v.x), r1 = f2tf32(v.y),
                     r2 = f2tf32(v.z), r3 = f2tf32(v.w);
            uint32_t dst = sb + 16384u + sw128((uint32_t)(row * 128 + fo * 16));
            asm volatile("st.shared.v4.b32 [%0], {%1,%2,%3,%4};"
                         :: "r"(dst), "r"(r0), "r"(r1), "r"(r2), "r"(r3) : "memory");
        }
        __syncthreads();

        if (wid == 0 && elect_one()) {
            FENCE_ASYNC();
            const uint64_t dA = DESC_BASE | ((uint64_t)(sb >> 4) & 0x3FFF);
            const uint64_t dB = DESC_BASE | ((uint64_t)((sb + 16384u) >> 4) & 0x3FFF);
#pragma unroll
            for (int k = 0; k < 4; k++) {
                uint32_t en = (c > 0 || k > 0) ? 1u : 0u;
                mma_tf32_ss(tmem, dA + k * 2, dB + k * 2, IDESC, en);
            }
            TCGEN05_COMMIT(barb);
        }
    }

    MBARRIER_WAIT_PARITY(bar0, ph0);
    MBARRIER_WAIT_PARITY(bar1, ph1);
    TCGEN05_FENCE_AFTER();

    // epilogue: warp w -> rows (w&3)*32+lid, col half (w>>2)*64
    {
        const int colh = wid >> 2;
        const int sub  = wid & 3;
        const int r = sub * 32 + lid;
        float* Crow = C + (size_t)(m0 + r) * N + n0 + colh * 64;
        const float* bp = bias ? (bias + n0 + colh * 64) : nullptr;
#pragma unroll
        for (int half = 0; half < 2; half++) {
            uint32_t rr[32];
            TCGEN05_LD_X32(rr, tmem + colh * 64 + half * 32);
            TCGEN05_WAIT_LD();
#pragma unroll
            for (int j = 0; j < 32; j += 4) {
                float4 o;
                o.x = __uint_as_float(rr[j + 0]);
                o.y = __uint_as_float(rr[j + 1]);
                o.z = __uint_as_float(rr[j + 2]);
                o.w = __uint_as_float(rr[j + 3]);
                if (bp) {
                    o.x += bp[half * 32 + j + 0]; o.y += bp[half * 32 + j + 1];
                    o.z += bp[half * 32 + j + 2]; o.w += bp[half * 32 + j + 3];
                }
                *(float4*)(Crow + half * 32 + j) = o;
            }
        }
    }
    TCGEN05_FENCE_BEFORE();
    __syncthreads();
    if (wid == 0) TCGEN05_DEALLOC(tmem, 128);

#else
    // SIMT fallback (proven round-1 128x128 body)
    __shared__ float As[8][128];
    __shared__ float Ws[8][128];
    const int tid  = threadIdx.x;
    const int ty   = tid >> 4;
    const int tx   = tid & 15;
    const int row0 = blockIdx.y * 128;
    const int col0 = blockIdx.x * 128;
    const int lrow = tid >> 1;
    const int lk   = (tid & 1) * 4;

    const float* Ap = A + (size_t)(row0 + lrow) * K + lk;
    const float* Wp = W + (size_t)(col0 + lrow) * K + lk;
    float acc[8][8];
#pragma unroll
    for (int i = 0; i < 8; i++)
#pragma unroll
        for (int j = 0; j < 8; j++) acc[i][j] = 0.0f;

    for (int k0 = 0; k0 < K; k0 += 8) {
        float4 av = *(const float4*)(Ap + k0);
        float4 wv = *(const float4*)(Wp + k0);
        As[lk + 0][lrow] = av.x; As[lk + 1][lrow] = av.y;
        As[lk + 2][lrow] = av.z; As[lk + 3][lrow] = av.w;
        Ws[lk + 0][lrow] = wv.x; Ws[lk + 1][lrow] = wv.y;
        Ws[lk + 2][lrow] = wv.z; Ws[lk + 3][lrow] = wv.w;
        __syncthreads();
#pragma unroll
        for (int k = 0; k < 8; k++) {
            float a[8], b[8];
            float4 t0 = *(const float4*)(&As[k][ty * 8 + 0]);
            float4 t1 = *(const float4*)(&As[k][ty * 8 + 4]);
            a[0]=t0.x;a[1]=t0.y;a[2]=t0.z;a[3]=t0.w;a[4]=t1.x;a[5]=t1.y;a[6]=t1.z;a[7]=t1.w;
            float4 u0 = *(const float4*)(&Ws[k][tx * 8 + 0]);
            float4 u1 = *(const float4*)(&Ws[k][tx * 8 + 4]);
            b[0]=u0.x;b[1]=u0.y;b[2]=u0.z;b[3]=u0.w;b[4]=u1.x;b[5]=u1.y;b[6]=u1.z;b[7]=u1.w;
#pragma unroll
            for (int i = 0; i < 8; i++)
#pragma unroll
                for (int j = 0; j < 8; j++) acc[i][j] += a[i] * b[j];
        }
        __syncthreads();
    }
#pragma unroll
    for (int i = 0; i < 8; i++) {
        const size_t r = (size_t)(row0 + ty * 8 + i);
#pragma unroll
        for (int j = 0; j < 8; j++) {
            const int cc = col0 + tx * 8 + j;
            float v = acc[i][j];
            if (bias) v += bias[cc];
            C[r * N + cc] = v;
        }
    }
#endif
}

// =================================================================
// GEMM (256x128 tile) — kv projection, fused V^T epilogue. 2 CTAs/SM.
// grid (N/128, M/256). Two M=128 atoms share one 128-row B tile.
// =================================================================
#define GKV_STAGE 49152                       // A0 16K + A1 16K + B 16K
#define GEMMKV_SMEM (2 * GKV_STAGE + 1024)    // 97.3KB

__global__ __launch_bounds__(256, 2)
void gemm_tc_kv(const float* __restrict__ A, const float* __restrict__ W,
                float* __restrict__ C, float* __restrict__ vtb,
                int M, int N, int K)
{
#if HAS_TCGEN05
    extern __shared__ char smraw[];
    __shared__ uint64_t mbar[2];
    __shared__ uint32_t tmem_slot;

    const uint32_t smbase = (smem_u32(smraw) + 1023u) & ~1023u;
    const uint32_t bar0 = smem_u32(&mbar[0]);
    const uint32_t bar1 = smem_u32(&mbar[1]);
    const uint32_t slot = smem_u32(&tmem_slot);

    const int tid = threadIdx.x;
    const int wid = tid >> 5;
    const int lid = tid & 31;
    const int m0 = blockIdx.y * 256;
    const int n0 = blockIdx.x * 128;

    if (wid == 0) TCGEN05_ALLOC(slot, 256);
    if (tid == 0) { MBARRIER_INIT(bar0, 1); MBARRIER_INIT(bar1, 1); }
    __syncthreads();
    uint32_t tmem;
    asm volatile("ld.shared.b32 %0, [%1];" : "=r"(tmem) : "r"(slot));
    if (wid == 0) TCGEN05_RELINQ();

    const uint32_t IDESC = (1u << 4) | (2u << 7) | (2u << 10)
                         | ((128u / 8) << 17) | ((128u / 16) << 24);

    const int NC = K / GK;
    int ph0 = 0, ph1 = 0;

    for (int c = 0; c < NC; c++) {
        const int buf = c & 1;
        const uint32_t barb = buf ? bar1 : bar0;
        if (c >= 2) {
            MBARRIER_WAIT_PARITY(barb, (buf ? ph1 : ph0));
            if (buf) ph1 ^= 1; else ph0 ^= 1;
        }
        const uint32_t sb = smbase + buf * GKV_STAGE;
        const float* Ap = A + (size_t)m0 * K + c * GK;
        const float* Wp = W + (size_t)n0 * K + c * GK;

        // A: 256 rows -> A0 (rows<128) @0 / A1 @16K
#pragma unroll
        for (int it = 0; it < 8; it++) {
            int i = tid + it * 256;            // 0..2047
            int row = i >> 3, fo = i & 7;
            float4 v = *(const float4*)(Ap + (size_t)row * K + fo * 4);
            uint32_t r0 = f2tf32(v.x), r1 = f2tf32(v.y),
                     r2 = f2tf32(v.z), r3 = f2tf32(v.w);
            uint32_t off = sw128((uint32_t)((row & 127) * 128 + fo * 16));
            uint32_t dst = sb + ((row < 128) ? 0u : 16384u) + off;
            asm volatile("st.shared.v4.b32 [%0], {%1,%2,%3,%4};"
                         :: "r"(dst), "r"(r0), "r"(r1), "r"(r2), "r"(r3) : "memory");
        }
        // B: 128 rows @32K
#pragma unroll
        for (int it = 0; it < 4; it++) {
            int i = tid + it * 256;            // 0..1023
            int row = i >> 3, fo = i & 7;
            float4 v = *(const float4*)(Wp + (size_t)row * K + fo * 4);
            uint32_t r0 = f2tf32(v.x), r1 = f2tf32(v.y),
                     r2 = f2tf32(v.z), r3 = f2tf32(v.w);
            uint32_t dst = sb + 32768u + sw128((uint32_t)(row * 128 + fo * 16));
            asm volatile("st.shared.v4.b32 [%0], {%1,%2,%3,%4};"
                         :: "r"(dst), "r"(r0), "r"(r1), "r"(r2), "r"(r3) : "memory");
        }
        __syncthreads();

        if (wid == 0 && elect_one()) {
            FENCE_ASYNC();
            const uint64_t dA0 = DESC_BASE | ((uint64_t)(sb >> 4) & 0x3FFF);
            const uint64_t dA1 = DESC_BASE | ((uint64_t)((sb + 16384u) >> 4) & 0x3FFF);
            const uint64_t dB  = DESC_BASE | ((uint64_t)((sb + 32768u) >> 4) & 0x3FFF);
#pragma unroll
            for (int k = 0; k < 4; k++) {
                uint32_t en = (c > 0 || k > 0) ? 1u : 0u;
                mma_tf32_ss(tmem,       dA0 + k * 2, dB + k * 2, IDESC, en);
                mma_tf32_ss(tmem + 128, dA1 + k * 2, dB + k * 2, IDESC, en);
            }
            TCGEN05_COMMIT(barb);
        }
    }

    MBARRIER_WAIT_PARITY(bar0, ph0);
    MBARRIER_WAIT_PARITY(bar1, ph1);
    TCGEN05_FENCE_AFTER();

    // epilogue: warps 0-3 -> atom0 rows, warps 4-7 -> atom1 rows; 128 cols each
    {
        const int tile = wid >> 2;
        const uint32_t dbase = tmem + tile * 128;
        const int rowl = (wid & 3) * 32 + lid;
        const size_t grow = (size_t)m0 + tile * 128 + rowl;    // global row = b*SEQ + s

        if (vtb && n0 >= DIM) {
            // V tile: write ONLY transposed tf32 into vtb (coalesced over s)
            const int s  = (int)(grow & (SEQ - 1));
            const int bq = (int)(grow >> 13);
            const size_t vb0 = (size_t)bq * NHEADS * HDIM;
#pragma unroll
            for (int cb = 0; cb < 4; cb++) {
                uint32_t rr[32];
                TCGEN05_LD_X32(rr, dbase + cb * 32);
                TCGEN05_WAIT_LD();
#pragma unroll
                for (int j = 0; j < 32; j++) {
                    const int dcol = (n0 - DIM) + cb * 32 + j;
                    vtb[(vb0 + (size_t)dcol) * SEQ + s] =
                        __uint_as_float(f2tf32(__uint_as_float(rr[j])));
                }
            }
        } else {
            float* Crow = C + grow * N + n0;
#pragma unroll
            for (int cb = 0; cb < 4; cb++) {
                uint32_t rr[32];
                TCGEN05_LD_X32(rr, dbase + cb * 32);
                TCGEN05_WAIT_LD();
#pragma unroll
                for (int j = 0; j < 32; j += 4) {
                    float4 o;
                    o.x = __uint_as_float(rr[j + 0]);
                    o.y = __uint_as_float(rr[j + 1]);
                    o.z = __uint_as_float(rr[j + 2]);
                    o.w = __uint_as_float(rr[j + 3]);
                    *(float4*)(Crow + cb * 32 + j) = o;
                }
            }
        }
    }
    TCGEN05_FENCE_BEFORE();
    __syncthreads();
    if (wid == 0) TCGEN05_DEALLOC(tmem, 256);

#else
    // SIMT fallback: two 128x128 subtiles (hm = atom)
    __shared__ float As[8][128];
    __shared__ float Ws[8][128];
    const int tid  = threadIdx.x;
    const int ty   = tid >> 4;
    const int tx   = tid & 15;
    const int lrow = tid >> 1;
    const int lk   = (tid & 1) * 4;
    const int col0 = blockIdx.x * 128;

    for (int hm = 0; hm < 2; hm++) {
        const int row0 = blockIdx.y * 256 + hm * 128;
        const float* Ap = A + (size_t)(row0 + lrow) * K + lk;
        const float* Wp = W + (size_t)(col0 + lrow) * K + lk;
        float acc[8][8];
#pragma unroll
        for (int i = 0; i < 8; i++)
#pragma unroll
            for (int j = 0; j < 8; j++) acc[i][j] = 0.0f;

        for (int k0 = 0; k0 < K; k0 += 8) {
            float4 av = *(const float4*)(Ap + k0);
            float4 wv = *(const float4*)(Wp + k0);
            As[lk + 0][lrow] = av.x; As[lk + 1][lrow] = av.y;
            As[lk + 2][lrow] = av.z; As[lk + 3][lrow] = av.w;
            Ws[lk + 0][lrow] = wv.x; Ws[lk + 1][lrow] = wv.y;
            Ws[lk + 2][lrow] = wv.z; Ws[lk + 3][lrow] = wv.w;
            __syncthreads();
#pragma unroll
            for (int k = 0; k < 8; k++) {
                float a[8], b[8];
                float4 t0 = *(const float4*)(&As[k][ty * 8 + 0]);
                float4 t1 = *(const float4*)(&As[k][ty * 8 + 4]);
                a[0]=t0.x;a[1]=t0.y;a[2]=t0.z;a[3]=t0.w;a[4]=t1.x;a[5]=t1.y;a[6]=t1.z;a[7]=t1.w;
                float4 u0 = *(const float4*)(&Ws[k][tx * 8 + 0]);
                float4 u1 = *(const float4*)(&Ws[k][tx * 8 + 4]);
                b[0]=u0.x;b[1]=u0.y;b[2]=u0.z;b[3]=u0.w;b[4]=u1.x;b[5]=u1.y;b[6]=u1.z;b[7]=u1.w;
#pragma unroll
                for (int i = 0; i < 8; i++)
#pragma unroll
                    for (int j = 0; j < 8; j++) acc[i][j] += a[i] * b[j];
            }
            __syncthreads();
        }
#pragma unroll
        for (int i = 0; i < 8; i++) {
            const size_t grow = (size_t)(row0 + ty * 8 + i);
#pragma unroll
            for (int j = 0; j < 8; j++) {
                const int cc = col0 + tx * 8 + j;
                if (vtb && cc >= DIM) {
                    const int s  = (int)(grow & (SEQ - 1));
                    const int bq = (int)(grow >> 13);
                    vtb[((size_t)bq * NHEADS * HDIM + (cc - DIM)) * SEQ + s] =
                        __uint_as_float(f2tf32(acc[i][j]));
                } else {
                    C[grow * N + cc] = acc[i][j];
                }
            }
        }
        __syncthreads();
    }
#endif
}

// =================================================================
// Tensor-core flash attention — round-9 version (proven 251us).
// 2 CTAs/SM (97KB smem, 256 TMEM cols). S->P in-place in TMEM.
// smem: Q 32K | K 32K | VT 32K   TMEM: SP @+0 (128), O @+128 (64)
// =================================================================
#define SCHUNK 128
#define NCH (SEQ / SCHUNK)
#define ATTN_SMEM (3 * 32768 + 1024)
#define SCALE_L2E 0.18033688011112042f   // SCALE * log2(e)

__global__ __launch_bounds__(256, 2)
void attn_tc(const float* __restrict__ q, const float* __restrict__ kv,
             const float* __restrict__ vt, float* __restrict__ out)
{
#if HAS_TCGEN05
    extern __shared__ char smraw[];
    __shared__ uint64_t mbar[2];
    __shared__ uint32_t tmem_slot;
    __shared__ float ls_sh[256];

    const uint32_t smbase = (smem_u32(smraw) + 1023u) & ~1023u;
    const uint32_t QS = smbase;
    const uint32_t KS = smbase + 32768u;
    const uint32_t VS = smbase + 65536u;
    const uint32_t barQK = smem_u32(&mbar[0]);
    const uint32_t barPV = smem_u32(&mbar[1]);
    const uint32_t slot  = smem_u32(&tmem_slot);

    const int tid = threadIdx.x;
    const int wid = tid >> 5;
    const int lid = tid & 31;
    const int bh  = blockIdx.x >> 2;
    const int lt  = blockIdx.x & 3;
    const int b   = bh >> 4, h = bh & 15;
    const int l0  = lt * 128;

    if (wid == 0) TCGEN05_ALLOC(slot, 256);
    if (tid == 0) { MBARRIER_INIT(barQK, 1); MBARRIER_INIT(barPV, 1); }
    __syncthreads();
    uint32_t tmem;
    asm volatile("ld.shared.b32 %0, [%1];" : "=r"(tmem) : "r"(slot));
    if (wid == 0) TCGEN05_RELINQ();
    const uint32_t tmem_SP = tmem;           // S and P share these 128 cols
    const uint32_t tmem_O  = tmem + 128;

    const uint32_t IDESC_S = (1u << 4) | (2u << 7) | (2u << 10)
                           | ((128u / 8) << 17) | ((128u / 16) << 24);
    const uint32_t IDESC_O = (1u << 4) | (2u << 7) | (2u << 10)
                           | ((64u / 8) << 17) | ((128u / 16) << 24);

    const float* kbase = kv + (size_t)b * SEQ * (2 * DIM) + h * HDIM;
    const float* vbase = vt + ((size_t)bh * HDIM) * SEQ;

    // ---- load Q (scaled by SCALE*log2e) ----
    const float* qbase = q + ((size_t)b * LAT + l0) * DIM + h * HDIM;
#pragma unroll
    for (int it = 0; it < 8; it++) {
        int i = tid + it * 256;
        int row = i >> 4, f = i & 15;
        int kc = f >> 3, fo = f & 7;
        float4 v = *(const float4*)(qbase + (size_t)row * DIM + f * 4);
        uint32_t r0 = f2tf32(v.x * SCALE_L2E), r1 = f2tf32(v.y * SCALE_L2E);
        uint32_t r2 = f2tf32(v.z * SCALE_L2E), r3 = f2tf32(v.w * SCALE_L2E);
        uint32_t dst = QS + kc * 16384u + sw128((uint32_t)(row * 128 + fo * 16));
        asm volatile("st.shared.v4.b32 [%0], {%1,%2,%3,%4};"
                     :: "r"(dst), "r"(r0), "r"(r1), "r"(r2), "r"(r3) : "memory");
    }

    auto loadK = [&](int ci) {
        const int s0 = ci * SCHUNK;
#pragma unroll
        for (int it = 0; it < 8; it++) {
            int i = tid + it * 256;
            int kr = i >> 4, f = i & 15;
            int kc = f >> 3, fo = f & 7;
            float4 v = *(const float4*)(kbase + (size_t)(s0 + kr) * (2 * DIM) + f * 4);
            uint32_t r0 = f2tf32(v.x), r1 = f2tf32(v.y),
                     r2 = f2tf32(v.z), r3 = f2tf32(v.w);
            uint32_t dst = KS + kc * 16384u + sw128((uint32_t)(kr * 128 + fo * 16));
            asm volatile("st.shared.v4.b32 [%0], {%1,%2,%3,%4};"
                         :: "r"(dst), "r"(r0), "r"(r1), "r"(r2), "r"(r3) : "memory");
        }
    };
    auto loadVT = [&](int ci) {
        const int s0 = ci * SCHUNK;
#pragma unroll
        for (int it = 0; it < 8; it++) {
            int i = tid + it * 256;
            int d = i >> 5, f = i & 31;
            int sc = f >> 3, fo = f & 7;
            float4 v = *(const float4*)(vbase + (size_t)d * SEQ + s0 + f * 4);
            uint32_t dst = VS + sc * 8192u + sw128((uint32_t)(d * 128 + fo * 16));
            asm volatile("st.shared.v4.b32 [%0], {%1,%2,%3,%4};"
                         :: "r"(dst), "r"(__float_as_uint(v.x)), "r"(__float_as_uint(v.y)),
                            "r"(__float_as_uint(v.z)), "r"(__float_as_uint(v.w)) : "memory");
        }
    };

    const uint64_t dQ0 = DESC_BASE | ((uint64_t)(QS >> 4) & 0x3FFF);
    const uint64_t dQ1 = DESC_BASE | ((uint64_t)((QS + 16384u) >> 4) & 0x3FFF);
    const uint64_t dK0 = DESC_BASE | ((uint64_t)(KS >> 4) & 0x3FFF);
    const uint64_t dK1 = DESC_BASE | ((uint64_t)((KS + 16384u) >> 4) & 0x3FFF);

    float lsum = 0.0f;
    int phQK = 0, phPV = 0;

    loadK(0);
    loadVT(0);
    __syncthreads();

    for (int ci = 0; ci < NCH; ci++) {
        // ---- QK(ci) ----
        if (wid == 0 && elect_one()) {
            FENCE_ASYNC();
#pragma unroll
            for (int blk = 0; blk < 2; blk++) {
                const uint64_t dq = blk ? dQ1 : dQ0;
                const uint64_t dk = blk ? dK1 : dK0;
#pragma unroll
                for (int ks = 0; ks < 4; ks++)
                    mma_tf32_ss(tmem_SP, dq + ks * 2, dk + ks * 2, IDESC_S,
                                (blk > 0 || ks > 0) ? 1u : 0u);
            }
            TCGEN05_COMMIT(barQK);
        }
        MBARRIER_WAIT_PARITY(barQK, phQK); phQK ^= 1;
        TCGEN05_FENCE_AFTER();

        // ---- softmax in place ----
        {
            const uint32_t colofs = (uint32_t)(wid >> 2) * 64u;
            const uint32_t wlane  = (uint32_t)(wid & 3) << 21;
#pragma unroll
            for (int blk = 0; blk < 2; blk++) {
                uint32_t rr[32];
                TCGEN05_LD_X32(rr, tmem_SP + colofs + blk * 32);
                TCGEN05_WAIT_LD();
#pragma unroll
                for (int j = 0; j < 32; j++) {
                    float p;
                    asm("ex2.approx.f32 %0, %1;" : "=f"(p) : "f"(__uint_as_float(rr[j])));
                    lsum += p;
                    rr[j] = f2tf32(p);
                }
                TCGEN05_ST_X32(tmem_SP + wlane + colofs + blk * 32, rr);
            }
            TCGEN05_WAIT_ST();
        }
        TCGEN05_FENCE_BEFORE();
        __syncthreads();

        // ---- PV(ci) ----
        if (wid == 0 && elect_one()) {
            TCGEN05_FENCE_AFTER();
            FENCE_ASYNC();
#pragma unroll
            for (int st = 0; st < 16; st++) {
                const uint64_t dV = DESC_BASE
                    | ((uint64_t)((VS + (st >> 2) * 8192u) >> 4) & 0x3FFF);
                mma_tf32_ts(tmem_O, tmem_SP + st * 8, dV + (st & 3) * 2, IDESC_O,
                            (ci > 0 || st > 0) ? 1u : 0u);
            }
            TCGEN05_COMMIT(barPV);
        }

        if (ci + 1 < NCH) loadK(ci + 1);
        MBARRIER_WAIT_PARITY(barPV, phPV); phPV ^= 1;
        if (ci + 1 < NCH) loadVT(ci + 1);
        __syncthreads();
    }

    TCGEN05_FENCE_AFTER();

    ls_sh[tid] = lsum;
    __syncthreads();

    if (wid < 4) {
        const int r = wid * 32 + lid;
        const float inv = 1.0f / (ls_sh[tid] + ls_sh[tid + 128]);
        float* op = out + ((size_t)b * LAT + l0 + r) * DIM + h * HDIM;
#pragma unroll
        for (int cb = 0; cb < 2; cb++) {
            uint32_t rr[32];
            TCGEN05_LD_X32(rr, tmem_O + cb * 32);
            TCGEN05_WAIT_LD();
#pragma unroll
            for (int j = 0; j < 32; j += 4) {
                float4 o;
                o.x = __uint_as_float(rr[j + 0]) * inv;
                o.y = __uint_as_float(rr[j + 1]) * inv;
                o.z = __uint_as_float(rr[j + 2]) * inv;
                o.w = __uint_as_float(rr[j + 3]) * inv;
                *(float4*)(op + cb * 32 + j) = o;
            }
        }
    }
    TCGEN05_FENCE_BEFORE();
    __syncthreads();
    if (wid == 0) TCGEN05_DEALLOC(tmem, 256);

#else
    // SIMT fallback (thread-per-row; never runs on GB300)
    const int tid = threadIdx.x;
    const int bh  = blockIdx.x >> 2;
    const int lt  = blockIdx.x & 3;
    const int b   = bh >> 4, h = bh & 15;
    const int l0  = lt * 128;
    if (tid < 128) {
        const float* qrow = q + ((size_t)b * LAT + l0 + tid) * DIM + h * HDIM;
        const float* kb = kv + (size_t)b * SEQ * (2 * DIM) + h * HDIM;
        const float* vb = vt + ((size_t)bh * HDIM) * SEQ;
        float qr[64];
#pragma unroll
        for (int d = 0; d < 64; d++) qr[d] = qrow[d] * SCALE;
        float O[64];
#pragma unroll
        for (int d = 0; d < 64; d++) O[d] = 0.0f;
        float l = 0.0f;
        for (int s = 0; s < SEQ; s++) {
            const float* kr = kb + (size_t)s * (2 * DIM);
            float sv = 0.0f;
#pragma unroll 16
            for (int d = 0; d < 64; d++) sv += qr[d] * kr[d];
            float p = __expf(sv);
            l += p;
#pragma unroll 16
            for (int d = 0; d < 64; d++) O[d] += p * vb[(size_t)d * SEQ + s];
        }
        float* op = out + ((size_t)b * LAT + l0 + tid) * DIM + h * HDIM;
        float inv = 1.0f / l;
#pragma unroll
        for (int d = 0; d < 64; d++) op[d] = O[d] * inv;
    }
#endif
}

// =================================================================
// launch
// =================================================================
extern "C" void kernel_launch(void* const* d_in, const int* in_sizes, int n_in,
                              void* d_out, int out_size)
{
    const float* x       = (const float*)d_in[0];
    const float* latents = (const float*)d_in[1];
    if (in_sizes[0] != BATCH * SEQ * DIM) {
        x       = (const float*)d_in[1];
        latents = (const float*)d_in[0];
    }
    const float* w_q   = (const float*)d_in[2];
    const float* w_kv  = (const float*)d_in[3];
    const float* w_out = (const float*)d_in[4];
    const float* b_out = (const float*)d_in[5];
    float* out = (float*)d_out;

    float *q, *kvbuf, *att, *vt;
    cudaGetSymbolAddress((void**)&q,     g_q);
    cudaGetSymbolAddress((void**)&kvbuf, g_kv);
    cudaGetSymbolAddress((void**)&att,   g_att);
    cudaGetSymbolAddress((void**)&vt,    g_vt);

    const int M_q  = BATCH * LAT;    // 2048
    const int M_kv = BATCH * SEQ;    // 32768

    cudaFuncSetAttribute(gemm_tc128, cudaFuncAttributeMaxDynamicSharedMemorySize, GEMM128_SMEM);
    cudaFuncSetAttribute(gemm_tc_kv, cudaFuncAttributeMaxDynamicSharedMemorySize, GEMMKV_SMEM);
    cudaFuncSetAttribute(attn_tc,    cudaFuncAttributeMaxDynamicSharedMemorySize, ATTN_SMEM);

    // 1) q = latents @ w_q^T        (2048 x 1024), 128 CTAs, 2/SM
    gemm_tc128<<<dim3(DIM / 128, M_q / 128), 256, GEMM128_SMEM>>>(
        latents, w_q, q, nullptr, M_q, DIM, DIM);
    // 2) kv = x @ w_kv^T            (32768 x 2048), 2048 CTAs, 2/SM;
    //    V half goes straight to vt (tf32, transposed)
    gemm_tc_kv<<<dim3(2 * DIM / 128, M_kv / 256), 256, GEMMKV_SMEM>>>(
        x, w_kv, kvbuf, vt, M_kv, 2 * DIM, DIM);
    // 3) attention
    attn_tc<<<BATCH * NHEADS * (LAT / 128), 256, ATTN_SMEM>>>(q, kvbuf, vt, att);
    // 4) out = att @ w_out^T + b_out, 128 CTAs, 2/SM
    gemm_tc128<<<dim3(DIM / 128, M_q / 128), 256, GEMM128_SMEM>>>(
        att, w_out, out, b_out, M_q, DIM, DIM);
}

// round 13
// speedup vs baseline: 1.0214x; 1.0214x over previous
#include <cuda_runtime.h>
#include <cstdint>
#include <math.h>

#define DIM       1024
#define NHEADS    16
#define HDIM      64
#define BATCH     4
#define SEQ       8192
#define LAT       512
#define SCALE     0.125f   // 64^-0.5

#if defined(__CUDA_ARCH_FEAT_SM103_ALL) || defined(__CUDA_ARCH_FEAT_SM100_ALL) || \
    (defined(__CUDA_ARCH_SPECIFIC__) && (__CUDA_ARCH_SPECIFIC__ >= 1000))
#define HAS_TCGEN05 1
#else
#define HAS_TCGEN05 0
#endif

// -------- scratch (device globals; no allocation allowed) --------
__device__ float g_q  [(size_t)BATCH * LAT * DIM];                    // 8 MB
__device__ float g_kv [(size_t)BATCH * SEQ * 2 * DIM];                // 268 MB (V half unused)
__device__ float g_att[(size_t)BATCH * LAT * DIM];                    // 8 MB
__device__ float g_vt [(size_t)BATCH * NHEADS * HDIM * SEQ];          // 134 MB (V^T, tf32)

// ================= helpers =================
__device__ __forceinline__ uint32_t smem_u32(const void* p) {
    uint32_t a;
    asm("{ .reg .u64 t; cvta.to.shared.u64 t, %1; cvt.u32.u64 %0, t; }"
        : "=r"(a) : "l"(p));
    return a;
}
__device__ __forceinline__ uint32_t f2tf32(float f) {
    uint32_t r;
    asm("cvt.rna.tf32.f32 %0, %1;" : "=r"(r) : "f"(f));
    return r;
}

#if HAS_TCGEN05
__device__ __forceinline__ uint32_t elect_one() {
    uint32_t p;
    asm volatile("{ .reg .pred p; elect.sync _|p, 0xFFFFFFFF; selp.b32 %0,1,0,p; }"
                 : "=r"(p));
    return p;
}

#define MBARRIER_INIT(addr, cnt) \
    asm volatile("mbarrier.init.shared.b64 [%0], %1;" :: "r"(addr), "r"(cnt) : "memory")

#define MBARRIER_WAIT_PARITY(mbar, par) do {                                   \
    uint32_t _m = (mbar); uint32_t _p = (par); uint32_t _done;                 \
    asm volatile("{\n\t.reg .pred p;\n\t"                                      \
        "mbarrier.try_wait.parity.acquire.cta.shared::cta.b64 p, [%1], %2;\n\t"\
        "selp.b32 %0, 1, 0, p;\n\t}"                                           \
        : "=r"(_done) : "r"(_m), "r"(_p) : "memory");                          \
    if (!_done) {                                                              \
        asm volatile("{\n\t.reg .pred P1;\n\t"                                 \
            "WL_%=:\n\t"                                                       \
            "mbarrier.try_wait.parity.acquire.cta.shared::cta.b64 P1, [%0], %1, 0x989680;\n\t" \
            "@P1 bra.uni WD_%=;\n\t"                                           \
            "bra.uni WL_%=;\n\t"                                               \
            "WD_%=:\n\t}"                                                      \
            :: "r"(_m), "r"(_p) : "memory");                                   \
    }                                                                          \
} while (0)

#define TCGEN05_ALLOC(slot, n) \
    asm volatile("tcgen05.alloc.cta_group::1.sync.aligned.shared::cta.b32 [%0], %1;" \
                 :: "r"(slot), "r"(n) : "memory")
#define TCGEN05_DEALLOC(tm, n) \
    asm volatile("tcgen05.dealloc.cta_group::1.sync.aligned.b32 %0, %1;" :: "r"(tm), "r"(n))
#define TCGEN05_RELINQ() \
    asm volatile("tcgen05.relinquish_alloc_permit.cta_group::1.sync.aligned;")
#define TCGEN05_COMMIT(mbar) \
    asm volatile("tcgen05.commit.cta_group::1.mbarrier::arrive::one.shared::cluster.b64 [%0];" \
                 :: "r"(mbar) : "memory")
#define TCGEN05_WAIT_LD() asm volatile("tcgen05.wait::ld.sync.aligned;" ::: "memory")
#define TCGEN05_WAIT_ST() asm volatile("tcgen05.wait::st.sync.aligned;" ::: "memory")
#define TCGEN05_FENCE_AFTER() asm volatile("tcgen05.fence::after_thread_sync;" ::: "memory")
#define TCGEN05_FENCE_BEFORE() asm volatile("tcgen05.fence::before_thread_sync;" ::: "memory")
#define FENCE_ASYNC() asm volatile("fence.proxy.async.shared::cta;" ::: "memory")

#define TCGEN05_LD_X32(r, addr)                                                \
    asm volatile("tcgen05.ld.sync.aligned.32x32b.x32.b32 "                     \
        "{%0,%1,%2,%3,%4,%5,%6,%7,%8,%9,%10,%11,%12,%13,%14,%15,"              \
        "%16,%17,%18,%19,%20,%21,%22,%23,%24,%25,%26,%27,%28,%29,%30,%31}, [%32];" \
        : "=r"((r)[0]),"=r"((r)[1]),"=r"((r)[2]),"=r"((r)[3]),                 \
          "=r"((r)[4]),"=r"((r)[5]),"=r"((r)[6]),"=r"((r)[7]),                 \
          "=r"((r)[8]),"=r"((r)[9]),"=r"((r)[10]),"=r"((r)[11]),               \
          "=r"((r)[12]),"=r"((r)[13]),"=r"((r)[14]),"=r"((r)[15]),             \
          "=r"((r)[16]),"=r"((r)[17]),"=r"((r)[18]),"=r"((r)[19]),             \
          "=r"((r)[20]),"=r"((r)[21]),"=r"((r)[22]),"=r"((r)[23]),             \
          "=r"((r)[24]),"=r"((r)[25]),"=r"((r)[26]),"=r"((r)[27]),             \
          "=r"((r)[28]),"=r"((r)[29]),"=r"((r)[30]),"=r"((r)[31])              \
        : "r"(addr))

#define TCGEN05_ST_X32(addr, r)                                                \
    asm volatile("tcgen05.st.sync.aligned.32x32b.x32.b32 [%0], "               \
        "{%1,%2,%3,%4,%5,%6,%7,%8,%9,%10,%11,%12,%13,%14,%15,%16,"             \
        "%17,%18,%19,%20,%21,%22,%23,%24,%25,%26,%27,%28,%29,%30,%31,%32};"    \
        :: "r"(addr),                                                          \
           "r"((r)[0]),"r"((r)[1]),"r"((r)[2]),"r"((r)[3]),                    \
           "r"((r)[4]),"r"((r)[5]),"r"((r)[6]),"r"((r)[7]),                    \
           "r"((r)[8]),"r"((r)[9]),"r"((r)[10]),"r"((r)[11]),                  \
           "r"((r)[12]),"r"((r)[13]),"r"((r)[14]),"r"((r)[15]),                \
           "r"((r)[16]),"r"((r)[17]),"r"((r)[18]),"r"((r)[19]),                \
           "r"((r)[20]),"r"((r)[21]),"r"((r)[22]),"r"((r)[23]),                \
           "r"((r)[24]),"r"((r)[25]),"r"((r)[26]),"r"((r)[27]),                \
           "r"((r)[28]),"r"((r)[29]),"r"((r)[30]),"r"((r)[31])                 \
        : "memory")

__device__ __forceinline__ void mma_tf32_ss(uint32_t d_tmem, uint64_t a_desc,
                                            uint64_t b_desc, uint32_t idesc,
                                            uint32_t enable) {
    asm volatile(
        "{\n\t.reg .pred p;\n\t"
        "setp.ne.u32 p, %4, 0;\n\t"
        "tcgen05.mma.cta_group::1.kind::tf32 [%0], %1, %2, %3, {%5,%5,%5,%5}, p;\n\t}"
        :: "r"(d_tmem), "l"(a_desc), "l"(b_desc), "r"(idesc), "r"(enable), "r"(0u)
        : "memory");
}
__device__ __forceinline__ void mma_tf32_ts(uint32_t d_tmem, uint32_t a_tmem,
                                            uint64_t b_desc, uint32_t idesc,
                                            uint32_t enable) {
    asm volatile(
        "{\n\t.reg .pred p;\n\t"
        "setp.ne.u32 p, %4, 0;\n\t"
        "tcgen05.mma.cta_group::1.kind::tf32 [%0], [%1], %2, %3, {%5,%5,%5,%5}, p;\n\t}"
        :: "r"(d_tmem), "r"(a_tmem), "l"(b_desc), "r"(idesc), "r"(enable), "r"(0u)
        : "memory");
}
#endif  // HAS_TCGEN05

// SW128 K-major descriptor base: layout=SW128(2), version=1, SBO=64, LBO=1
static constexpr uint64_t DESC_BASE =
    (2ull << 61) | (1ull << 46) | (64ull << 32) | (1ull << 16);

__device__ __forceinline__ uint32_t sw128(uint32_t off) {
    return off ^ ((off >> 3) & 0x70);
}

#define GK 32

// =================================================================
// GEMM (128x128 tile) — small projections (r12-proven, 51.4us)
// =================================================================
#define G128_STAGE 32768                      // A 16K + B 16K
#define GEMM128_SMEM (2 * G128_STAGE + 1024)

__global__ __launch_bounds__(256, 2)
void gemm_tc128(const float* __restrict__ A, const float* __restrict__ W,
                float* __restrict__ C, const float* __restrict__ bias,
                int M, int N, int K)
{
#if HAS_TCGEN05
    extern __shared__ char smraw[];
    __shared__ uint64_t mbar[2];
    __shared__ uint32_t tmem_slot;

    const uint32_t smbase = (smem_u32(smraw) + 1023u) & ~1023u;
    const uint32_t bar0 = smem_u32(&mbar[0]);
    const uint32_t bar1 = smem_u32(&mbar[1]);
    const uint32_t slot = smem_u32(&tmem_slot);

    const int tid = threadIdx.x;
    const int wid = tid >> 5;
    const int lid = tid & 31;
    const int m0 = blockIdx.y * 128;
    const int n0 = blockIdx.x * 128;

    if (wid == 0) TCGEN05_ALLOC(slot, 128);
    if (tid == 0) { MBARRIER_INIT(bar0, 1); MBARRIER_INIT(bar1, 1); }
    __syncthreads();
    uint32_t tmem;
    asm volatile("ld.shared.b32 %0, [%1];" : "=r"(tmem) : "r"(slot));
    if (wid == 0) TCGEN05_RELINQ();

    const uint32_t IDESC = (1u << 4) | (2u << 7) | (2u << 10)
                         | ((128u / 8) << 17) | ((128u / 16) << 24);

    const int NC = K / GK;
    int ph0 = 0, ph1 = 0;

    for (int c = 0; c < NC; c++) {
        const int buf = c & 1;
        const uint32_t barb = buf ? bar1 : bar0;
        if (c >= 2) {
            MBARRIER_WAIT_PARITY(barb, (buf ? ph1 : ph0));
            if (buf) ph1 ^= 1; else ph0 ^= 1;
        }
        const uint32_t sb = smbase + buf * G128_STAGE;
        const float* Ap = A + (size_t)m0 * K + c * GK;
        const float* Wp = W + (size_t)n0 * K + c * GK;

#pragma unroll
        for (int it = 0; it < 4; it++) {
            int i = tid + it * 256;
            int row = i >> 3, fo = i & 7;
            float4 v = *(const float4*)(Ap + (size_t)row * K + fo * 4);
            uint32_t r0 = f2tf32(v.x), r1 = f2tf32(v.y),
                     r2 = f2tf32(v.z), r3 = f2tf32(v.w);
            uint32_t dst = sb + sw128((uint32_t)(row * 128 + fo * 16));
            asm volatile("st.shared.v4.b32 [%0], {%1,%2,%3,%4};"
                         :: "r"(dst), "r"(r0), "r"(r1), "r"(r2), "r"(r3) : "memory");
        }
#pragma unroll
        for (int it = 0; it < 4; it++) {
            int i = tid + it * 256;
            int row = i >> 3, fo = i & 7;
            float4 v = *(const float4*)(Wp + (size_t)row * K + fo * 4);
            uint32_t r0 = f2tf32(v.x), r1 = f2tf32(v.y),
                     r2 = f2tf32(v.z), r3 = f2tf32(v.w);
            uint32_t dst = sb + 16384u + sw128((uint32_t)(row * 128 + fo * 16));
            asm volatile("st.shared.v4.b32 [%0], {%1,%2,%3,%4};"
                         :: "r"(dst), "r"(r0), "r"(r1), "r"(r2), "r"(r3) : "memory");
        }
        __syncthreads();

        if (wid == 0 && elect_one()) {
            FENCE_ASYNC();
            const uint64_t dA = DESC_BASE | ((uint64_t)(sb >> 4) & 0x3FFF);
            const uint64_t dB = DESC_BASE | ((uint64_t)((sb + 16384u) >> 4) & 0x3FFF);
#pragma unroll
            for (int k = 0; k < 4; k++) {
                uint32_t en = (c > 0 || k > 0) ? 1u : 0u;
                mma_tf32_ss(tmem, dA + k * 2, dB + k * 2, IDESC, en);
            }
            TCGEN05_COMMIT(barb);
        }
    }

    MBARRIER_WAIT_PARITY(bar0, ph0);
    MBARRIER_WAIT_PARITY(bar1, ph1);
    TCGEN05_FENCE_AFTER();

    {
        const int colh = wid >> 2;
        const int sub  = wid & 3;
        const int r = sub * 32 + lid;
        float* Crow = C + (size_t)(m0 + r) * N + n0 + colh * 64;
        const float* bp = bias ? (bias + n0 + colh * 64) : nullptr;
#pragma unroll
        for (int half = 0; half < 2; half++) {
            uint32_t rr[32];
            TCGEN05_LD_X32(rr, tmem + colh * 64 + half * 32);
            TCGEN05_WAIT_LD();
#pragma unroll
            for (int j = 0; j < 32; j += 4) {
                float4 o;
                o.x = __uint_as_float(rr[j + 0]);
                o.y = __uint_as_float(rr[j + 1]);
                o.z = __uint_as_float(rr[j + 2]);
                o.w = __uint_as_float(rr[j + 3]);
                if (bp) {
                    o.x += bp[half * 32 + j + 0]; o.y += bp[half * 32 + j + 1];
                    o.z += bp[half * 32 + j + 2]; o.w += bp[half * 32 + j + 3];
                }
                *(float4*)(Crow + half * 32 + j) = o;
            }
        }
    }
    TCGEN05_FENCE_BEFORE();
    __syncthreads();
    if (wid == 0) TCGEN05_DEALLOC(tmem, 128);

#else
    __shared__ float As[8][128];
    __shared__ float Ws[8][128];
    const int tid  = threadIdx.x;
    const int ty   = tid >> 4;
    const int tx   = tid & 15;
    const int row0 = blockIdx.y * 128;
    const int col0 = blockIdx.x * 128;
    const int lrow = tid >> 1;
    const int lk   = (tid & 1) * 4;

    const float* Ap = A + (size_t)(row0 + lrow) * K + lk;
    const float* Wp = W + (size_t)(col0 + lrow) * K + lk;
    float acc[8][8];
#pragma unroll
    for (int i = 0; i < 8; i++)
#pragma unroll
        for (int j = 0; j < 8; j++) acc[i][j] = 0.0f;

    for (int k0 = 0; k0 < K; k0 += 8) {
        float4 av = *(const float4*)(Ap + k0);
        float4 wv = *(const float4*)(Wp + k0);
        As[lk + 0][lrow] = av.x; As[lk + 1][lrow] = av.y;
        As[lk + 2][lrow] = av.z; As[lk + 3][lrow] = av.w;
        Ws[lk + 0][lrow] = wv.x; Ws[lk + 1][lrow] = wv.y;
        Ws[lk + 2][lrow] = wv.z; Ws[lk + 3][lrow] = wv.w;
        __syncthreads();
#pragma unroll
        for (int k = 0; k < 8; k++) {
            float a[8], b[8];
            float4 t0 = *(const float4*)(&As[k][ty * 8 + 0]);
            float4 t1 = *(const float4*)(&As[k][ty * 8 + 4]);
            a[0]=t0.x;a[1]=t0.y;a[2]=t0.z;a[3]=t0.w;a[4]=t1.x;a[5]=t1.y;a[6]=t1.z;a[7]=t1.w;
            float4 u0 = *(const float4*)(&Ws[k][tx * 8 + 0]);
            float4 u1 = *(const float4*)(&Ws[k][tx * 8 + 4]);
            b[0]=u0.x;b[1]=u0.y;b[2]=u0.z;b[3]=u0.w;b[4]=u1.x;b[5]=u1.y;b[6]=u1.z;b[7]=u1.w;
#pragma unroll
            for (int i = 0; i < 8; i++)
#pragma unroll
                for (int j = 0; j < 8; j++) acc[i][j] += a[i] * b[j];
        }
        __syncthreads();
    }
#pragma unroll
    for (int i = 0; i < 8; i++) {
        const size_t r = (size_t)(row0 + ty * 8 + i);
#pragma unroll
        for (int j = 0; j < 8; j++) {
            const int cc = col0 + tx * 8 + j;
            float v = acc[i][j];
            if (bias) v += bias[cc];
            C[r * N + cc] = v;
        }
    }
#endif
}

// =================================================================
// GEMM (256x256 tile, 3-stage pipeline) — kv projection with fused
// V^T epilogue. TMEM 512 cols -> occ 1; 3 stages hide retire latency.
// =================================================================
#define A256_BYTES 32768
#define B256_BYTES 32768
#define STAGE256 (A256_BYTES + B256_BYTES)       // 64KB
#define KV_NSTAGE 3
#define GEMMKV_SMEM (KV_NSTAGE * STAGE256 + 1024)  // 193KB

__global__ __launch_bounds__(256, 1)
void gemm_tc_kv(const float* __restrict__ A, const float* __restrict__ W,
                float* __restrict__ C, float* __restrict__ vtb,
                int M, int N, int K)
{
#if HAS_TCGEN05
    extern __shared__ char smraw[];
    __shared__ uint64_t mbar[KV_NSTAGE];
    __shared__ uint32_t tmem_slot;

    const uint32_t smbase = (smem_u32(smraw) + 1023u) & ~1023u;
    uint32_t baru[KV_NSTAGE];
#pragma unroll
    for (int s = 0; s < KV_NSTAGE; s++) baru[s] = smem_u32(&mbar[s]);
    const uint32_t slot = smem_u32(&tmem_slot);

    const int tid = threadIdx.x;
    const int wid = tid >> 5;
    const int lid = tid & 31;
    const int m0 = blockIdx.y * 256;
    const int n0 = blockIdx.x * 256;

    if (wid == 0) TCGEN05_ALLOC(slot, 512);
    if (tid == 0) {
#pragma unroll
        for (int s = 0; s < KV_NSTAGE; s++) MBARRIER_INIT(baru[s], 1);
    }
    __syncthreads();
    uint32_t tmem;
    asm volatile("ld.shared.b32 %0, [%1];" : "=r"(tmem) : "r"(slot));
    if (wid == 0) TCGEN05_RELINQ();

    const uint32_t IDESC = (1u << 4) | (2u << 7) | (2u << 10)
                         | ((256u / 8) << 17) | ((128u / 16) << 24);

    const int NC = K / GK;                       // 32
    int ph[KV_NSTAGE] = {0, 0, 0};

    for (int c = 0; c < NC; c++) {
        const int buf = c % KV_NSTAGE;
        if (c >= KV_NSTAGE) {
            MBARRIER_WAIT_PARITY(baru[buf], ph[buf]);
            ph[buf] ^= 1;
        }
        const uint32_t sb = smbase + buf * STAGE256;
        const float* Ap = A + (size_t)m0 * K + c * GK;
        const float* Wp = W + (size_t)n0 * K + c * GK;

        // A: 256 rows -> A0 (rows<128) @0 / A1 @16K
#pragma unroll
        for (int it = 0; it < 8; it++) {
            int i = tid + it * 256;
            int row = i >> 3, fo = i & 7;
            float4 v = *(const float4*)(Ap + (size_t)row * K + fo * 4);
            uint32_t r0 = f2tf32(v.x), r1 = f2tf32(v.y),
                     r2 = f2tf32(v.z), r3 = f2tf32(v.w);
            uint32_t off = sw128((uint32_t)((row & 127) * 128 + fo * 16));
            uint32_t dst = sb + ((row < 128) ? 0u : 16384u) + off;
            asm volatile("st.shared.v4.b32 [%0], {%1,%2,%3,%4};"
                         :: "r"(dst), "r"(r0), "r"(r1), "r"(r2), "r"(r3) : "memory");
        }
        // B: 256 rows @32K
#pragma unroll
        for (int it = 0; it < 8; it++) {
            int i = tid + it * 256;
            int row = i >> 3, fo = i & 7;
            float4 v = *(const float4*)(Wp + (size_t)row * K + fo * 4);
            uint32_t r0 = f2tf32(v.x), r1 = f2tf32(v.y),
                     r2 = f2tf32(v.z), r3 = f2tf32(v.w);
            uint32_t dst = sb + A256_BYTES + sw128((uint32_t)(row * 128 + fo * 16));
            asm volatile("st.shared.v4.b32 [%0], {%1,%2,%3,%4};"
                         :: "r"(dst), "r"(r0), "r"(r1), "r"(r2), "r"(r3) : "memory");
        }
        __syncthreads();

        if (wid == 0 && elect_one()) {
            FENCE_ASYNC();
            const uint64_t dA0 = DESC_BASE | ((uint64_t)(sb >> 4) & 0x3FFF);
            const uint64_t dA1 = DESC_BASE | ((uint64_t)((sb + 16384u) >> 4) & 0x3FFF);
            const uint64_t dB  = DESC_BASE | ((uint64_t)((sb + A256_BYTES) >> 4) & 0x3FFF);
#pragma unroll
            for (int k = 0; k < 4; k++) {
                uint32_t en = (c > 0 || k > 0) ? 1u : 0u;
                mma_tf32_ss(tmem,       dA0 + k * 2, dB + k * 2, IDESC, en);
                mma_tf32_ss(tmem + 256, dA1 + k * 2, dB + k * 2, IDESC, en);
            }
            TCGEN05_COMMIT(baru[buf]);
        }
    }

    // drain all stages (NC >= KV_NSTAGE always here)
#pragma unroll
    for (int s = 0; s < KV_NSTAGE; s++)
        MBARRIER_WAIT_PARITY(baru[s], ph[s]);
    TCGEN05_FENCE_AFTER();

    // epilogue: warps 0-3 -> atom0 rows, warps 4-7 -> atom1 rows
    {
        const int tile = wid >> 2;
        const uint32_t dbase = tmem + tile * 256;
        const int rowl = (wid & 3) * 32 + lid;
        const size_t grow = (size_t)m0 + tile * 128 + rowl;    // global row = b*SEQ + s

        if (vtb && n0 >= DIM) {
            // V tile: write ONLY transposed tf32 into vtb (coalesced over s)
            const int s  = (int)(grow & (SEQ - 1));
            const int bq = (int)(grow >> 13);
            const size_t vb0 = (size_t)bq * NHEADS * HDIM;
#pragma unroll
            for (int cb = 0; cb < 8; cb++) {
                uint32_t rr[32];
                TCGEN05_LD_X32(rr, dbase + cb * 32);
                TCGEN05_WAIT_LD();
#pragma unroll
                for (int j = 0; j < 32; j++) {
                    const int dcol = (n0 - DIM) + cb * 32 + j;
                    vtb[(vb0 + (size_t)dcol) * SEQ + s] =
                        __uint_as_float(f2tf32(__uint_as_float(rr[j])));
                }
            }
        } else {
            float* Crow = C + grow * N + n0;
#pragma unroll
            for (int cb = 0; cb < 8; cb++) {
                uint32_t rr[32];
                TCGEN05_LD_X32(rr, dbase + cb * 32);
                TCGEN05_WAIT_LD();
#pragma unroll
                for (int j = 0; j < 32; j += 4) {
                    float4 o;
                    o.x = __uint_as_float(rr[j + 0]);
                    o.y = __uint_as_float(rr[j + 1]);
                    o.z = __uint_as_float(rr[j + 2]);
                    o.w = __uint_as_float(rr[j + 3]);
                    *(float4*)(Crow + cb * 32 + j) = o;
                }
            }
        }
    }
    TCGEN05_FENCE_BEFORE();
    __syncthreads();
    if (wid == 0) TCGEN05_DEALLOC(tmem, 512);

#else
    // SIMT fallback: 2x2 subtiles of 128x128 with fused vt on V columns
    __shared__ float As[8][128];
    __shared__ float Ws[8][128];
    const int tid  = threadIdx.x;
    const int ty   = tid >> 4;
    const int tx   = tid & 15;
    const int lrow = tid >> 1;
    const int lk   = (tid & 1) * 4;

    for (int hm = 0; hm < 2; hm++)
    for (int hn = 0; hn < 2; hn++) {
        const int row0 = blockIdx.y * 256 + hm * 128;
        const int col0 = blockIdx.x * 256 + hn * 128;
        const float* Ap = A + (size_t)(row0 + lrow) * K + lk;
        const float* Wp = W + (size_t)(col0 + lrow) * K + lk;
        float acc[8][8];
#pragma unroll
        for (int i = 0; i < 8; i++)
#pragma unroll
            for (int j = 0; j < 8; j++) acc[i][j] = 0.0f;

        for (int k0 = 0; k0 < K; k0 += 8) {
            float4 av = *(const float4*)(Ap + k0);
            float4 wv = *(const float4*)(Wp + k0);
            As[lk + 0][lrow] = av.x; As[lk + 1][lrow] = av.y;
            As[lk + 2][lrow] = av.z; As[lk + 3][lrow] = av.w;
            Ws[lk + 0][lrow] = wv.x; Ws[lk + 1][lrow] = wv.y;
            Ws[lk + 2][lrow] = wv.z; Ws[lk + 3][lrow] = wv.w;
            __syncthreads();
#pragma unroll
            for (int k = 0; k < 8; k++) {
                float a[8], b[8];
                float4 t0 = *(const float4*)(&As[k][ty * 8 + 0]);
                float4 t1 = *(const float4*)(&As[k][ty * 8 + 4]);
                a[0]=t0.x;a[1]=t0.y;a[2]=t0.z;a[3]=t0.w;a[4]=t1.x;a[5]=t1.y;a[6]=t1.z;a[7]=t1.w;
                float4 u0 = *(const float4*)(&Ws[k][tx * 8 + 0]);
                float4 u1 = *(const float4*)(&Ws[k][tx * 8 + 4]);
                b[0]=u0.x;b[1]=u0.y;b[2]=u0.z;b[3]=u0.w;b[4]=u1.x;b[5]=u1.y;b[6]=u1.z;b[7]=u1.w;
#pragma unroll
                for (int i = 0; i < 8; i++)
#pragma unroll
                    for (int j = 0; j < 8; j++) acc[i][j] += a[i] * b[j];
            }
            __syncthreads();
        }
#pragma unroll
        for (int i = 0; i < 8; i++) {
            const size_t grow = (size_t)(row0 + ty * 8 + i);
#pragma unroll
            for (int j = 0; j < 8; j++) {
                const int cc = col0 + tx * 8 + j;
                if (vtb && cc >= DIM) {
                    const int s  = (int)(grow & (SEQ - 1));
                    const int bq = (int)(grow >> 13);
                    vtb[((size_t)bq * NHEADS * HDIM + (cc - DIM)) * SEQ + s] =
                        __uint_as_float(f2tf32(acc[i][j]));
                } else {
                    C[grow * N + cc] = acc[i][j];
                }
            }
        }
        __syncthreads();
    }
#endif
}

// =================================================================
// Tensor-core flash attention — round-9 version (proven 251us).
// 2 CTAs/SM (97KB smem, 256 TMEM cols). S->P in-place in TMEM.
// =================================================================
#define SCHUNK 128
#define NCH (SEQ / SCHUNK)
#define ATTN_SMEM (3 * 32768 + 1024)
#define SCALE_L2E 0.18033688011112042f   // SCALE * log2(e)

__global__ __launch_bounds__(256, 2)
void attn_tc(const float* __restrict__ q, const float* __restrict__ kv,
             const float* __restrict__ vt, float* __restrict__ out)
{
#if HAS_TCGEN05
    extern __shared__ char smraw[];
    __shared__ uint64_t mbar[2];
    __shared__ uint32_t tmem_slot;
    __shared__ float ls_sh[256];

    const uint32_t smbase = (smem_u32(smraw) + 1023u) & ~1023u;
    const uint32_t QS = smbase;
    const uint32_t KS = smbase + 32768u;
    const uint32_t VS = smbase + 65536u;
    const uint32_t barQK = smem_u32(&mbar[0]);
    const uint32_t barPV = smem_u32(&mbar[1]);
    const uint32_t slot  = smem_u32(&tmem_slot);

    const int tid = threadIdx.x;
    const int wid = tid >> 5;
    const int lid = tid & 31;
    const int bh  = blockIdx.x >> 2;
    const int lt  = blockIdx.x & 3;
    const int b   = bh >> 4, h = bh & 15;
    const int l0  = lt * 128;

    if (wid == 0) TCGEN05_ALLOC(slot, 256);
    if (tid == 0) { MBARRIER_INIT(barQK, 1); MBARRIER_INIT(barPV, 1); }
    __syncthreads();
    uint32_t tmem;
    asm volatile("ld.shared.b32 %0, [%1];" : "=r"(tmem) : "r"(slot));
    if (wid == 0) TCGEN05_RELINQ();
    const uint32_t tmem_SP = tmem;
    const uint32_t tmem_O  = tmem + 128;

    const uint32_t IDESC_S = (1u << 4) | (2u << 7) | (2u << 10)
                           | ((128u / 8) << 17) | ((128u / 16) << 24);
    const uint32_t IDESC_O = (1u << 4) | (2u << 7) | (2u << 10)
                           | ((64u / 8) << 17) | ((128u / 16) << 24);

    const float* kbase = kv + (size_t)b * SEQ * (2 * DIM) + h * HDIM;
    const float* vbase = vt + ((size_t)bh * HDIM) * SEQ;

    const float* qbase = q + ((size_t)b * LAT + l0) * DIM + h * HDIM;
#pragma unroll
    for (int it = 0; it < 8; it++) {
        int i = tid + it * 256;
        int row = i >> 4, f = i & 15;
        int kc = f >> 3, fo = f & 7;
        float4 v = *(const float4*)(qbase + (size_t)row * DIM + f * 4);
        uint32_t r0 = f2tf32(v.x * SCALE_L2E), r1 = f2tf32(v.y * SCALE_L2E);
        uint32_t r2 = f2tf32(v.z * SCALE_L2E), r3 = f2tf32(v.w * SCALE_L2E);
        uint32_t dst = QS + kc * 16384u + sw128((uint32_t)(row * 128 + fo * 16));
        asm volatile("st.shared.v4.b32 [%0], {%1,%2,%3,%4};"
                     :: "r"(dst), "r"(r0), "r"(r1), "r"(r2), "r"(r3) : "memory");
    }

    auto loadK = [&](int ci) {
        const int s0 = ci * SCHUNK;
#pragma unroll
        for (int it = 0; it < 8; it++) {
            int i = tid + it * 256;
            int kr = i >> 4, f = i & 15;
            int kc = f >> 3, fo = f & 7;
            float4 v = *(const float4*)(kbase + (size_t)(s0 + kr) * (2 * DIM) + f * 4);
            uint32_t r0 = f2tf32(v.x), r1 = f2tf32(v.y),
                     r2 = f2tf32(v.z), r3 = f2tf32(v.w);
            uint32_t dst = KS + kc * 16384u + sw128((uint32_t)(kr * 128 + fo * 16));
            asm volatile("st.shared.v4.b32 [%0], {%1,%2,%3,%4};"
                         :: "r"(dst), "r"(r0), "r"(r1), "r"(r2), "r"(r3) : "memory");
        }
    };
    auto loadVT = [&](int ci) {
        const int s0 = ci * SCHUNK;
#pragma unroll
        for (int it = 0; it < 8; it++) {
            int i = tid + it * 256;
            int d = i >> 5, f = i & 31;
            int sc = f >> 3, fo = f & 7;
            float4 v = *(const float4*)(vbase + (size_t)d * SEQ + s0 + f * 4);
            uint32_t dst = VS + sc * 8192u + sw128((uint32_t)(d * 128 + fo * 16));
            asm volatile("st.shared.v4.b32 [%0], {%1,%2,%3,%4};"
                         :: "r"(dst), "r"(__float_as_uint(v.x)), "r"(__float_as_uint(v.y)),
                            "r"(__float_as_uint(v.z)), "r"(__float_as_uint(v.w)) : "memory");
        }
    };

    const uint64_t dQ0 = DESC_BASE | ((uint64_t)(QS >> 4) & 0x3FFF);
    const uint64_t dQ1 = DESC_BASE | ((uint64_t)((QS + 16384u) >> 4) & 0x3FFF);
    const uint64_t dK0 = DESC_BASE | ((uint64_t)(KS >> 4) & 0x3FFF);
    const uint64_t dK1 = DESC_BASE | ((uint64_t)((KS + 16384u) >> 4) & 0x3FFF);

    float lsum = 0.0f;
    int phQK = 0, phPV = 0;

    loadK(0);
    loadVT(0);
    __syncthreads();

    for (int ci = 0; ci < NCH; ci++) {
        if (wid == 0 && elect_one()) {
            FENCE_ASYNC();
#pragma unroll
            for (int blk = 0; blk < 2; blk++) {
                const uint64_t dq = blk ? dQ1 : dQ0;
                const uint64_t dk = blk ? dK1 : dK0;
#pragma unroll
                for (int ks = 0; ks < 4; ks++)
                    mma_tf32_ss(tmem_SP, dq + ks * 2, dk + ks * 2, IDESC_S,
                                (blk > 0 || ks > 0) ? 1u : 0u);
            }
            TCGEN05_COMMIT(barQK);
        }
        MBARRIER_WAIT_PARITY(barQK, phQK); phQK ^= 1;
        TCGEN05_FENCE_AFTER();

        {
            const uint32_t colofs = (uint32_t)(wid >> 2) * 64u;
            const uint32_t wlane  = (uint32_t)(wid & 3) << 21;
#pragma unroll
            for (int blk = 0; blk < 2; blk++) {
                uint32_t rr[32];
                TCGEN05_LD_X32(rr, tmem_SP + colofs + blk * 32);
                TCGEN05_WAIT_LD();
#pragma unroll
                for (int j = 0; j < 32; j++) {
                    float p;
                    asm("ex2.approx.f32 %0, %1;" : "=f"(p) : "f"(__uint_as_float(rr[j])));
                    lsum += p;
                    rr[j] = f2tf32(p);
                }
                TCGEN05_ST_X32(tmem_SP + wlane + colofs + blk * 32, rr);
            }
            TCGEN05_WAIT_ST();
        }
        TCGEN05_FENCE_BEFORE();
        __syncthreads();

        if (wid == 0 && elect_one()) {
            TCGEN05_FENCE_AFTER();
            FENCE_ASYNC();
#pragma unroll
            for (int st = 0; st < 16; st++) {
                const uint64_t dV = DESC_BASE
                    | ((uint64_t)((VS + (st >> 2) * 8192u) >> 4) & 0x3FFF);
                mma_tf32_ts(tmem_O, tmem_SP + st * 8, dV + (st & 3) * 2, IDESC_O,
                            (ci > 0 || st > 0) ? 1u : 0u);
            }
            TCGEN05_COMMIT(barPV);
        }

        if (ci + 1 < NCH) loadK(ci + 1);
        MBARRIER_WAIT_PARITY(barPV, phPV); phPV ^= 1;
        if (ci + 1 < NCH) loadVT(ci + 1);
        __syncthreads();
    }

    TCGEN05_FENCE_AFTER();

    ls_sh[tid] = lsum;
    __syncthreads();

    if (wid < 4) {
        const int r = wid * 32 + lid;
        const float inv = 1.0f / (ls_sh[tid] + ls_sh[tid + 128]);
        float* op = out + ((size_t)b * LAT + l0 + r) * DIM + h * HDIM;
#pragma unroll
        for (int cb = 0; cb < 2; cb++) {
            uint32_t rr[32];
            TCGEN05_LD_X32(rr, tmem_O + cb * 32);
            TCGEN05_WAIT_LD();
#pragma unroll
            for (int j = 0; j < 32; j += 4) {
                float4 o;
                o.x = __uint_as_float(rr[j + 0]) * inv;
                o.y = __uint_as_float(rr[j + 1]) * inv;
                o.z = __uint_as_float(rr[j + 2]) * inv;
                o.w = __uint_as_float(rr[j + 3]) * inv;
                *(float4*)(op + cb * 32 + j) = o;
            }
        }
    }
    TCGEN05_FENCE_BEFORE();
    __syncthreads();
    if (wid == 0) TCGEN05_DEALLOC(tmem, 256);

#else
    // SIMT fallback (thread-per-row; never runs on GB300)
    const int tid = threadIdx.x;
    const int bh  = blockIdx.x >> 2;
    const int lt  = blockIdx.x & 3;
    const int b   = bh >> 4, h = bh & 15;
    const int l0  = lt * 128;
    if (tid < 128) {
        const float* qrow = q + ((size_t)b * LAT + l0 + tid) * DIM + h * HDIM;
        const float* kb = kv + (size_t)b * SEQ * (2 * DIM) + h * HDIM;
        const float* vb = vt + ((size_t)bh * HDIM) * SEQ;
        float qr[64];
#pragma unroll
        for (int d = 0; d < 64; d++) qr[d] = qrow[d] * SCALE;
        float O[64];
#pragma unroll
        for (int d = 0; d < 64; d++) O[d] = 0.0f;
        float l = 0.0f;
        for (int s = 0; s < SEQ; s++) {
            const float* kr = kb + (size_t)s * (2 * DIM);
            float sv = 0.0f;
#pragma unroll 16
            for (int d = 0; d < 64; d++) sv += qr[d] * kr[d];
            float p = __expf(sv);
            l += p;
#pragma unroll 16
            for (int d = 0; d < 64; d++) O[d] += p * vb[(size_t)d * SEQ + s];
        }
        float* op = out + ((size_t)b * LAT + l0 + tid) * DIM + h * HDIM;
        float inv = 1.0f / l;
#pragma unroll
        for (int d = 0; d < 64; d++) op[d] = O[d] * inv;
    }
#endif
}

// =================================================================
// launch
// =================================================================
extern "C" void kernel_launch(void* const* d_in, const int* in_sizes, int n_in,
                              void* d_out, int out_size)
{
    const float* x       = (const float*)d_in[0];
    const float* latents = (const float*)d_in[1];
    if (in_sizes[0] != BATCH * SEQ * DIM) {
        x       = (const float*)d_in[1];
        latents = (const float*)d_in[0];
    }
    const float* w_q   = (const float*)d_in[2];
    const float* w_kv  = (const float*)d_in[3];
    const float* w_out = (const float*)d_in[4];
    const float* b_out = (const float*)d_in[5];
    float* out = (float*)d_out;

    float *q, *kvbuf, *att, *vt;
    cudaGetSymbolAddress((void**)&q,     g_q);
    cudaGetSymbolAddress((void**)&kvbuf, g_kv);
    cudaGetSymbolAddress((void**)&att,   g_att);
    cudaGetSymbolAddress((void**)&vt,    g_vt);

    const int M_q  = BATCH * LAT;    // 2048
    const int M_kv = BATCH * SEQ;    // 32768

    cudaFuncSetAttribute(gemm_tc128, cudaFuncAttributeMaxDynamicSharedMemorySize, GEMM128_SMEM);
    cudaFuncSetAttribute(gemm_tc_kv, cudaFuncAttributeMaxDynamicSharedMemorySize, GEMMKV_SMEM);
    cudaFuncSetAttribute(attn_tc,    cudaFuncAttributeMaxDynamicSharedMemorySize, ATTN_SMEM);

    // 1) q = latents @ w_q^T        (2048 x 1024), 128 CTAs
    gemm_tc128<<<dim3(DIM / 128, M_q / 128), 256, GEMM128_SMEM>>>(
        latents, w_q, q, nullptr, M_q, DIM, DIM);
    // 2) kv = x @ w_kv^T            (32768 x 2048), 1024 CTAs, 3-stage;
    //    V half goes straight to vt (tf32, transposed)
    gemm_tc_kv<<<dim3(2 * DIM / 256, M_kv / 256), 256, GEMMKV_SMEM>>>(
        x, w_kv, kvbuf, vt, M_kv, 2 * DIM, DIM);
    // 3) attention
    attn_tc<<<BATCH * NHEADS * (LAT / 128), 256, ATTN_SMEM>>>(q, kvbuf, vt, att);
    // 4) out = att @ w_out^T + b_out, 128 CTAs
    gemm_tc128<<<dim3(DIM / 128, M_q / 128), 256, GEMM128_SMEM>>>(
        att, w_out, out, b_out, M_q, DIM, DIM);
}

// round 14
// speedup vs baseline: 1.0993x; 1.0764x over previous
#include <cuda_runtime.h>
#include <cstdint>
#include <math.h>

#define DIM       1024
#define NHEADS    16
#define HDIM      64
#define BATCH     4
#define SEQ       8192
#define LAT       512
#define SCALE     0.125f   // 64^-0.5

#if defined(__CUDA_ARCH_FEAT_SM103_ALL) || defined(__CUDA_ARCH_FEAT_SM100_ALL) || \
    (defined(__CUDA_ARCH_SPECIFIC__) && (__CUDA_ARCH_SPECIFIC__ >= 1000))
#define HAS_TCGEN05 1
#else
#define HAS_TCGEN05 0
#endif

// -------- scratch (device globals; no allocation allowed) --------
__device__ float g_q  [(size_t)BATCH * LAT * DIM];                    // 8 MB
__device__ float g_kv [(size_t)BATCH * SEQ * 2 * DIM];                // 268 MB (V half unused)
__device__ float g_att[(size_t)BATCH * LAT * DIM];                    // 8 MB
__device__ float g_vt [(size_t)BATCH * NHEADS * HDIM * SEQ];          // 134 MB (V^T, tf32)

// ================= helpers =================
__device__ __forceinline__ uint32_t smem_u32(const void* p) {
    uint32_t a;
    asm("{ .reg .u64 t; cvta.to.shared.u64 t, %1; cvt.u32.u64 %0, t; }"
        : "=r"(a) : "l"(p));
    return a;
}
__device__ __forceinline__ uint32_t f2tf32(float f) {
    uint32_t r;
    asm("cvt.rna.tf32.f32 %0, %1;" : "=r"(r) : "f"(f));
    return r;
}

#if HAS_TCGEN05
__device__ __forceinline__ uint32_t elect_one() {
    uint32_t p;
    asm volatile("{ .reg .pred p; elect.sync _|p, 0xFFFFFFFF; selp.b32 %0,1,0,p; }"
                 : "=r"(p));
    return p;
}

#define MBARRIER_INIT(addr, cnt) \
    asm volatile("mbarrier.init.shared.b64 [%0], %1;" :: "r"(addr), "r"(cnt) : "memory")

#define MBARRIER_WAIT_PARITY(mbar, par) do {                                   \
    uint32_t _m = (mbar); uint32_t _p = (par); uint32_t _done;                 \
    asm volatile("{\n\t.reg .pred p;\n\t"                                      \
        "mbarrier.try_wait.parity.acquire.cta.shared::cta.b64 p, [%1], %2;\n\t"\
        "selp.b32 %0, 1, 0, p;\n\t}"                                           \
        : "=r"(_done) : "r"(_m), "r"(_p) : "memory");                          \
    if (!_done) {                                                              \
        asm volatile("{\n\t.reg .pred P1;\n\t"                                 \
            "WL_%=:\n\t"                                                       \
            "mbarrier.try_wait.parity.acquire.cta.shared::cta.b64 P1, [%0], %1, 0x989680;\n\t" \
            "@P1 bra.uni WD_%=;\n\t"                                           \
            "bra.uni WL_%=;\n\t"                                               \
            "WD_%=:\n\t}"                                                      \
            :: "r"(_m), "r"(_p) : "memory");                                   \
    }                                                                          \
} while (0)

#define TCGEN05_ALLOC(slot, n) \
    asm volatile("tcgen05.alloc.cta_group::1.sync.aligned.shared::cta.b32 [%0], %1;" \
                 :: "r"(slot), "r"(n) : "memory")
#define TCGEN05_DEALLOC(tm, n) \
    asm volatile("tcgen05.dealloc.cta_group::1.sync.aligned.b32 %0, %1;" :: "r"(tm), "r"(n))
#define TCGEN05_RELINQ() \
    asm volatile("tcgen05.relinquish_alloc_permit.cta_group::1.sync.aligned;")
#define TCGEN05_COMMIT(mbar) \
    asm volatile("tcgen05.commit.cta_group::1.mbarrier::arrive::one.shared::cluster.b64 [%0];" \
                 :: "r"(mbar) : "memory")
#define TCGEN05_WAIT_LD() asm volatile("tcgen05.wait::ld.sync.aligned;" ::: "memory")
#define TCGEN05_WAIT_ST() asm volatile("tcgen05.wait::st.sync.aligned;" ::: "memory")
#define TCGEN05_FENCE_AFTER() asm volatile("tcgen05.fence::after_thread_sync;" ::: "memory")
#define TCGEN05_FENCE_BEFORE() asm volatile("tcgen05.fence::before_thread_sync;" ::: "memory")
#define FENCE_ASYNC() asm volatile("fence.proxy.async.shared::cta;" ::: "memory")

#define TCGEN05_LD_X32(r, addr)                                                \
    asm volatile("tcgen05.ld.sync.aligned.32x32b.x32.b32 "                     \
        "{%0,%1,%2,%3,%4,%5,%6,%7,%8,%9,%10,%11,%12,%13,%14,%15,"              \
        "%16,%17,%18,%19,%20,%21,%22,%23,%24,%25,%26,%27,%28,%29,%30,%31}, [%32];" \
        : "=r"((r)[0]),"=r"((r)[1]),"=r"((r)[2]),"=r"((r)[3]),                 \
          "=r"((r)[4]),"=r"((r)[5]),"=r"((r)[6]),"=r"((r)[7]),                 \
          "=r"((r)[8]),"=r"((r)[9]),"=r"((r)[10]),"=r"((r)[11]),               \
          "=r"((r)[12]),"=r"((r)[13]),"=r"((r)[14]),"=r"((r)[15]),             \
          "=r"((r)[16]),"=r"((r)[17]),"=r"((r)[18]),"=r"((r)[19]),             \
          "=r"((r)[20]),"=r"((r)[21]),"=r"((r)[22]),"=r"((r)[23]),             \
          "=r"((r)[24]),"=r"((r)[25]),"=r"((r)[26]),"=r"((r)[27]),             \
          "=r"((r)[28]),"=r"((r)[29]),"=r"((r)[30]),"=r"((r)[31])              \
        : "r"(addr))

#define TCGEN05_ST_X32(addr, r)                                                \
    asm volatile("tcgen05.st.sync.aligned.32x32b.x32.b32 [%0], "               \
        "{%1,%2,%3,%4,%5,%6,%7,%8,%9,%10,%11,%12,%13,%14,%15,%16,"             \
        "%17,%18,%19,%20,%21,%22,%23,%24,%25,%26,%27,%28,%29,%30,%31,%32};"    \
        :: "r"(addr),                                                          \
           "r"((r)[0]),"r"((r)[1]),"r"((r)[2]),"r"((r)[3]),                    \
           "r"((r)[4]),"r"((r)[5]),"r"((r)[6]),"r"((r)[7]),                    \
           "r"((r)[8]),"r"((r)[9]),"r"((r)[10]),"r"((r)[11]),                  \
           "r"((r)[12]),"r"((r)[13]),"r"((r)[14]),"r"((r)[15]),                \
           "r"((r)[16]),"r"((r)[17]),"r"((r)[18]),"r"((r)[19]),                \
           "r"((r)[20]),"r"((r)[21]),"r"((r)[22]),"r"((r)[23]),                \
           "r"((r)[24]),"r"((r)[25]),"r"((r)[26]),"r"((r)[27]),                \
           "r"((r)[28]),"r"((r)[29]),"r"((r)[30]),"r"((r)[31])                 \
        : "memory")

__device__ __forceinline__ void mma_tf32_ss(uint32_t d_tmem, uint64_t a_desc,
                                            uint64_t b_desc, uint32_t idesc,
                                            uint32_t enable) {
    asm volatile(
        "{\n\t.reg .pred p;\n\t"
        "setp.ne.u32 p, %4, 0;\n\t"
        "tcgen05.mma.cta_group::1.kind::tf32 [%0], %1, %2, %3, {%5,%5,%5,%5}, p;\n\t}"
        :: "r"(d_tmem), "l"(a_desc), "l"(b_desc), "r"(idesc), "r"(enable), "r"(0u)
        : "memory");
}
__device__ __forceinline__ void mma_tf32_ts(uint32_t d_tmem, uint32_t a_tmem,
                                            uint64_t b_desc, uint32_t idesc,
                                            uint32_t enable) {
    asm volatile(
        "{\n\t.reg .pred p;\n\t"
        "setp.ne.u32 p, %4, 0;\n\t"
        "tcgen05.mma.cta_group::1.kind::tf32 [%0], [%1], %2, %3, {%5,%5,%5,%5}, p;\n\t}"
        :: "r"(d_tmem), "r"(a_tmem), "l"(b_desc), "r"(idesc), "r"(enable), "r"(0u)
        : "memory");
}
#endif  // HAS_TCGEN05

// SW128 K-major descriptor base: layout=SW128(2), version=1, SBO=64, LBO=1
static constexpr uint64_t DESC_BASE =
    (2ull << 61) | (1ull << 46) | (64ull << 32) | (1ull << 16);

__device__ __forceinline__ uint32_t sw128(uint32_t off) {
    return off ^ ((off >> 3) & 0x70);
}

#define GK 32

// =================================================================
// GEMM (128x128 tile) — small projections (measured 51.2us twice)
// =================================================================
#define G128_STAGE 32768                      // A 16K + B 16K
#define GEMM128_SMEM (2 * G128_STAGE + 1024)

__global__ __launch_bounds__(256, 2)
void gemm_tc128(const float* __restrict__ A, const float* __restrict__ W,
                float* __restrict__ C, const float* __restrict__ bias,
                int M, int N, int K)
{
#if HAS_TCGEN05
    extern __shared__ char smraw[];
    __shared__ uint64_t mbar[2];
    __shared__ uint32_t tmem_slot;

    const uint32_t smbase = (smem_u32(smraw) + 1023u) & ~1023u;
    const uint32_t bar0 = smem_u32(&mbar[0]);
    const uint32_t bar1 = smem_u32(&mbar[1]);
    const uint32_t slot = smem_u32(&tmem_slot);

    const int tid = threadIdx.x;
    const int wid = tid >> 5;
    const int lid = tid & 31;
    const int m0 = blockIdx.y * 128;
    const int n0 = blockIdx.x * 128;

    if (wid == 0) TCGEN05_ALLOC(slot, 128);
    if (tid == 0) { MBARRIER_INIT(bar0, 1); MBARRIER_INIT(bar1, 1); }
    __syncthreads();
    uint32_t tmem;
    asm volatile("ld.shared.b32 %0, [%1];" : "=r"(tmem) : "r"(slot));
    if (wid == 0) TCGEN05_RELINQ();

    const uint32_t IDESC = (1u << 4) | (2u << 7) | (2u << 10)
                         | ((128u / 8) << 17) | ((128u / 16) << 24);

    const int NC = K / GK;
    int ph0 = 0, ph1 = 0;

    for (int c = 0; c < NC; c++) {
        const int buf = c & 1;
        const uint32_t barb = buf ? bar1 : bar0;
        if (c >= 2) {
            MBARRIER_WAIT_PARITY(barb, (buf ? ph1 : ph0));
            if (buf) ph1 ^= 1; else ph0 ^= 1;
        }
        const uint32_t sb = smbase + buf * G128_STAGE;
        const float* Ap = A + (size_t)m0 * K + c * GK;
        const float* Wp = W + (size_t)n0 * K + c * GK;

#pragma unroll
        for (int it = 0; it < 4; it++) {
            int i = tid + it * 256;
            int row = i >> 3, fo = i & 7;
            float4 v = *(const float4*)(Ap + (size_t)row * K + fo * 4);
            uint32_t r0 = f2tf32(v.x), r1 = f2tf32(v.y),
                     r2 = f2tf32(v.z), r3 = f2tf32(v.w);
            uint32_t dst = sb + sw128((uint32_t)(row * 128 + fo * 16));
            asm volatile("st.shared.v4.b32 [%0], {%1,%2,%3,%4};"
                         :: "r"(dst), "r"(r0), "r"(r1), "r"(r2), "r"(r3) : "memory");
        }
#pragma unroll
        for (int it = 0; it < 4; it++) {
            int i = tid + it * 256;
            int row = i >> 3, fo = i & 7;
            float4 v = *(const float4*)(Wp + (size_t)row * K + fo * 4);
            uint32_t r0 = f2tf32(v.x), r1 = f2tf32(v.y),
                     r2 = f2tf32(v.z), r3 = f2tf32(v.w);
            uint32_t dst = sb + 16384u + sw128((uint32_t)(row * 128 + fo * 16));
            asm volatile("st.shared.v4.b32 [%0], {%1,%2,%3,%4};"
                         :: "r"(dst), "r"(r0), "r"(r1), "r"(r2), "r"(r3) : "memory");
        }
        __syncthreads();

        if (wid == 0 && elect_one()) {
            FENCE_ASYNC();
            const uint64_t dA = DESC_BASE | ((uint64_t)(sb >> 4) & 0x3FFF);
            const uint64_t dB = DESC_BASE | ((uint64_t)((sb + 16384u) >> 4) & 0x3FFF);
#pragma unroll
            for (int k = 0; k < 4; k++) {
                uint32_t en = (c > 0 || k > 0) ? 1u : 0u;
                mma_tf32_ss(tmem, dA + k * 2, dB + k * 2, IDESC, en);
            }
            TCGEN05_COMMIT(barb);
        }
    }

    MBARRIER_WAIT_PARITY(bar0, ph0);
    MBARRIER_WAIT_PARITY(bar1, ph1);
    TCGEN05_FENCE_AFTER();

    {
        const int colh = wid >> 2;
        const int sub  = wid & 3;
        const int r = sub * 32 + lid;
        float* Crow = C + (size_t)(m0 + r) * N + n0 + colh * 64;
        const float* bp = bias ? (bias + n0 + colh * 64) : nullptr;
#pragma unroll
        for (int half = 0; half < 2; half++) {
            uint32_t rr[32];
            TCGEN05_LD_X32(rr, tmem + colh * 64 + half * 32);
            TCGEN05_WAIT_LD();
#pragma unroll
            for (int j = 0; j < 32; j += 4) {
                float4 o;
                o.x = __uint_as_float(rr[j + 0]);
                o.y = __uint_as_float(rr[j + 1]);
                o.z = __uint_as_float(rr[j + 2]);
                o.w = __uint_as_float(rr[j + 3]);
                if (bp) {
                    o.x += bp[half * 32 + j + 0]; o.y += bp[half * 32 + j + 1];
                    o.z += bp[half * 32 + j + 2]; o.w += bp[half * 32 + j + 3];
                }
                *(float4*)(Crow + half * 32 + j) = o;
            }
        }
    }
    TCGEN05_FENCE_BEFORE();
    __syncthreads();
    if (wid == 0) TCGEN05_DEALLOC(tmem, 128);

#else
    __shared__ float As[8][128];
    __shared__ float Ws[8][128];
    const int tid  = threadIdx.x;
    const int ty   = tid >> 4;
    const int tx   = tid & 15;
    const int row0 = blockIdx.y * 128;
    const int col0 = blockIdx.x * 128;
    const int lrow = tid >> 1;
    const int lk   = (tid & 1) * 4;

    const float* Ap = A + (size_t)(row0 + lrow) * K + lk;
    const float* Wp = W + (size_t)(col0 + lrow) * K + lk;
    float acc[8][8];
#pragma unroll
    for (int i = 0; i < 8; i++)
#pragma unroll
        for (int j = 0; j < 8; j++) acc[i][j] = 0.0f;

    for (int k0 = 0; k0 < K; k0 += 8) {
        float4 av = *(const float4*)(Ap + k0);
        float4 wv = *(const float4*)(Wp + k0);
        As[lk + 0][lrow] = av.x; As[lk + 1][lrow] = av.y;
        As[lk + 2][lrow] = av.z; As[lk + 3][lrow] = av.w;
        Ws[lk + 0][lrow] = wv.x; Ws[lk + 1][lrow] = wv.y;
        Ws[lk + 2][lrow] = wv.z; Ws[lk + 3][lrow] = wv.w;
        __syncthreads();
#pragma unroll
        for (int k = 0; k < 8; k++) {
            float a[8], b[8];
            float4 t0 = *(const float4*)(&As[k][ty * 8 + 0]);
            float4 t1 = *(const float4*)(&As[k][ty * 8 + 4]);
            a[0]=t0.x;a[1]=t0.y;a[2]=t0.z;a[3]=t0.w;a[4]=t1.x;a[5]=t1.y;a[6]=t1.z;a[7]=t1.w;
            float4 u0 = *(const float4*)(&Ws[k][tx * 8 + 0]);
            float4 u1 = *(const float4*)(&Ws[k][tx * 8 + 4]);
            b[0]=u0.x;b[1]=u0.y;b[2]=u0.z;b[3]=u0.w;b[4]=u1.x;b[5]=u1.y;b[6]=u1.z;b[7]=u1.w;
#pragma unroll
            for (int i = 0; i < 8; i++)
#pragma unroll
                for (int j = 0; j < 8; j++) acc[i][j] += a[i] * b[j];
        }
        __syncthreads();
    }
#pragma unroll
    for (int i = 0; i < 8; i++) {
        const size_t r = (size_t)(row0 + ty * 8 + i);
#pragma unroll
        for (int j = 0; j < 8; j++) {
            const int cc = col0 + tx * 8 + j;
            float v = acc[i][j];
            if (bias) v += bias[cc];
            C[r * N + cc] = v;
        }
    }
#endif
}

// =================================================================
// GEMM (256x256 tile, 2-stage) — kv projection with fused V^T
// epilogue (r11-proven as part of the 717.8us run).
// =================================================================
#define A256_BYTES 32768
#define B256_BYTES 32768
#define STAGE256 (A256_BYTES + B256_BYTES)       // 64KB
#define GEMMKV_SMEM (2 * STAGE256 + 1024)        // 129KB

__global__ __launch_bounds__(256, 1)
void gemm_tc_kv(const float* __restrict__ A, const float* __restrict__ W,
                float* __restrict__ C, float* __restrict__ vtb,
                int M, int N, int K)
{
#if HAS_TCGEN05
    extern __shared__ char smraw[];
    __shared__ uint64_t mbar[2];
    __shared__ uint32_t tmem_slot;

    const uint32_t smbase = (smem_u32(smraw) + 1023u) & ~1023u;
    const uint32_t bar0 = smem_u32(&mbar[0]);
    const uint32_t bar1 = smem_u32(&mbar[1]);
    const uint32_t slot = smem_u32(&tmem_slot);

    const int tid = threadIdx.x;
    const int wid = tid >> 5;
    const int lid = tid & 31;
    const int m0 = blockIdx.y * 256;
    const int n0 = blockIdx.x * 256;

    if (wid == 0) TCGEN05_ALLOC(slot, 512);
    if (tid == 0) { MBARRIER_INIT(bar0, 1); MBARRIER_INIT(bar1, 1); }
    __syncthreads();
    uint32_t tmem;
    asm volatile("ld.shared.b32 %0, [%1];" : "=r"(tmem) : "r"(slot));
    if (wid == 0) TCGEN05_RELINQ();

    const uint32_t IDESC = (1u << 4) | (2u << 7) | (2u << 10)
                         | ((256u / 8) << 17) | ((128u / 16) << 24);

    const int NC = K / GK;
    int ph0 = 0, ph1 = 0;

    for (int c = 0; c < NC; c++) {
        const int buf = c & 1;
        const uint32_t barb = buf ? bar1 : bar0;
        if (c >= 2) {
            MBARRIER_WAIT_PARITY(barb, (buf ? ph1 : ph0));
            if (buf) ph1 ^= 1; else ph0 ^= 1;
        }
        const uint32_t sb = smbase + buf * STAGE256;
        const float* Ap = A + (size_t)m0 * K + c * GK;
        const float* Wp = W + (size_t)n0 * K + c * GK;

        // A: 256 rows -> A0 (rows<128) @0 / A1 @16K
#pragma unroll
        for (int it = 0; it < 8; it++) {
            int i = tid + it * 256;
            int row = i >> 3, fo = i & 7;
            float4 v = *(const float4*)(Ap + (size_t)row * K + fo * 4);
            uint32_t r0 = f2tf32(v.x), r1 = f2tf32(v.y),
                     r2 = f2tf32(v.z), r3 = f2tf32(v.w);
            uint32_t off = sw128((uint32_t)((row & 127) * 128 + fo * 16));
            uint32_t dst = sb + ((row < 128) ? 0u : 16384u) + off;
            asm volatile("st.shared.v4.b32 [%0], {%1,%2,%3,%4};"
                         :: "r"(dst), "r"(r0), "r"(r1), "r"(r2), "r"(r3) : "memory");
        }
        // B: 256 rows @32K
#pragma unroll
        for (int it = 0; it < 8; it++) {
            int i = tid + it * 256;
            int row = i >> 3, fo = i & 7;
            float4 v = *(const float4*)(Wp + (size_t)row * K + fo * 4);
            uint32_t r0 = f2tf32(v.x), r1 = f2tf32(v.y),
                     r2 = f2tf32(v.z), r3 = f2tf32(v.w);
            uint32_t dst = sb + A256_BYTES + sw128((uint32_t)(row * 128 + fo * 16));
            asm volatile("st.shared.v4.b32 [%0], {%1,%2,%3,%4};"
                         :: "r"(dst), "r"(r0), "r"(r1), "r"(r2), "r"(r3) : "memory");
        }
        __syncthreads();

        if (wid == 0 && elect_one()) {
            FENCE_ASYNC();
            const uint64_t dA0 = DESC_BASE | ((uint64_t)(sb >> 4) & 0x3FFF);
            const uint64_t dA1 = DESC_BASE | ((uint64_t)((sb + 16384u) >> 4) & 0x3FFF);
            const uint64_t dB  = DESC_BASE | ((uint64_t)((sb + A256_BYTES) >> 4) & 0x3FFF);
#pragma unroll
            for (int k = 0; k < 4; k++) {
                uint32_t en = (c > 0 || k > 0) ? 1u : 0u;
                mma_tf32_ss(tmem,       dA0 + k * 2, dB + k * 2, IDESC, en);
                mma_tf32_ss(tmem + 256, dA1 + k * 2, dB + k * 2, IDESC, en);
            }
            TCGEN05_COMMIT(barb);
        }
    }

    MBARRIER_WAIT_PARITY(bar0, ph0);
    MBARRIER_WAIT_PARITY(bar1, ph1);
    TCGEN05_FENCE_AFTER();

    {
        const int tile = wid >> 2;
        const uint32_t dbase = tmem + tile * 256;
        const int rowl = (wid & 3) * 32 + lid;
        const size_t grow = (size_t)m0 + tile * 128 + rowl;    // global row = b*SEQ + s

        if (vtb && n0 >= DIM) {
            const int s  = (int)(grow & (SEQ - 1));
            const int bq = (int)(grow >> 13);
            const size_t vb0 = (size_t)bq * NHEADS * HDIM;
#pragma unroll
            for (int cb = 0; cb < 8; cb++) {
                uint32_t rr[32];
                TCGEN05_LD_X32(rr, dbase + cb * 32);
                TCGEN05_WAIT_LD();
#pragma unroll
                for (int j = 0; j < 32; j++) {
                    const int dcol = (n0 - DIM) + cb * 32 + j;
                    vtb[(vb0 + (size_t)dcol) * SEQ + s] =
                        __uint_as_float(f2tf32(__uint_as_float(rr[j])));
                }
            }
        } else {
            float* Crow = C + grow * N + n0;
#pragma unroll
            for (int cb = 0; cb < 8; cb++) {
                uint32_t rr[32];
                TCGEN05_LD_X32(rr, dbase + cb * 32);
                TCGEN05_WAIT_LD();
#pragma unroll
                for (int j = 0; j < 32; j += 4) {
                    float4 o;
                    o.x = __uint_as_float(rr[j + 0]);
                    o.y = __uint_as_float(rr[j + 1]);
                    o.z = __uint_as_float(rr[j + 2]);
                    o.w = __uint_as_float(rr[j + 3]);
                    *(float4*)(Crow + cb * 32 + j) = o;
                }
            }
        }
    }
    TCGEN05_FENCE_BEFORE();
    __syncthreads();
    if (wid == 0) TCGEN05_DEALLOC(tmem, 512);

#else
    // SIMT fallback: 2x2 subtiles of 128x128 with fused vt on V columns
    __shared__ float As[8][128];
    __shared__ float Ws[8][128];
    const int tid  = threadIdx.x;
    const int ty   = tid >> 4;
    const int tx   = tid & 15;
    const int lrow = tid >> 1;
    const int lk   = (tid & 1) * 4;

    for (int hm = 0; hm < 2; hm++)
    for (int hn = 0; hn < 2; hn++) {
        const int row0 = blockIdx.y * 256 + hm * 128;
        const int col0 = blockIdx.x * 256 + hn * 128;
        const float* Ap = A + (size_t)(row0 + lrow) * K + lk;
        const float* Wp = W + (size_t)(col0 + lrow) * K + lk;
        float acc[8][8];
#pragma unroll
        for (int i = 0; i < 8; i++)
#pragma unroll
            for (int j = 0; j < 8; j++) acc[i][j] = 0.0f;

        for (int k0 = 0; k0 < K; k0 += 8) {
            float4 av = *(const float4*)(Ap + k0);
            float4 wv = *(const float4*)(Wp + k0);
            As[lk + 0][lrow] = av.x; As[lk + 1][lrow] = av.y;
            As[lk + 2][lrow] = av.z; As[lk + 3][lrow] = av.w;
            Ws[lk + 0][lrow] = wv.x; Ws[lk + 1][lrow] = wv.y;
            Ws[lk + 2][lrow] = wv.z; Ws[lk + 3][lrow] = wv.w;
            __syncthreads();
#pragma unroll
            for (int k = 0; k < 8; k++) {
                float a[8], b[8];
                float4 t0 = *(const float4*)(&As[k][ty * 8 + 0]);
                float4 t1 = *(const float4*)(&As[k][ty * 8 + 4]);
                a[0]=t0.x;a[1]=t0.y;a[2]=t0.z;a[3]=t0.w;a[4]=t1.x;a[5]=t1.y;a[6]=t1.z;a[7]=t1.w;
                float4 u0 = *(const float4*)(&Ws[k][tx * 8 + 0]);
                float4 u1 = *(const float4*)(&Ws[k][tx * 8 + 4]);
                b[0]=u0.x;b[1]=u0.y;b[2]=u0.z;b[3]=u0.w;b[4]=u1.x;b[5]=u1.y;b[6]=u1.z;b[7]=u1.w;
#pragma unroll
                for (int i = 0; i < 8; i++)
#pragma unroll
                    for (int j = 0; j < 8; j++) acc[i][j] += a[i] * b[j];
            }
            __syncthreads();
        }
#pragma unroll
        for (int i = 0; i < 8; i++) {
            const size_t grow = (size_t)(row0 + ty * 8 + i);
#pragma unroll
            for (int j = 0; j < 8; j++) {
                const int cc = col0 + tx * 8 + j;
                if (vtb && cc >= DIM) {
                    const int s  = (int)(grow & (SEQ - 1));
                    const int bq = (int)(grow >> 13);
                    vtb[((size_t)bq * NHEADS * HDIM + (cc - DIM)) * SEQ + s] =
                        __uint_as_float(f2tf32(acc[i][j]));
                } else {
                    C[grow * N + cc] = acc[i][j];
                }
            }
        }
        __syncthreads();
    }
#endif
}

// =================================================================
// Tensor-core flash attention — round-9 version (proven 251us).
// =================================================================
#define SCHUNK 128
#define NCH (SEQ / SCHUNK)
#define ATTN_SMEM (3 * 32768 + 1024)
#define SCALE_L2E 0.18033688011112042f   // SCALE * log2(e)

__global__ __launch_bounds__(256, 2)
void attn_tc(const float* __restrict__ q, const float* __restrict__ kv,
             const float* __restrict__ vt, float* __restrict__ out)
{
#if HAS_TCGEN05
    extern __shared__ char smraw[];
    __shared__ uint64_t mbar[2];
    __shared__ uint32_t tmem_slot;
    __shared__ float ls_sh[256];

    const uint32_t smbase = (smem_u32(smraw) + 1023u) & ~1023u;
    const uint32_t QS = smbase;
    const uint32_t KS = smbase + 32768u;
    const uint32_t VS = smbase + 65536u;
    const uint32_t barQK = smem_u32(&mbar[0]);
    const uint32_t barPV = smem_u32(&mbar[1]);
    const uint32_t slot  = smem_u32(&tmem_slot);

    const int tid = threadIdx.x;
    const int wid = tid >> 5;
    const int lid = tid & 31;
    const int bh  = blockIdx.x >> 2;
    const int lt  = blockIdx.x & 3;
    const int b   = bh >> 4, h = bh & 15;
    const int l0  = lt * 128;

    if (wid == 0) TCGEN05_ALLOC(slot, 256);
    if (tid == 0) { MBARRIER_INIT(barQK, 1); MBARRIER_INIT(barPV, 1); }
    __syncthreads();
    uint32_t tmem;
    asm volatile("ld.shared.b32 %0, [%1];" : "=r"(tmem) : "r"(slot));
    if (wid == 0) TCGEN05_RELINQ();
    const uint32_t tmem_SP = tmem;
    const uint32_t tmem_O  = tmem + 128;

    const uint32_t IDESC_S = (1u << 4) | (2u << 7) | (2u << 10)
                           | ((128u / 8) << 17) | ((128u / 16) << 24);
    const uint32_t IDESC_O = (1u << 4) | (2u << 7) | (2u << 10)
                           | ((64u / 8) << 17) | ((128u / 16) << 24);

    const float* kbase = kv + (size_t)b * SEQ * (2 * DIM) + h * HDIM;
    const float* vbase = vt + ((size_t)bh * HDIM) * SEQ;

    const float* qbase = q + ((size_t)b * LAT + l0) * DIM + h * HDIM;
#pragma unroll
    for (int it = 0; it < 8; it++) {
        int i = tid + it * 256;
        int row = i >> 4, f = i & 15;
        int kc = f >> 3, fo = f & 7;
        float4 v = *(const float4*)(qbase + (size_t)row * DIM + f * 4);
        uint32_t r0 = f2tf32(v.x * SCALE_L2E), r1 = f2tf32(v.y * SCALE_L2E);
        uint32_t r2 = f2tf32(v.z * SCALE_L2E), r3 = f2tf32(v.w * SCALE_L2E);
        uint32_t dst = QS + kc * 16384u + sw128((uint32_t)(row * 128 + fo * 16));
        asm volatile("st.shared.v4.b32 [%0], {%1,%2,%3,%4};"
                     :: "r"(dst), "r"(r0), "r"(r1), "r"(r2), "r"(r3) : "memory");
    }

    auto loadK = [&](int ci) {
        const int s0 = ci * SCHUNK;
#pragma unroll
        for (int it = 0; it < 8; it++) {
            int i = tid + it * 256;
            int kr = i >> 4, f = i & 15;
            int kc = f >> 3, fo = f & 7;
            float4 v = *(const float4*)(kbase + (size_t)(s0 + kr) * (2 * DIM) + f * 4);
            uint32_t r0 = f2tf32(v.x), r1 = f2tf32(v.y),
                     r2 = f2tf32(v.z), r3 = f2tf32(v.w);
            uint32_t dst = KS + kc * 16384u + sw128((uint32_t)(kr * 128 + fo * 16));
            asm volatile("st.shared.v4.b32 [%0], {%1,%2,%3,%4};"
                         :: "r"(dst), "r"(r0), "r"(r1), "r"(r2), "r"(r3) : "memory");
        }
    };
    auto loadVT = [&](int ci) {
        const int s0 = ci * SCHUNK;
#pragma unroll
        for (int it = 0; it < 8; it++) {
            int i = tid + it * 256;
            int d = i >> 5, f = i & 31;
            int sc = f >> 3, fo = f & 7;
            float4 v = *(const float4*)(vbase + (size_t)d * SEQ + s0 + f * 4);
            uint32_t dst = VS + sc * 8192u + sw128((uint32_t)(d * 128 + fo * 16));
            asm volatile("st.shared.v4.b32 [%0], {%1,%2,%3,%4};"
                         :: "r"(dst), "r"(__float_as_uint(v.x)), "r"(__float_as_uint(v.y)),
                            "r"(__float_as_uint(v.z)), "r"(__float_as_uint(v.w)) : "memory");
        }
    };

    const uint64_t dQ0 = DESC_BASE | ((uint64_t)(QS >> 4) & 0x3FFF);
    const uint64_t dQ1 = DESC_BASE | ((uint64_t)((QS + 16384u) >> 4) & 0x3FFF);
    const uint64_t dK0 = DESC_BASE | ((uint64_t)(KS >> 4) & 0x3FFF);
    const uint64_t dK1 = DESC_BASE | ((uint64_t)((KS + 16384u) >> 4) & 0x3FFF);

    float lsum = 0.0f;
    int phQK = 0, phPV = 0;

    loadK(0);
    loadVT(0);
    __syncthreads();

    for (int ci = 0; ci < NCH; ci++) {
        if (wid == 0 && elect_one()) {
            FENCE_ASYNC();
#pragma unroll
            for (int blk = 0; blk < 2; blk++) {
                const uint64_t dq = blk ? dQ1 : dQ0;
                const uint64_t dk = blk ? dK1 : dK0;
#pragma unroll
                for (int ks = 0; ks < 4; ks++)
                    mma_tf32_ss(tmem_SP, dq + ks * 2, dk + ks * 2, IDESC_S,
                                (blk > 0 || ks > 0) ? 1u : 0u);
            }
            TCGEN05_COMMIT(barQK);
        }
        MBARRIER_WAIT_PARITY(barQK, phQK); phQK ^= 1;
        TCGEN05_FENCE_AFTER();

        {
            const uint32_t colofs = (uint32_t)(wid >> 2) * 64u;
            const uint32_t wlane  = (uint32_t)(wid & 3) << 21;
#pragma unroll
            for (int blk = 0; blk < 2; blk++) {
                uint32_t rr[32];
                TCGEN05_LD_X32(rr, tmem_SP + colofs + blk * 32);
                TCGEN05_WAIT_LD();
#pragma unroll
                for (int j = 0; j < 32; j++) {
                    float p;
                    asm("ex2.approx.f32 %0, %1;" : "=f"(p) : "f"(__uint_as_float(rr[j])));
                    lsum += p;
                    rr[j] = f2tf32(p);
                }
                TCGEN05_ST_X32(tmem_SP + wlane + colofs + blk * 32, rr);
            }
            TCGEN05_WAIT_ST();
        }
        TCGEN05_FENCE_BEFORE();
        __syncthreads();

        if (wid == 0 && elect_one()) {
            TCGEN05_FENCE_AFTER();
            FENCE_ASYNC();
#pragma unroll
            for (int st = 0; st < 16; st++) {
                const uint64_t dV = DESC_BASE
                    | ((uint64_t)((VS + (st >> 2) * 8192u) >> 4) & 0x3FFF);
                mma_tf32_ts(tmem_O, tmem_SP + st * 8, dV + (st & 3) * 2, IDESC_O,
                            (ci > 0 || st > 0) ? 1u : 0u);
            }
            TCGEN05_COMMIT(barPV);
        }

        if (ci + 1 < NCH) loadK(ci + 1);
        MBARRIER_WAIT_PARITY(barPV, phPV); phPV ^= 1;
        if (ci + 1 < NCH) loadVT(ci + 1);
        __syncthreads();
    }

    TCGEN05_FENCE_AFTER();

    ls_sh[tid] = lsum;
    __syncthreads();

    if (wid < 4) {
        const int r = wid * 32 + lid;
        const float inv = 1.0f / (ls_sh[tid] + ls_sh[tid + 128]);
        float* op = out + ((size_t)b * LAT + l0 + r) * DIM + h * HDIM;
#pragma unroll
        for (int cb = 0; cb < 2; cb++) {
            uint32_t rr[32];
            TCGEN05_LD_X32(rr, tmem_O + cb * 32);
            TCGEN05_WAIT_LD();
#pragma unroll
            for (int j = 0; j < 32; j += 4) {
                float4 o;
                o.x = __uint_as_float(rr[j + 0]) * inv;
                o.y = __uint_as_float(rr[j + 1]) * inv;
                o.z = __uint_as_float(rr[j + 2]) * inv;
                o.w = __uint_as_float(rr[j + 3]) * inv;
                *(float4*)(op + cb * 32 + j) = o;
            }
        }
    }
    TCGEN05_FENCE_BEFORE();
    __syncthreads();
    if (wid == 0) TCGEN05_DEALLOC(tmem, 256);

#else
    // SIMT fallback (thread-per-row; never runs on GB300)
    const int tid = threadIdx.x;
    const int bh  = blockIdx.x >> 2;
    const int lt  = blockIdx.x & 3;
    const int b   = bh >> 4, h = bh & 15;
    const int l0  = lt * 128;
    if (tid < 128) {
        const float* qrow = q + ((size_t)b * LAT + l0 + tid) * DIM + h * HDIM;
        const float* kb = kv + (size_t)b * SEQ * (2 * DIM) + h * HDIM;
        const float* vb = vt + ((size_t)bh * HDIM) * SEQ;
        float qr[64];
#pragma unroll
        for (int d = 0; d < 64; d++) qr[d] = qrow[d] * SCALE;
        float O[64];
#pragma unroll
        for (int d = 0; d < 64; d++) O[d] = 0.0f;
        float l = 0.0f;
        for (int s = 0; s < SEQ; s++) {
            const float* kr = kb + (size_t)s * (2 * DIM);
            float sv = 0.0f;
#pragma unroll 16
            for (int d = 0; d < 64; d++) sv += qr[d] * kr[d];
            float p = __expf(sv);
            l += p;
#pragma unroll 16
            for (int d = 0; d < 64; d++) O[d] += p * vb[(size_t)d * SEQ + s];
        }
        float* op = out + ((size_t)b * LAT + l0 + tid) * DIM + h * HDIM;
        float inv = 1.0f / l;
#pragma unroll
        for (int d = 0; d < 64; d++) op[d] = O[d] * inv;
    }
#endif
}

// =================================================================
// launch
// =================================================================
extern "C" void kernel_launch(void* const* d_in, const int* in_sizes, int n_in,
                              void* d_out, int out_size)
{
    const float* x       = (const float*)d_in[0];
    const float* latents = (const float*)d_in[1];
    if (in_sizes[0] != BATCH * SEQ * DIM) {
        x       = (const float*)d_in[1];
        latents = (const float*)d_in[0];
    }
    const float* w_q   = (const float*)d_in[2];
    const float* w_kv  = (const float*)d_in[3];
    const float* w_out = (const float*)d_in[4];
    const float* b_out = (const float*)d_in[5];
    float* out = (float*)d_out;

    float *q, *kvbuf, *att, *vt;
    cudaGetSymbolAddress((void**)&q,     g_q);
    cudaGetSymbolAddress((void**)&kvbuf, g_kv);
    cudaGetSymbolAddress((void**)&att,   g_att);
    cudaGetSymbolAddress((void**)&vt,    g_vt);

    const int M_q  = BATCH * LAT;    // 2048
    const int M_kv = BATCH * SEQ;    // 32768

    cudaFuncSetAttribute(gemm_tc128, cudaFuncAttributeMaxDynamicSharedMemorySize, GEMM128_SMEM);
    cudaFuncSetAttribute(gemm_tc_kv, cudaFuncAttributeMaxDynamicSharedMemorySize, GEMMKV_SMEM);
    cudaFuncSetAttribute(attn_tc,    cudaFuncAttributeMaxDynamicSharedMemorySize, ATTN_SMEM);

    // 1) q = latents @ w_q^T        (2048 x 1024), 128 CTAs
    gemm_tc128<<<dim3(DIM / 128, M_q / 128), 256, GEMM128_SMEM>>>(
        latents, w_q, q, nullptr, M_q, DIM, DIM);
    // 2) kv = x @ w_kv^T            (32768 x 2048), 1024 CTAs, 2-stage;
    //    V half goes straight to vt (tf32, transposed)
    gemm_tc_kv<<<dim3(2 * DIM / 256, M_kv / 256), 256, GEMMKV_SMEM>>>(
        x, w_kv, kvbuf, vt, M_kv, 2 * DIM, DIM);
    // 3) attention
    attn_tc<<<BATCH * NHEADS * (LAT / 128), 256, ATTN_SMEM>>>(q, kvbuf, vt, att);
    // 4) out = att @ w_out^T + b_out, 128 CTAs
    gemm_tc128<<<dim3(DIM / 128, M_q / 128), 256, GEMM128_SMEM>>>(
        att, w_out, out, b_out, M_q, DIM, DIM);
}

// round 15
// speedup vs baseline: 1.2122x; 1.1027x over previous
#include <cuda_runtime.h>
#include <cstdint>
#include <math.h>

#define DIM       1024
#define NHEADS    16
#define HDIM      64
#define BATCH     4
#define SEQ       8192
#define LAT       512
#define SCALE     0.125f   // 64^-0.5

#if defined(__CUDA_ARCH_FEAT_SM103_ALL) || defined(__CUDA_ARCH_FEAT_SM100_ALL) || \
    (defined(__CUDA_ARCH_SPECIFIC__) && (__CUDA_ARCH_SPECIFIC__ >= 1000))
#define HAS_TCGEN05 1
#else
#define HAS_TCGEN05 0
#endif

// -------- scratch (device globals; no allocation allowed) --------
__device__ float g_q  [(size_t)BATCH * LAT * DIM];                    // 8 MB
__device__ float g_kv [(size_t)BATCH * SEQ * 2 * DIM];                // 268 MB (V half unused)
__device__ float g_att[(size_t)BATCH * LAT * DIM];                    // 8 MB
__device__ float g_vt [(size_t)BATCH * NHEADS * HDIM * SEQ];          // 134 MB (V^T, tf32)

// ================= helpers =================
__device__ __forceinline__ uint32_t smem_u32(const void* p) {
    uint32_t a;
    asm("{ .reg .u64 t; cvta.to.shared.u64 t, %1; cvt.u32.u64 %0, t; }"
        : "=r"(a) : "l"(p));
    return a;
}
__device__ __forceinline__ uint32_t f2tf32(float f) {
    uint32_t r;
    asm("cvt.rna.tf32.f32 %0, %1;" : "=r"(r) : "f"(f));
    return r;
}

#if HAS_TCGEN05
__device__ __forceinline__ uint32_t elect_one() {
    uint32_t p;
    asm volatile("{ .reg .pred p; elect.sync _|p, 0xFFFFFFFF; selp.b32 %0,1,0,p; }"
                 : "=r"(p));
    return p;
}

#define MBARRIER_INIT(addr, cnt) \
    asm volatile("mbarrier.init.shared.b64 [%0], %1;" :: "r"(addr), "r"(cnt) : "memory")

#define MBARRIER_WAIT_PARITY(mbar, par) do {                                   \
    uint32_t _m = (mbar); uint32_t _p = (par); uint32_t _done;                 \
    asm volatile("{\n\t.reg .pred p;\n\t"                                      \
        "mbarrier.try_wait.parity.acquire.cta.shared::cta.b64 p, [%1], %2;\n\t"\
        "selp.b32 %0, 1, 0, p;\n\t}"                                           \
        : "=r"(_done) : "r"(_m), "r"(_p) : "memory");                          \
    if (!_done) {                                                              \
        asm volatile("{\n\t.reg .pred P1;\n\t"                                 \
            "WL_%=:\n\t"                                                       \
            "mbarrier.try_wait.parity.acquire.cta.shared::cta.b64 P1, [%0], %1, 0x989680;\n\t" \
            "@P1 bra.uni WD_%=;\n\t"                                           \
            "bra.uni WL_%=;\n\t"                                               \
            "WD_%=:\n\t}"                                                      \
            :: "r"(_m), "r"(_p) : "memory");                                   \
    }                                                                          \
} while (0)

#define TCGEN05_ALLOC(slot, n) \
    asm volatile("tcgen05.alloc.cta_group::1.sync.aligned.shared::cta.b32 [%0], %1;" \
                 :: "r"(slot), "r"(n) : "memory")
#define TCGEN05_DEALLOC(tm, n) \
    asm volatile("tcgen05.dealloc.cta_group::1.sync.aligned.b32 %0, %1;" :: "r"(tm), "r"(n))
#define TCGEN05_RELINQ() \
    asm volatile("tcgen05.relinquish_alloc_permit.cta_group::1.sync.aligned;")
#define TCGEN05_COMMIT(mbar) \
    asm volatile("tcgen05.commit.cta_group::1.mbarrier::arrive::one.shared::cluster.b64 [%0];" \
                 :: "r"(mbar) : "memory")
#define TCGEN05_WAIT_LD() asm volatile("tcgen05.wait::ld.sync.aligned;" ::: "memory")
#define TCGEN05_WAIT_ST() asm volatile("tcgen05.wait::st.sync.aligned;" ::: "memory")
#define TCGEN05_FENCE_AFTER() asm volatile("tcgen05.fence::after_thread_sync;" ::: "memory")
#define TCGEN05_FENCE_BEFORE() asm volatile("tcgen05.fence::before_thread_sync;" ::: "memory")
#define FENCE_ASYNC() asm volatile("fence.proxy.async.shared::cta;" ::: "memory")

#define TCGEN05_LD_X32(r, addr)                                                \
    asm volatile("tcgen05.ld.sync.aligned.32x32b.x32.b32 "                     \
        "{%0,%1,%2,%3,%4,%5,%6,%7,%8,%9,%10,%11,%12,%13,%14,%15,"              \
        "%16,%17,%18,%19,%20,%21,%22,%23,%24,%25,%26,%27,%28,%29,%30,%31}, [%32];" \
        : "=r"((r)[0]),"=r"((r)[1]),"=r"((r)[2]),"=r"((r)[3]),                 \
          "=r"((r)[4]),"=r"((r)[5]),"=r"((r)[6]),"=r"((r)[7]),                 \
          "=r"((r)[8]),"=r"((r)[9]),"=r"((r)[10]),"=r"((r)[11]),               \
          "=r"((r)[12]),"=r"((r)[13]),"=r"((r)[14]),"=r"((r)[15]),             \
          "=r"((r)[16]),"=r"((r)[17]),"=r"((r)[18]),"=r"((r)[19]),             \
          "=r"((r)[20]),"=r"((r)[21]),"=r"((r)[22]),"=r"((r)[23]),             \
          "=r"((r)[24]),"=r"((r)[25]),"=r"((r)[26]),"=r"((r)[27]),             \
          "=r"((r)[28]),"=r"((r)[29]),"=r"((r)[30]),"=r"((r)[31])              \
        : "r"(addr))

#define TCGEN05_ST_X32(addr, r)                                                \
    asm volatile("tcgen05.st.sync.aligned.32x32b.x32.b32 [%0], "               \
        "{%1,%2,%3,%4,%5,%6,%7,%8,%9,%10,%11,%12,%13,%14,%15,%16,"             \
        "%17,%18,%19,%20,%21,%22,%23,%24,%25,%26,%27,%28,%29,%30,%31,%32};"    \
        :: "r"(addr),                                                          \
           "r"((r)[0]),"r"((r)[1]),"r"((r)[2]),"r"((r)[3]),                    \
           "r"((r)[4]),"r"((r)[5]),"r"((r)[6]),"r"((r)[7]),                    \
           "r"((r)[8]),"r"((r)[9]),"r"((r)[10]),"r"((r)[11]),                  \
           "r"((r)[12]),"r"((r)[13]),"r"((r)[14]),"r"((r)[15]),                \
           "r"((r)[16]),"r"((r)[17]),"r"((r)[18]),"r"((r)[19]),                \
           "r"((r)[20]),"r"((r)[21]),"r"((r)[22]),"r"((r)[23]),                \
           "r"((r)[24]),"r"((r)[25]),"r"((r)[26]),"r"((r)[27]),                \
           "r"((r)[28]),"r"((r)[29]),"r"((r)[30]),"r"((r)[31])                 \
        : "memory")

__device__ __forceinline__ void mma_tf32_ss(uint32_t d_tmem, uint64_t a_desc,
                                            uint64_t b_desc, uint32_t idesc,
                                            uint32_t enable) {
    asm volatile(
        "{\n\t.reg .pred p;\n\t"
        "setp.ne.u32 p, %4, 0;\n\t"
        "tcgen05.mma.cta_group::1.kind::tf32 [%0], %1, %2, %3, {%5,%5,%5,%5}, p;\n\t}"
        :: "r"(d_tmem), "l"(a_desc), "l"(b_desc), "r"(idesc), "r"(enable), "r"(0u)
        : "memory");
}
__device__ __forceinline__ void mma_tf32_ts(uint32_t d_tmem, uint32_t a_tmem,
                                            uint64_t b_desc, uint32_t idesc,
                                            uint32_t enable) {
    asm volatile(
        "{\n\t.reg .pred p;\n\t"
        "setp.ne.u32 p, %4, 0;\n\t"
        "tcgen05.mma.cta_group::1.kind::tf32 [%0], [%1], %2, %3, {%5,%5,%5,%5}, p;\n\t}"
        :: "r"(d_tmem), "r"(a_tmem), "l"(b_desc), "r"(idesc), "r"(enable), "r"(0u)
        : "memory");
}
#endif  // HAS_TCGEN05

// SW128 K-major descriptor base: layout=SW128(2), version=1, SBO=64, LBO=1
static constexpr uint64_t DESC_BASE =
    (2ull << 61) | (1ull << 46) | (64ull << 32) | (1ull << 16);

__device__ __forceinline__ uint32_t sw128(uint32_t off) {
    return off ^ ((off >> 3) & 0x70);
}

#define GK 32

// =================================================================
// GEMM (128x128 tile) — small projections (measured 51-52us, proven)
// =================================================================
#define G128_STAGE 32768                      // A 16K + B 16K
#define GEMM128_SMEM (2 * G128_STAGE + 1024)

__global__ __launch_bounds__(256, 2)
void gemm_tc128(const float* __restrict__ A, const float* __restrict__ W,
                float* __restrict__ C, const float* __restrict__ bias,
                int M, int N, int K)
{
#if HAS_TCGEN05
    extern __shared__ char smraw[];
    __shared__ uint64_t mbar[2];
    __shared__ uint32_t tmem_slot;

    const uint32_t smbase = (smem_u32(smraw) + 1023u) & ~1023u;
    const uint32_t bar0 = smem_u32(&mbar[0]);
    const uint32_t bar1 = smem_u32(&mbar[1]);
    const uint32_t slot = smem_u32(&tmem_slot);

    const int tid = threadIdx.x;
    const int wid = tid >> 5;
    const int lid = tid & 31;
    const int m0 = blockIdx.y * 128;
    const int n0 = blockIdx.x * 128;

    if (wid == 0) TCGEN05_ALLOC(slot, 128);
    if (tid == 0) { MBARRIER_INIT(bar0, 1); MBARRIER_INIT(bar1, 1); }
    __syncthreads();
    uint32_t tmem;
    asm volatile("ld.shared.b32 %0, [%1];" : "=r"(tmem) : "r"(slot));
    if (wid == 0) TCGEN05_RELINQ();

    const uint32_t IDESC = (1u << 4) | (2u << 7) | (2u << 10)
                         | ((128u / 8) << 17) | ((128u / 16) << 24);

    const int NC = K / GK;
    int ph0 = 0, ph1 = 0;

    for (int c = 0; c < NC; c++) {
        const int buf = c & 1;
        const uint32_t barb = buf ? bar1 : bar0;
        if (c >= 2) {
            MBARRIER_WAIT_PARITY(barb, (buf ? ph1 : ph0));
            if (buf) ph1 ^= 1; else ph0 ^= 1;
        }
        const uint32_t sb = smbase + buf * G128_STAGE;
        const float* Ap = A + (size_t)m0 * K + c * GK;
        const float* Wp = W + (size_t)n0 * K + c * GK;

#pragma unroll
        for (int it = 0; it < 4; it++) {
            int i = tid + it * 256;
            int row = i >> 3, fo = i & 7;
            float4 v = *(const float4*)(Ap + (size_t)row * K + fo * 4);
            uint32_t r0 = f2tf32(v.x), r1 = f2tf32(v.y),
                     r2 = f2tf32(v.z), r3 = f2tf32(v.w);
            uint32_t dst = sb + sw128((uint32_t)(row * 128 + fo * 16));
            asm volatile("st.shared.v4.b32 [%0], {%1,%2,%3,%4};"
                         :: "r"(dst), "r"(r0), "r"(r1), "r"(r2), "r"(r3) : "memory");
        }
#pragma unroll
        for (int it = 0; it < 4; it++) {
            int i = tid + it * 256;
            int row = i >> 3, fo = i & 7;
            float4 v = *(const float4*)(Wp + (size_t)row * K + fo * 4);
            uint32_t r0 = f2tf32(v.x), r1 = f2tf32(v.y),
                     r2 = f2tf32(v.z), r3 = f2tf32(v.w);
            uint32_t dst = sb + 16384u + sw128((uint32_t)(row * 128 + fo * 16));
            asm volatile("st.shared.v4.b32 [%0], {%1,%2,%3,%4};"
                         :: "r"(dst), "r"(r0), "r"(r1), "r"(r2), "r"(r3) : "memory");
        }
        __syncthreads();

        if (wid == 0 && elect_one()) {
            FENCE_ASYNC();
            const uint64_t dA = DESC_BASE | ((uint64_t)(sb >> 4) & 0x3FFF);
            const uint64_t dB = DESC_BASE | ((uint64_t)((sb + 16384u) >> 4) & 0x3FFF);
#pragma unroll
            for (int k = 0; k < 4; k++) {
                uint32_t en = (c > 0 || k > 0) ? 1u : 0u;
                mma_tf32_ss(tmem, dA + k * 2, dB + k * 2, IDESC, en);
            }
            TCGEN05_COMMIT(barb);
        }
    }

    MBARRIER_WAIT_PARITY(bar0, ph0);
    MBARRIER_WAIT_PARITY(bar1, ph1);
    TCGEN05_FENCE_AFTER();

    {
        const int colh = wid >> 2;
        const int sub  = wid & 3;
        const int r = sub * 32 + lid;
        float* Crow = C + (size_t)(m0 + r) * N + n0 + colh * 64;
        const float* bp = bias ? (bias + n0 + colh * 64) : nullptr;
#pragma unroll
        for (int half = 0; half < 2; half++) {
            uint32_t rr[32];
            TCGEN05_LD_X32(rr, tmem + colh * 64 + half * 32);
            TCGEN05_WAIT_LD();
#pragma unroll
            for (int j = 0; j < 32; j += 4) {
                float4 o;
                o.x = __uint_as_float(rr[j + 0]);
                o.y = __uint_as_float(rr[j + 1]);
                o.z = __uint_as_float(rr[j + 2]);
                o.w = __uint_as_float(rr[j + 3]);
                if (bp) {
                    o.x += bp[half * 32 + j + 0]; o.y += bp[half * 32 + j + 1];
                    o.z += bp[half * 32 + j + 2]; o.w += bp[half * 32 + j + 3];
                }
                *(float4*)(Crow + half * 32 + j) = o;
            }
        }
    }
    TCGEN05_FENCE_BEFORE();
    __syncthreads();
    if (wid == 0) TCGEN05_DEALLOC(tmem, 128);

#else
    __shared__ float As[8][128];
    __shared__ float Ws[8][128];
    const int tid  = threadIdx.x;
    const int ty   = tid >> 4;
    const int tx   = tid & 15;
    const int row0 = blockIdx.y * 128;
    const int col0 = blockIdx.x * 128;
    const int lrow = tid >> 1;
    const int lk   = (tid & 1) * 4;

    const float* Ap = A + (size_t)(row0 + lrow) * K + lk;
    const float* Wp = W + (size_t)(col0 + lrow) * K + lk;
    float acc[8][8];
#pragma unroll
    for (int i = 0; i < 8; i++)
#pragma unroll
        for (int j = 0; j < 8; j++) acc[i][j] = 0.0f;

    for (int k0 = 0; k0 < K; k0 += 8) {
        float4 av = *(const float4*)(Ap + k0);
        float4 wv = *(const float4*)(Wp + k0);
        As[lk + 0][lrow] = av.x; As[lk + 1][lrow] = av.y;
        As[lk + 2][lrow] = av.z; As[lk + 3][lrow] = av.w;
        Ws[lk + 0][lrow] = wv.x; Ws[lk + 1][lrow] = wv.y;
        Ws[lk + 2][lrow] = wv.z; Ws[lk + 3][lrow] = wv.w;
        __syncthreads();
#pragma unroll
        for (int k = 0; k < 8; k++) {
            float a[8], b[8];
            float4 t0 = *(const float4*)(&As[k][ty * 8 + 0]);
            float4 t1 = *(const float4*)(&As[k][ty * 8 + 4]);
            a[0]=t0.x;a[1]=t0.y;a[2]=t0.z;a[3]=t0.w;a[4]=t1.x;a[5]=t1.y;a[6]=t1.z;a[7]=t1.w;
            float4 u0 = *(const float4*)(&Ws[k][tx * 8 + 0]);
            float4 u1 = *(const float4*)(&Ws[k][tx * 8 + 4]);
            b[0]=u0.x;b[1]=u0.y;b[2]=u0.z;b[3]=u0.w;b[4]=u1.x;b[5]=u1.y;b[6]=u1.z;b[7]=u1.w;
#pragma unroll
            for (int i = 0; i < 8; i++)
#pragma unroll
                for (int j = 0; j < 8; j++) acc[i][j] += a[i] * b[j];
        }
        __syncthreads();
    }
#pragma unroll
    for (int i = 0; i < 8; i++) {
        const size_t r = (size_t)(row0 + ty * 8 + i);
#pragma unroll
        for (int j = 0; j < 8; j++) {
            const int cc = col0 + tx * 8 + j;
            float v = acc[i][j];
            if (bias) v += bias[cc];
            C[r * N + cc] = v;
        }
    }
#endif
}

// =================================================================
// GEMM (256x256 tile, 2-stage, register-staged loads) — kv projection
// with fused V^T epilogue. LDG for chunk c+1 issues before MMA(c) so
// its latency hides under the MMA; only cvt+STS remain on the path.
// =================================================================
#define A256_BYTES 32768
#define B256_BYTES 32768
#define STAGE256 (A256_BYTES + B256_BYTES)       // 64KB
#define GEMMKV_SMEM (2 * STAGE256 + 1024)        // 129KB

__global__ __launch_bounds__(256, 1)
void gemm_tc_kv(const float* __restrict__ A, const float* __restrict__ W,
                float* __restrict__ C, float* __restrict__ vtb,
                int M, int N, int K)
{
#if HAS_TCGEN05
    extern __shared__ char smraw[];
    __shared__ uint64_t mbar[2];
    __shared__ uint32_t tmem_slot;

    const uint32_t smbase = (smem_u32(smraw) + 1023u) & ~1023u;
    const uint32_t bar0 = smem_u32(&mbar[0]);
    const uint32_t bar1 = smem_u32(&mbar[1]);
    const uint32_t slot = smem_u32(&tmem_slot);

    const int tid = threadIdx.x;
    const int wid = tid >> 5;
    const int lid = tid & 31;
    const int m0 = blockIdx.y * 256;
    const int n0 = blockIdx.x * 256;

    if (wid == 0) TCGEN05_ALLOC(slot, 512);
    if (tid == 0) { MBARRIER_INIT(bar0, 1); MBARRIER_INIT(bar1, 1); }
    __syncthreads();
    uint32_t tmem;
    asm volatile("ld.shared.b32 %0, [%1];" : "=r"(tmem) : "r"(slot));
    if (wid == 0) TCGEN05_RELINQ();

    const uint32_t IDESC = (1u << 4) | (2u << 7) | (2u << 10)
                         | ((256u / 8) << 17) | ((128u / 16) << 24);

    const int NC = K / GK;
    int ph0 = 0, ph1 = 0;

    // precomputed per-thread indices: i = tid + it*256, row = i>>3, fo = i&7
    const int row_ = tid >> 3;          // + it*32
    const int fo_  = tid & 7;

    float4 ra[8], rb[8];
    // preload chunk 0 into registers
    {
        const float* Ap = A + (size_t)m0 * K;
        const float* Wp = W + (size_t)n0 * K;
#pragma unroll
        for (int it = 0; it < 8; it++) {
            int row = row_ + it * 32;
            ra[it] = *(const float4*)(Ap + (size_t)row * K + fo_ * 4);
            rb[it] = *(const float4*)(Wp + (size_t)row * K + fo_ * 4);
        }
    }

    for (int c = 0; c < NC; c++) {
        const int buf = c & 1;
        const uint32_t barb = buf ? bar1 : bar0;
        if (c >= 2) {
            MBARRIER_WAIT_PARITY(barb, (buf ? ph1 : ph0));
            if (buf) ph1 ^= 1; else ph0 ^= 1;
        }
        const uint32_t sb = smbase + buf * STAGE256;

        // cvt+STS the registers staged last iteration
#pragma unroll
        for (int it = 0; it < 8; it++) {
            int row = row_ + it * 32;
            float4 v = ra[it];
            uint32_t r0 = f2tf32(v.x), r1 = f2tf32(v.y),
                     r2 = f2tf32(v.z), r3 = f2tf32(v.w);
            uint32_t off = sw128((uint32_t)((row & 127) * 128 + fo_ * 16));
            uint32_t dst = sb + ((row < 128) ? 0u : 16384u) + off;
            asm volatile("st.shared.v4.b32 [%0], {%1,%2,%3,%4};"
                         :: "r"(dst), "r"(r0), "r"(r1), "r"(r2), "r"(r3) : "memory");
        }
#pragma unroll
        for (int it = 0; it < 8; it++) {
            int row = row_ + it * 32;
            float4 v = rb[it];
            uint32_t r0 = f2tf32(v.x), r1 = f2tf32(v.y),
                     r2 = f2tf32(v.z), r3 = f2tf32(v.w);
            uint32_t dst = sb + A256_BYTES + sw128((uint32_t)(row * 128 + fo_ * 16));
            asm volatile("st.shared.v4.b32 [%0], {%1,%2,%3,%4};"
                         :: "r"(dst), "r"(r0), "r"(r1), "r"(r2), "r"(r3) : "memory");
        }

        // prefetch chunk c+1 into registers — latency hides under MMA(c)
        if (c + 1 < NC) {
            const float* Ap = A + (size_t)m0 * K + (c + 1) * GK;
            const float* Wp = W + (size_t)n0 * K + (c + 1) * GK;
#pragma unroll
            for (int it = 0; it < 8; it++) {
                int row = row_ + it * 32;
                ra[it] = *(const float4*)(Ap + (size_t)row * K + fo_ * 4);
                rb[it] = *(const float4*)(Wp + (size_t)row * K + fo_ * 4);
            }
        }

        __syncthreads();

        if (wid == 0 && elect_one()) {
            FENCE_ASYNC();
            const uint64_t dA0 = DESC_BASE | ((uint64_t)(sb >> 4) & 0x3FFF);
            const uint64_t dA1 = DESC_BASE | ((uint64_t)((sb + 16384u) >> 4) & 0x3FFF);
            const uint64_t dB  = DESC_BASE | ((uint64_t)((sb + A256_BYTES) >> 4) & 0x3FFF);
#pragma unroll
            for (int k = 0; k < 4; k++) {
                uint32_t en = (c > 0 || k > 0) ? 1u : 0u;
                mma_tf32_ss(tmem,       dA0 + k * 2, dB + k * 2, IDESC, en);
                mma_tf32_ss(tmem + 256, dA1 + k * 2, dB + k * 2, IDESC, en);
            }
            TCGEN05_COMMIT(barb);
        }
    }

    MBARRIER_WAIT_PARITY(bar0, ph0);
    MBARRIER_WAIT_PARITY(bar1, ph1);
    TCGEN05_FENCE_AFTER();

    {
        const int tile = wid >> 2;
        const uint32_t dbase = tmem + tile * 256;
        const int rowl = (wid & 3) * 32 + lid;
        const size_t grow = (size_t)m0 + tile * 128 + rowl;    // global row = b*SEQ + s

        if (vtb && n0 >= DIM) {
            const int s  = (int)(grow & (SEQ - 1));
            const int bq = (int)(grow >> 13);
            const size_t vb0 = (size_t)bq * NHEADS * HDIM;
#pragma unroll
            for (int cb = 0; cb < 8; cb++) {
                uint32_t rr[32];
                TCGEN05_LD_X32(rr, dbase + cb * 32);
                TCGEN05_WAIT_LD();
#pragma unroll
                for (int j = 0; j < 32; j++) {
                    const int dcol = (n0 - DIM) + cb * 32 + j;
                    vtb[(vb0 + (size_t)dcol) * SEQ + s] =
                        __uint_as_float(f2tf32(__uint_as_float(rr[j])));
                }
            }
        } else {
            float* Crow = C + grow * N + n0;
#pragma unroll
            for (int cb = 0; cb < 8; cb++) {
                uint32_t rr[32];
                TCGEN05_LD_X32(rr, dbase + cb * 32);
                TCGEN05_WAIT_LD();
#pragma unroll
                for (int j = 0; j < 32; j += 4) {
                    float4 o;
                    o.x = __uint_as_float(rr[j + 0]);
                    o.y = __uint_as_float(rr[j + 1]);
                    o.z = __uint_as_float(rr[j + 2]);
                    o.w = __uint_as_float(rr[j + 3]);
                    *(float4*)(Crow + cb * 32 + j) = o;
                }
            }
        }
    }
    TCGEN05_FENCE_BEFORE();
    __syncthreads();
    if (wid == 0) TCGEN05_DEALLOC(tmem, 512);

#else
    // SIMT fallback: 2x2 subtiles of 128x128 with fused vt on V columns
    __shared__ float As[8][128];
    __shared__ float Ws[8][128];
    const int tid  = threadIdx.x;
    const int ty   = tid >> 4;
    const int tx   = tid & 15;
    const int lrow = tid >> 1;
    const int lk   = (tid & 1) * 4;

    for (int hm = 0; hm < 2; hm++)
    for (int hn = 0; hn < 2; hn++) {
        const int row0 = blockIdx.y * 256 + hm * 128;
        const int col0 = blockIdx.x * 256 + hn * 128;
        const float* Ap = A + (size_t)(row0 + lrow) * K + lk;
        const float* Wp = W + (size_t)(col0 + lrow) * K + lk;
        float acc[8][8];
#pragma unroll
        for (int i = 0; i < 8; i++)
#pragma unroll
            for (int j = 0; j < 8; j++) acc[i][j] = 0.0f;

        for (int k0 = 0; k0 < K; k0 += 8) {
            float4 av = *(const float4*)(Ap + k0);
            float4 wv = *(const float4*)(Wp + k0);
            As[lk + 0][lrow] = av.x; As[lk + 1][lrow] = av.y;
            As[lk + 2][lrow] = av.z; As[lk + 3][lrow] = av.w;
            Ws[lk + 0][lrow] = wv.x; Ws[lk + 1][lrow] = wv.y;
            Ws[lk + 2][lrow] = wv.z; Ws[lk + 3][lrow] = wv.w;
            __syncthreads();
#pragma unroll
            for (int k = 0; k < 8; k++) {
                float a[8], b[8];
                float4 t0 = *(const float4*)(&As[k][ty * 8 + 0]);
                float4 t1 = *(const float4*)(&As[k][ty * 8 + 4]);
                a[0]=t0.x;a[1]=t0.y;a[2]=t0.z;a[3]=t0.w;a[4]=t1.x;a[5]=t1.y;a[6]=t1.z;a[7]=t1.w;
                float4 u0 = *(const float4*)(&Ws[k][tx * 8 + 0]);
                float4 u1 = *(const float4*)(&Ws[k][tx * 8 + 4]);
                b[0]=u0.x;b[1]=u0.y;b[2]=u0.z;b[3]=u0.w;b[4]=u1.x;b[5]=u1.y;b[6]=u1.z;b[7]=u1.w;
#pragma unroll
                for (int i = 0; i < 8; i++)
#pragma unroll
                    for (int j = 0; j < 8; j++) acc[i][j] += a[i] * b[j];
            }
            __syncthreads();
        }
#pragma unroll
        for (int i = 0; i < 8; i++) {
            const size_t grow = (size_t)(row0 + ty * 8 + i);
#pragma unroll
            for (int j = 0; j < 8; j++) {
                const int cc = col0 + tx * 8 + j;
                if (vtb && cc >= DIM) {
                    const int s  = (int)(grow & (SEQ - 1));
                    const int bq = (int)(grow >> 13);
                    vtb[((size_t)bq * NHEADS * HDIM + (cc - DIM)) * SEQ + s] =
                        __uint_as_float(f2tf32(acc[i][j]));
                } else {
                    C[grow * N + cc] = acc[i][j];
                }
            }
        }
        __syncthreads();
    }
#endif
}

// =================================================================
// Tensor-core flash attention — round-9 version (proven 251us).
// =================================================================
#define SCHUNK 128
#define NCH (SEQ / SCHUNK)
#define ATTN_SMEM (3 * 32768 + 1024)
#define SCALE_L2E 0.18033688011112042f   // SCALE * log2(e)

__global__ __launch_bounds__(256, 2)
void attn_tc(const float* __restrict__ q, const float* __restrict__ kv,
             const float* __restrict__ vt, float* __restrict__ out)
{
#if HAS_TCGEN05
    extern __shared__ char smraw[];
    __shared__ uint64_t mbar[2];
    __shared__ uint32_t tmem_slot;
    __shared__ float ls_sh[256];

    const uint32_t smbase = (smem_u32(smraw) + 1023u) & ~1023u;
    const uint32_t QS = smbase;
    const uint32_t KS = smbase + 32768u;
    const uint32_t VS = smbase + 65536u;
    const uint32_t barQK = smem_u32(&mbar[0]);
    const uint32_t barPV = smem_u32(&mbar[1]);
    const uint32_t slot  = smem_u32(&tmem_slot);

    const int tid = threadIdx.x;
    const int wid = tid >> 5;
    const int lid = tid & 31;
    const int bh  = blockIdx.x >> 2;
    const int lt  = blockIdx.x & 3;
    const int b   = bh >> 4, h = bh & 15;
    const int l0  = lt * 128;

    if (wid == 0) TCGEN05_ALLOC(slot, 256);
    if (tid == 0) { MBARRIER_INIT(barQK, 1); MBARRIER_INIT(barPV, 1); }
    __syncthreads();
    uint32_t tmem;
    asm volatile("ld.shared.b32 %0, [%1];" : "=r"(tmem) : "r"(slot));
    if (wid == 0) TCGEN05_RELINQ();
    const uint32_t tmem_SP = tmem;
    const uint32_t tmem_O  = tmem + 128;

    const uint32_t IDESC_S = (1u << 4) | (2u << 7) | (2u << 10)
                           | ((128u / 8) << 17) | ((128u / 16) << 24);
    const uint32_t IDESC_O = (1u << 4) | (2u << 7) | (2u << 10)
                           | ((64u / 8) << 17) | ((128u / 16) << 24);

    const float* kbase = kv + (size_t)b * SEQ * (2 * DIM) + h * HDIM;
    const float* vbase = vt + ((size_t)bh * HDIM) * SEQ;

    const float* qbase = q + ((size_t)b * LAT + l0) * DIM + h * HDIM;
#pragma unroll
    for (int it = 0; it < 8; it++) {
        int i = tid + it * 256;
        int row = i >> 4, f = i & 15;
        int kc = f >> 3, fo = f & 7;
        float4 v = *(const float4*)(qbase + (size_t)row * DIM + f * 4);
        uint32_t r0 = f2tf32(v.x * SCALE_L2E), r1 = f2tf32(v.y * SCALE_L2E);
        uint32_t r2 = f2tf32(v.z * SCALE_L2E), r3 = f2tf32(v.w * SCALE_L2E);
        uint32_t dst = QS + kc * 16384u + sw128((uint32_t)(row * 128 + fo * 16));
        asm volatile("st.shared.v4.b32 [%0], {%1,%2,%3,%4};"
                     :: "r"(dst), "r"(r0), "r"(r1), "r"(r2), "r"(r3) : "memory");
    }

    auto loadK = [&](int ci) {
        const int s0 = ci * SCHUNK;
#pragma unroll
        for (int it = 0; it < 8; it++) {
            int i = tid + it * 256;
            int kr = i >> 4, f = i & 15;
            int kc = f >> 3, fo = f & 7;
            float4 v = *(const float4*)(kbase + (size_t)(s0 + kr) * (2 * DIM) + f * 4);
            uint32_t r0 = f2tf32(v.x), r1 = f2tf32(v.y),
                     r2 = f2tf32(v.z), r3 = f2tf32(v.w);
            uint32_t dst = KS + kc * 16384u + sw128((uint32_t)(kr * 128 + fo * 16));
            asm volatile("st.shared.v4.b32 [%0], {%1,%2,%3,%4};"
                         :: "r"(dst), "r"(r0), "r"(r1), "r"(r2), "r"(r3) : "memory");
        }
    };
    auto loadVT = [&](int ci) {
        const int s0 = ci * SCHUNK;
#pragma unroll
        for (int it = 0; it < 8; it++) {
            int i = tid + it * 256;
            int d = i >> 5, f = i & 31;
            int sc = f >> 3, fo = f & 7;
            float4 v = *(const float4*)(vbase + (size_t)d * SEQ + s0 + f * 4);
            uint32_t dst = VS + sc * 8192u + sw128((uint32_t)(d * 128 + fo * 16));
            asm volatile("st.shared.v4.b32 [%0], {%1,%2,%3,%4};"
                         :: "r"(dst), "r"(__float_as_uint(v.x)), "r"(__float_as_uint(v.y)),
                            "r"(__float_as_uint(v.z)), "r"(__float_as_uint(v.w)) : "memory");
        }
    };

    const uint64_t dQ0 = DESC_BASE | ((uint64_t)(QS >> 4) & 0x3FFF);
    const uint64_t dQ1 = DESC_BASE | ((uint64_t)((QS + 16384u) >> 4) & 0x3FFF);
    const uint64_t dK0 = DESC_BASE | ((uint64_t)(KS >> 4) & 0x3FFF);
    const uint64_t dK1 = DESC_BASE | ((uint64_t)((KS + 16384u) >> 4) & 0x3FFF);

    float lsum = 0.0f;
    int phQK = 0, phPV = 0;

    loadK(0);
    loadVT(0);
    __syncthreads();

    for (int ci = 0; ci < NCH; ci++) {
        if (wid == 0 && elect_one()) {
            FENCE_ASYNC();
#pragma unroll
            for (int blk = 0; blk < 2; blk++) {
                const uint64_t dq = blk ? dQ1 : dQ0;
                const uint64_t dk = blk ? dK1 : dK0;
#pragma unroll
                for (int ks = 0; ks < 4; ks++)
                    mma_tf32_ss(tmem_SP, dq + ks * 2, dk + ks * 2, IDESC_S,
                                (blk > 0 || ks > 0) ? 1u : 0u);
            }
            TCGEN05_COMMIT(barQK);
        }
        MBARRIER_WAIT_PARITY(barQK, phQK); phQK ^= 1;
        TCGEN05_FENCE_AFTER();

        {
            const uint32_t colofs = (uint32_t)(wid >> 2) * 64u;
            const uint32_t wlane  = (uint32_t)(wid & 3) << 21;
#pragma unroll
            for (int blk = 0; blk < 2; blk++) {
                uint32_t rr[32];
                TCGEN05_LD_X32(rr, tmem_SP + colofs + blk * 32);
                TCGEN05_WAIT_LD();
#pragma unroll
                for (int j = 0; j < 32; j++) {
                    float p;
                    asm("ex2.approx.f32 %0, %1;" : "=f"(p) : "f"(__uint_as_float(rr[j])));
                    lsum += p;
                    rr[j] = f2tf32(p);
                }
                TCGEN05_ST_X32(tmem_SP + wlane + colofs + blk * 32, rr);
            }
            TCGEN05_WAIT_ST();
        }
        TCGEN05_FENCE_BEFORE();
        __syncthreads();

        if (wid == 0 && elect_one()) {
            TCGEN05_FENCE_AFTER();
            FENCE_ASYNC();
#pragma unroll
            for (int st = 0; st < 16; st++) {
                const uint64_t dV = DESC_BASE
                    | ((uint64_t)((VS + (st >> 2) * 8192u) >> 4) & 0x3FFF);
                mma_tf32_ts(tmem_O, tmem_SP + st * 8, dV + (st & 3) * 2, IDESC_O,
                            (ci > 0 || st > 0) ? 1u : 0u);
            }
            TCGEN05_COMMIT(barPV);
        }

        if (ci + 1 < NCH) loadK(ci + 1);
        MBARRIER_WAIT_PARITY(barPV, phPV); phPV ^= 1;
        if (ci + 1 < NCH) loadVT(ci + 1);
        __syncthreads();
    }

    TCGEN05_FENCE_AFTER();

    ls_sh[tid] = lsum;
    __syncthreads();

    if (wid < 4) {
        const int r = wid * 32 + lid;
        const float inv = 1.0f / (ls_sh[tid] + ls_sh[tid + 128]);
        float* op = out + ((size_t)b * LAT + l0 + r) * DIM + h * HDIM;
#pragma unroll
        for (int cb = 0; cb < 2; cb++) {
            uint32_t rr[32];
            TCGEN05_LD_X32(rr, tmem_O + cb * 32);
            TCGEN05_WAIT_LD();
#pragma unroll
            for (int j = 0; j < 32; j += 4) {
                float4 o;
                o.x = __uint_as_float(rr[j + 0]) * inv;
                o.y = __uint_as_float(rr[j + 1]) * inv;
                o.z = __uint_as_float(rr[j + 2]) * inv;
                o.w = __uint_as_float(rr[j + 3]) * inv;
                *(float4*)(op + cb * 32 + j) = o;
            }
        }
    }
    TCGEN05_FENCE_BEFORE();
    __syncthreads();
    if (wid == 0) TCGEN05_DEALLOC(tmem, 256);

#else
    // SIMT fallback (thread-per-row; never runs on GB300)
    const int tid = threadIdx.x;
    const int bh  = blockIdx.x >> 2;
    const int lt  = blockIdx.x & 3;
    const int b   = bh >> 4, h = bh & 15;
    const int l0  = lt * 128;
    if (tid < 128) {
        const float* qrow = q + ((size_t)b * LAT + l0 + tid) * DIM + h * HDIM;
        const float* kb = kv + (size_t)b * SEQ * (2 * DIM) + h * HDIM;
        const float* vb = vt + ((size_t)bh * HDIM) * SEQ;
        float qr[64];
#pragma unroll
        for (int d = 0; d < 64; d++) qr[d] = qrow[d] * SCALE;
        float O[64];
#pragma unroll
        for (int d = 0; d < 64; d++) O[d] = 0.0f;
        float l = 0.0f;
        for (int s = 0; s < SEQ; s++) {
            const float* kr = kb + (size_t)s * (2 * DIM);
            float sv = 0.0f;
#pragma unroll 16
            for (int d = 0; d < 64; d++) sv += qr[d] * kr[d];
            float p = __expf(sv);
            l += p;
#pragma unroll 16
            for (int d = 0; d < 64; d++) O[d] += p * vb[(size_t)d * SEQ + s];
        }
        float* op = out + ((size_t)b * LAT + l0 + tid) * DIM + h * HDIM;
        float inv = 1.0f / l;
#pragma unroll
        for (int d = 0; d < 64; d++) op[d] = O[d] * inv;
    }
#endif
}

// =================================================================
// launch
// =================================================================
extern "C" void kernel_launch(void* const* d_in, const int* in_sizes, int n_in,
                              void* d_out, int out_size)
{
    const float* x       = (const float*)d_in[0];
    const float* latents = (const float*)d_in[1];
    if (in_sizes[0] != BATCH * SEQ * DIM) {
        x       = (const float*)d_in[1];
        latents = (const float*)d_in[0];
    }
    const float* w_q   = (const float*)d_in[2];
    const float* w_kv  = (const float*)d_in[3];
    const float* w_out = (const float*)d_in[4];
    const float* b_out = (const float*)d_in[5];
    float* out = (float*)d_out;

    float *q, *kvbuf, *att, *vt;
    cudaGetSymbolAddress((void**)&q,     g_q);
    cudaGetSymbolAddress((void**)&kvbuf, g_kv);
    cudaGetSymbolAddress((void**)&att,   g_att);
    cudaGetSymbolAddress((void**)&vt,    g_vt);

    const int M_q  = BATCH * LAT;    // 2048
    const int M_kv = BATCH * SEQ;    // 32768

    cudaFuncSetAttribute(gemm_tc128, cudaFuncAttributeMaxDynamicSharedMemorySize, GEMM128_SMEM);
    cudaFuncSetAttribute(gemm_tc_kv, cudaFuncAttributeMaxDynamicSharedMemorySize, GEMMKV_SMEM);
    cudaFuncSetAttribute(attn_tc,    cudaFuncAttributeMaxDynamicSharedMemorySize, ATTN_SMEM);

    // 1) q = latents @ w_q^T        (2048 x 1024), 128 CTAs
    gemm_tc128<<<dim3(DIM / 128, M_q / 128), 256, GEMM128_SMEM>>>(
        latents, w_q, q, nullptr, M_q, DIM, DIM);
    // 2) kv = x @ w_kv^T            (32768 x 2048), 1024 CTAs, 2-stage,
    //    register-staged loads; V half goes straight to vt (tf32, transposed)
    gemm_tc_kv<<<dim3(2 * DIM / 256, M_kv / 256), 256, GEMMKV_SMEM>>>(
        x, w_kv, kvbuf, vt, M_kv, 2 * DIM, DIM);
    // 3) attention
    attn_tc<<<BATCH * NHEADS * (LAT / 128), 256, ATTN_SMEM>>>(q, kvbuf, vt, att);
    // 4) out = att @ w_out^T + b_out, 128 CTAs
    gemm_tc128<<<dim3(DIM / 128, M_q / 128), 256, GEMM128_SMEM>>>(
        att, w_out, out, b_out, M_q, DIM, DIM);
}

// round 16
// speedup vs baseline: 1.2664x; 1.0447x over previous
#include <cuda_runtime.h>
#include <cstdint>
#include <math.h>

#define DIM       1024
#define NHEADS    16
#define HDIM      64
#define BATCH     4
#define SEQ       8192
#define LAT       512
#define SCALE     0.125f   // 64^-0.5

#if defined(__CUDA_ARCH_FEAT_SM103_ALL) || defined(__CUDA_ARCH_FEAT_SM100_ALL) || \
    (defined(__CUDA_ARCH_SPECIFIC__) && (__CUDA_ARCH_SPECIFIC__ >= 1000))
#define HAS_TCGEN05 1
#else
#define HAS_TCGEN05 0
#endif

// -------- scratch (device globals; no allocation allowed) --------
__device__ float g_q  [(size_t)BATCH * LAT * DIM];                    // 8 MB
__device__ float g_kv [(size_t)BATCH * SEQ * 2 * DIM];                // 268 MB (V half unused)
__device__ float g_att[(size_t)BATCH * LAT * DIM];                    // 8 MB
__device__ float g_vt [(size_t)BATCH * NHEADS * HDIM * SEQ];          // 134 MB (V^T, tf32)

// ================= helpers =================
__device__ __forceinline__ uint32_t smem_u32(const void* p) {
    uint32_t a;
    asm("{ .reg .u64 t; cvta.to.shared.u64 t, %1; cvt.u32.u64 %0, t; }"
        : "=r"(a) : "l"(p));
    return a;
}
__device__ __forceinline__ uint32_t f2tf32(float f) {
    uint32_t r;
    asm("cvt.rna.tf32.f32 %0, %1;" : "=r"(r) : "f"(f));
    return r;
}

#if HAS_TCGEN05
__device__ __forceinline__ uint32_t elect_one() {
    uint32_t p;
    asm volatile("{ .reg .pred p; elect.sync _|p, 0xFFFFFFFF; selp.b32 %0,1,0,p; }"
                 : "=r"(p));
    return p;
}

#define MBARRIER_INIT(addr, cnt) \
    asm volatile("mbarrier.init.shared.b64 [%0], %1;" :: "r"(addr), "r"(cnt) : "memory")

#define MBARRIER_WAIT_PARITY(mbar, par) do {                                   \
    uint32_t _m = (mbar); uint32_t _p = (par); uint32_t _done;                 \
    asm volatile("{\n\t.reg .pred p;\n\t"                                      \
        "mbarrier.try_wait.parity.acquire.cta.shared::cta.b64 p, [%1], %2;\n\t"\
        "selp.b32 %0, 1, 0, p;\n\t}"                                           \
        : "=r"(_done) : "r"(_m), "r"(_p) : "memory");                          \
    if (!_done) {                                                              \
        asm volatile("{\n\t.reg .pred P1;\n\t"                                 \
            "WL_%=:\n\t"                                                       \
            "mbarrier.try_wait.parity.acquire.cta.shared::cta.b64 P1, [%0], %1, 0x989680;\n\t" \
            "@P1 bra.uni WD_%=;\n\t"                                           \
            "bra.uni WL_%=;\n\t"                                               \
            "WD_%=:\n\t}"                                                      \
            :: "r"(_m), "r"(_p) : "memory");                                   \
    }                                                                          \
} while (0)

#define TCGEN05_ALLOC(slot, n) \
    asm volatile("tcgen05.alloc.cta_group::1.sync.aligned.shared::cta.b32 [%0], %1;" \
                 :: "r"(slot), "r"(n) : "memory")
#define TCGEN05_DEALLOC(tm, n) \
    asm volatile("tcgen05.dealloc.cta_group::1.sync.aligned.b32 %0, %1;" :: "r"(tm), "r"(n))
#define TCGEN05_RELINQ() \
    asm volatile("tcgen05.relinquish_alloc_permit.cta_group::1.sync.aligned;")
#define TCGEN05_COMMIT(mbar) \
    asm volatile("tcgen05.commit.cta_group::1.mbarrier::arrive::one.shared::cluster.b64 [%0];" \
                 :: "r"(mbar) : "memory")
#define TCGEN05_WAIT_LD() asm volatile("tcgen05.wait::ld.sync.aligned;" ::: "memory")
#define TCGEN05_WAIT_ST() asm volatile("tcgen05.wait::st.sync.aligned;" ::: "memory")
#define TCGEN05_FENCE_AFTER() asm volatile("tcgen05.fence::after_thread_sync;" ::: "memory")
#define TCGEN05_FENCE_BEFORE() asm volatile("tcgen05.fence::before_thread_sync;" ::: "memory")
#define FENCE_ASYNC() asm volatile("fence.proxy.async.shared::cta;" ::: "memory")

#define TCGEN05_LD_X32(r, addr)                                                \
    asm volatile("tcgen05.ld.sync.aligned.32x32b.x32.b32 "                     \
        "{%0,%1,%2,%3,%4,%5,%6,%7,%8,%9,%10,%11,%12,%13,%14,%15,"              \
        "%16,%17,%18,%19,%20,%21,%22,%23,%24,%25,%26,%27,%28,%29,%30,%31}, [%32];" \
        : "=r"((r)[0]),"=r"((r)[1]),"=r"((r)[2]),"=r"((r)[3]),                 \
          "=r"((r)[4]),"=r"((r)[5]),"=r"((r)[6]),"=r"((r)[7]),                 \
          "=r"((r)[8]),"=r"((r)[9]),"=r"((r)[10]),"=r"((r)[11]),               \
          "=r"((r)[12]),"=r"((r)[13]),"=r"((r)[14]),"=r"((r)[15]),             \
          "=r"((r)[16]),"=r"((r)[17]),"=r"((r)[18]),"=r"((r)[19]),             \
          "=r"((r)[20]),"=r"((r)[21]),"=r"((r)[22]),"=r"((r)[23]),             \
          "=r"((r)[24]),"=r"((r)[25]),"=r"((r)[26]),"=r"((r)[27]),             \
          "=r"((r)[28]),"=r"((r)[29]),"=r"((r)[30]),"=r"((r)[31])              \
        : "r"(addr))

#define TCGEN05_ST_X32(addr, r)                                                \
    asm volatile("tcgen05.st.sync.aligned.32x32b.x32.b32 [%0], "               \
        "{%1,%2,%3,%4,%5,%6,%7,%8,%9,%10,%11,%12,%13,%14,%15,%16,"             \
        "%17,%18,%19,%20,%21,%22,%23,%24,%25,%26,%27,%28,%29,%30,%31,%32};"    \
        :: "r"(addr),                                                          \
           "r"((r)[0]),"r"((r)[1]),"r"((r)[2]),"r"((r)[3]),                    \
           "r"((r)[4]),"r"((r)[5]),"r"((r)[6]),"r"((r)[7]),                    \
           "r"((r)[8]),"r"((r)[9]),"r"((r)[10]),"r"((r)[11]),                  \
           "r"((r)[12]),"r"((r)[13]),"r"((r)[14]),"r"((r)[15]),                \
           "r"((r)[16]),"r"((r)[17]),"r"((r)[18]),"r"((r)[19]),                \
           "r"((r)[20]),"r"((r)[21]),"r"((r)[22]),"r"((r)[23]),                \
           "r"((r)[24]),"r"((r)[25]),"r"((r)[26]),"r"((r)[27]),                \
           "r"((r)[28]),"r"((r)[29]),"r"((r)[30]),"r"((r)[31])                 \
        : "memory")

__device__ __forceinline__ void mma_tf32_ss(uint32_t d_tmem, uint64_t a_desc,
                                            uint64_t b_desc, uint32_t idesc,
                                            uint32_t enable) {
    asm volatile(
        "{\n\t.reg .pred p;\n\t"
        "setp.ne.u32 p, %4, 0;\n\t"
        "tcgen05.mma.cta_group::1.kind::tf32 [%0], %1, %2, %3, {%5,%5,%5,%5}, p;\n\t}"
        :: "r"(d_tmem), "l"(a_desc), "l"(b_desc), "r"(idesc), "r"(enable), "r"(0u)
        : "memory");
}
__device__ __forceinline__ void mma_tf32_ts(uint32_t d_tmem, uint32_t a_tmem,
                                            uint64_t b_desc, uint32_t idesc,
                                            uint32_t enable) {
    asm volatile(
        "{\n\t.reg .pred p;\n\t"
        "setp.ne.u32 p, %4, 0;\n\t"
        "tcgen05.mma.cta_group::1.kind::tf32 [%0], [%1], %2, %3, {%5,%5,%5,%5}, p;\n\t}"
        :: "r"(d_tmem), "r"(a_tmem), "l"(b_desc), "r"(idesc), "r"(enable), "r"(0u)
        : "memory");
}
#endif  // HAS_TCGEN05

// SW128 K-major descriptor base: layout=SW128(2), version=1, SBO=64, LBO=1
static constexpr uint64_t DESC_BASE =
    (2ull << 61) | (1ull << 46) | (64ull << 32) | (1ull << 16);

__device__ __forceinline__ uint32_t sw128(uint32_t off) {
    return off ^ ((off >> 3) & 0x70);
}

#define GK 32

// =================================================================
// GEMM (128x128 tile, register-staged loads) — small projections.
// LDG for chunk c+1 issues before MMA(c); only cvt+STS on the path.
// =================================================================
#define G128_STAGE 32768                      // A 16K + B 16K
#define GEMM128_SMEM (2 * G128_STAGE + 1024)

__global__ __launch_bounds__(256, 2)
void gemm_tc128(const float* __restrict__ A, const float* __restrict__ W,
                float* __restrict__ C, const float* __restrict__ bias,
                int M, int N, int K)
{
#if HAS_TCGEN05
    extern __shared__ char smraw[];
    __shared__ uint64_t mbar[2];
    __shared__ uint32_t tmem_slot;

    const uint32_t smbase = (smem_u32(smraw) + 1023u) & ~1023u;
    const uint32_t bar0 = smem_u32(&mbar[0]);
    const uint32_t bar1 = smem_u32(&mbar[1]);
    const uint32_t slot = smem_u32(&tmem_slot);

    const int tid = threadIdx.x;
    const int wid = tid >> 5;
    const int lid = tid & 31;
    const int m0 = blockIdx.y * 128;
    const int n0 = blockIdx.x * 128;

    if (wid == 0) TCGEN05_ALLOC(slot, 128);
    if (tid == 0) { MBARRIER_INIT(bar0, 1); MBARRIER_INIT(bar1, 1); }
    __syncthreads();
    uint32_t tmem;
    asm volatile("ld.shared.b32 %0, [%1];" : "=r"(tmem) : "r"(slot));
    if (wid == 0) TCGEN05_RELINQ();

    const uint32_t IDESC = (1u << 4) | (2u << 7) | (2u << 10)
                         | ((128u / 8) << 17) | ((128u / 16) << 24);

    const int NC = K / GK;
    int ph0 = 0, ph1 = 0;

    // per-thread indices: i = tid + it*256, row = i>>3 (= row_ + it*32), fo = i&7
    const int row_ = tid >> 3;
    const int fo_  = tid & 7;

    float4 ra[4], rb[4];
    // preload chunk 0
    {
        const float* Ap = A + (size_t)m0 * K;
        const float* Wp = W + (size_t)n0 * K;
#pragma unroll
        for (int it = 0; it < 4; it++) {
            int row = row_ + it * 32;
            ra[it] = *(const float4*)(Ap + (size_t)row * K + fo_ * 4);
            rb[it] = *(const float4*)(Wp + (size_t)row * K + fo_ * 4);
        }
    }

    for (int c = 0; c < NC; c++) {
        const int buf = c & 1;
        const uint32_t barb = buf ? bar1 : bar0;
        if (c >= 2) {
            MBARRIER_WAIT_PARITY(barb, (buf ? ph1 : ph0));
            if (buf) ph1 ^= 1; else ph0 ^= 1;
        }
        const uint32_t sb = smbase + buf * G128_STAGE;

        // cvt+STS staged registers
#pragma unroll
        for (int it = 0; it < 4; it++) {
            int row = row_ + it * 32;
            float4 v = ra[it];
            uint32_t r0 = f2tf32(v.x), r1 = f2tf32(v.y),
                     r2 = f2tf32(v.z), r3 = f2tf32(v.w);
            uint32_t dst = sb + sw128((uint32_t)(row * 128 + fo_ * 16));
            asm volatile("st.shared.v4.b32 [%0], {%1,%2,%3,%4};"
                         :: "r"(dst), "r"(r0), "r"(r1), "r"(r2), "r"(r3) : "memory");
        }
#pragma unroll
        for (int it = 0; it < 4; it++) {
            int row = row_ + it * 32;
            float4 v = rb[it];
            uint32_t r0 = f2tf32(v.x), r1 = f2tf32(v.y),
                     r2 = f2tf32(v.z), r3 = f2tf32(v.w);
            uint32_t dst = sb + 16384u + sw128((uint32_t)(row * 128 + fo_ * 16));
            asm volatile("st.shared.v4.b32 [%0], {%1,%2,%3,%4};"
                         :: "r"(dst), "r"(r0), "r"(r1), "r"(r2), "r"(r3) : "memory");
        }

        // prefetch chunk c+1 — latency hides under MMA(c)
        if (c + 1 < NC) {
            const float* Ap = A + (size_t)m0 * K + (c + 1) * GK;
            const float* Wp = W + (size_t)n0 * K + (c + 1) * GK;
#pragma unroll
            for (int it = 0; it < 4; it++) {
                int row = row_ + it * 32;
                ra[it] = *(const float4*)(Ap + (size_t)row * K + fo_ * 4);
                rb[it] = *(const float4*)(Wp + (size_t)row * K + fo_ * 4);
            }
        }

        __syncthreads();

        if (wid == 0 && elect_one()) {
            FENCE_ASYNC();
            const uint64_t dA = DESC_BASE | ((uint64_t)(sb >> 4) & 0x3FFF);
            const uint64_t dB = DESC_BASE | ((uint64_t)((sb + 16384u) >> 4) & 0x3FFF);
#pragma unroll
            for (int k = 0; k < 4; k++) {
                uint32_t en = (c > 0 || k > 0) ? 1u : 0u;
                mma_tf32_ss(tmem, dA + k * 2, dB + k * 2, IDESC, en);
            }
            TCGEN05_COMMIT(barb);
        }
    }

    MBARRIER_WAIT_PARITY(bar0, ph0);
    MBARRIER_WAIT_PARITY(bar1, ph1);
    TCGEN05_FENCE_AFTER();

    {
        const int colh = wid >> 2;
        const int sub  = wid & 3;
        const int r = sub * 32 + lid;
        float* Crow = C + (size_t)(m0 + r) * N + n0 + colh * 64;
        const float* bp = bias ? (bias + n0 + colh * 64) : nullptr;
#pragma unroll
        for (int half = 0; half < 2; half++) {
            uint32_t rr[32];
            TCGEN05_LD_X32(rr, tmem + colh * 64 + half * 32);
            TCGEN05_WAIT_LD();
#pragma unroll
            for (int j = 0; j < 32; j += 4) {
                float4 o;
                o.x = __uint_as_float(rr[j + 0]);
                o.y = __uint_as_float(rr[j + 1]);
                o.z = __uint_as_float(rr[j + 2]);
                o.w = __uint_as_float(rr[j + 3]);
                if (bp) {
                    o.x += bp[half * 32 + j + 0]; o.y += bp[half * 32 + j + 1];
                    o.z += bp[half * 32 + j + 2]; o.w += bp[half * 32 + j + 3];
                }
                *(float4*)(Crow + half * 32 + j) = o;
            }
        }
    }
    TCGEN05_FENCE_BEFORE();
    __syncthreads();
    if (wid == 0) TCGEN05_DEALLOC(tmem, 128);

#else
    __shared__ float As[8][128];
    __shared__ float Ws[8][128];
    const int tid  = threadIdx.x;
    const int ty   = tid >> 4;
    const int tx   = tid & 15;
    const int row0 = blockIdx.y * 128;
    const int col0 = blockIdx.x * 128;
    const int lrow = tid >> 1;
    const int lk   = (tid & 1) * 4;

    const float* Ap = A + (size_t)(row0 + lrow) * K + lk;
    const float* Wp = W + (size_t)(col0 + lrow) * K + lk;
    float acc[8][8];
#pragma unroll
    for (int i = 0; i < 8; i++)
#pragma unroll
        for (int j = 0; j < 8; j++) acc[i][j] = 0.0f;

    for (int k0 = 0; k0 < K; k0 += 8) {
        float4 av = *(const float4*)(Ap + k0);
        float4 wv = *(const float4*)(Wp + k0);
        As[lk + 0][lrow] = av.x; As[lk + 1][lrow] = av.y;
        As[lk + 2][lrow] = av.z; As[lk + 3][lrow] = av.w;
        Ws[lk + 0][lrow] = wv.x; Ws[lk + 1][lrow] = wv.y;
        Ws[lk + 2][lrow] = wv.z; Ws[lk + 3][lrow] = wv.w;
        __syncthreads();
#pragma unroll
        for (int k = 0; k < 8; k++) {
            float a[8], b[8];
            float4 t0 = *(const float4*)(&As[k][ty * 8 + 0]);
            float4 t1 = *(const float4*)(&As[k][ty * 8 + 4]);
            a[0]=t0.x;a[1]=t0.y;a[2]=t0.z;a[3]=t0.w;a[4]=t1.x;a[5]=t1.y;a[6]=t1.z;a[7]=t1.w;
            float4 u0 = *(const float4*)(&Ws[k][tx * 8 + 0]);
            float4 u1 = *(const float4*)(&Ws[k][tx * 8 + 4]);
            b[0]=u0.x;b[1]=u0.y;b[2]=u0.z;b[3]=u0.w;b[4]=u1.x;b[5]=u1.y;b[6]=u1.z;b[7]=u1.w;
#pragma unroll
            for (int i = 0; i < 8; i++)
#pragma unroll
                for (int j = 0; j < 8; j++) acc[i][j] += a[i] * b[j];
        }
        __syncthreads();
    }
#pragma unroll
    for (int i = 0; i < 8; i++) {
        const size_t r = (size_t)(row0 + ty * 8 + i);
#pragma unroll
        for (int j = 0; j < 8; j++) {
            const int cc = col0 + tx * 8 + j;
            float v = acc[i][j];
            if (bias) v += bias[cc];
            C[r * N + cc] = v;
        }
    }
#endif
}

// =================================================================
// GEMM (256x256 tile, 2-stage, register-staged loads) — kv projection
// with fused V^T epilogue (r15-proven, ~275us).
// =================================================================
#define A256_BYTES 32768
#define B256_BYTES 32768
#define STAGE256 (A256_BYTES + B256_BYTES)       // 64KB
#define GEMMKV_SMEM (2 * STAGE256 + 1024)        // 129KB

__global__ __launch_bounds__(256, 1)
void gemm_tc_kv(const float* __restrict__ A, const float* __restrict__ W,
                float* __restrict__ C, float* __restrict__ vtb,
                int M, int N, int K)
{
#if HAS_TCGEN05
    extern __shared__ char smraw[];
    __shared__ uint64_t mbar[2];
    __shared__ uint32_t tmem_slot;

    const uint32_t smbase = (smem_u32(smraw) + 1023u) & ~1023u;
    const uint32_t bar0 = smem_u32(&mbar[0]);
    const uint32_t bar1 = smem_u32(&mbar[1]);
    const uint32_t slot = smem_u32(&tmem_slot);

    const int tid = threadIdx.x;
    const int wid = tid >> 5;
    const int lid = tid & 31;
    const int m0 = blockIdx.y * 256;
    const int n0 = blockIdx.x * 256;

    if (wid == 0) TCGEN05_ALLOC(slot, 512);
    if (tid == 0) { MBARRIER_INIT(bar0, 1); MBARRIER_INIT(bar1, 1); }
    __syncthreads();
    uint32_t tmem;
    asm volatile("ld.shared.b32 %0, [%1];" : "=r"(tmem) : "r"(slot));
    if (wid == 0) TCGEN05_RELINQ();

    const uint32_t IDESC = (1u << 4) | (2u << 7) | (2u << 10)
                         | ((256u / 8) << 17) | ((128u / 16) << 24);

    const int NC = K / GK;
    int ph0 = 0, ph1 = 0;

    const int row_ = tid >> 3;
    const int fo_  = tid & 7;

    float4 ra[8], rb[8];
    {
        const float* Ap = A + (size_t)m0 * K;
        const float* Wp = W + (size_t)n0 * K;
#pragma unroll
        for (int it = 0; it < 8; it++) {
            int row = row_ + it * 32;
            ra[it] = *(const float4*)(Ap + (size_t)row * K + fo_ * 4);
            rb[it] = *(const float4*)(Wp + (size_t)row * K + fo_ * 4);
        }
    }

    for (int c = 0; c < NC; c++) {
        const int buf = c & 1;
        const uint32_t barb = buf ? bar1 : bar0;
        if (c >= 2) {
            MBARRIER_WAIT_PARITY(barb, (buf ? ph1 : ph0));
            if (buf) ph1 ^= 1; else ph0 ^= 1;
        }
        const uint32_t sb = smbase + buf * STAGE256;

#pragma unroll
        for (int it = 0; it < 8; it++) {
            int row = row_ + it * 32;
            float4 v = ra[it];
            uint32_t r0 = f2tf32(v.x), r1 = f2tf32(v.y),
                     r2 = f2tf32(v.z), r3 = f2tf32(v.w);
            uint32_t off = sw128((uint32_t)((row & 127) * 128 + fo_ * 16));
            uint32_t dst = sb + ((row < 128) ? 0u : 16384u) + off;
            asm volatile("st.shared.v4.b32 [%0], {%1,%2,%3,%4};"
                         :: "r"(dst), "r"(r0), "r"(r1), "r"(r2), "r"(r3) : "memory");
        }
#pragma unroll
        for (int it = 0; it < 8; it++) {
            int row = row_ + it * 32;
            float4 v = rb[it];
            uint32_t r0 = f2tf32(v.x), r1 = f2tf32(v.y),
                     r2 = f2tf32(v.z), r3 = f2tf32(v.w);
            uint32_t dst = sb + A256_BYTES + sw128((uint32_t)(row * 128 + fo_ * 16));
            asm volatile("st.shared.v4.b32 [%0], {%1,%2,%3,%4};"
                         :: "r"(dst), "r"(r0), "r"(r1), "r"(r2), "r"(r3) : "memory");
        }

        if (c + 1 < NC) {
            const float* Ap = A + (size_t)m0 * K + (c + 1) * GK;
            const float* Wp = W + (size_t)n0 * K + (c + 1) * GK;
#pragma unroll
            for (int it = 0; it < 8; it++) {
                int row = row_ + it * 32;
                ra[it] = *(const float4*)(Ap + (size_t)row * K + fo_ * 4);
                rb[it] = *(const float4*)(Wp + (size_t)row * K + fo_ * 4);
            }
        }

        __syncthreads();

        if (wid == 0 && elect_one()) {
            FENCE_ASYNC();
            const uint64_t dA0 = DESC_BASE | ((uint64_t)(sb >> 4) & 0x3FFF);
            const uint64_t dA1 = DESC_BASE | ((uint64_t)((sb + 16384u) >> 4) & 0x3FFF);
            const uint64_t dB  = DESC_BASE | ((uint64_t)((sb + A256_BYTES) >> 4) & 0x3FFF);
#pragma unroll
            for (int k = 0; k < 4; k++) {
                uint32_t en = (c > 0 || k > 0) ? 1u : 0u;
                mma_tf32_ss(tmem,       dA0 + k * 2, dB + k * 2, IDESC, en);
                mma_tf32_ss(tmem + 256, dA1 + k * 2, dB + k * 2, IDESC, en);
            }
            TCGEN05_COMMIT(barb);
        }
    }

    MBARRIER_WAIT_PARITY(bar0, ph0);
    MBARRIER_WAIT_PARITY(bar1, ph1);
    TCGEN05_FENCE_AFTER();

    {
        const int tile = wid >> 2;
        const uint32_t dbase = tmem + tile * 256;
        const int rowl = (wid & 3) * 32 + lid;
        const size_t grow = (size_t)m0 + tile * 128 + rowl;    // global row = b*SEQ + s

        if (vtb && n0 >= DIM) {
            const int s  = (int)(grow & (SEQ - 1));
            const int bq = (int)(grow >> 13);
            const size_t vb0 = (size_t)bq * NHEADS * HDIM;
#pragma unroll
            for (int cb = 0; cb < 8; cb++) {
                uint32_t rr[32];
                TCGEN05_LD_X32(rr, dbase + cb * 32);
                TCGEN05_WAIT_LD();
#pragma unroll
                for (int j = 0; j < 32; j++) {
                    const int dcol = (n0 - DIM) + cb * 32 + j;
                    vtb[(vb0 + (size_t)dcol) * SEQ + s] =
                        __uint_as_float(f2tf32(__uint_as_float(rr[j])));
                }
            }
        } else {
            float* Crow = C + grow * N + n0;
#pragma unroll
            for (int cb = 0; cb < 8; cb++) {
                uint32_t rr[32];
                TCGEN05_LD_X32(rr, dbase + cb * 32);
                TCGEN05_WAIT_LD();
#pragma unroll
                for (int j = 0; j < 32; j += 4) {
                    float4 o;
                    o.x = __uint_as_float(rr[j + 0]);
                    o.y = __uint_as_float(rr[j + 1]);
                    o.z = __uint_as_float(rr[j + 2]);
                    o.w = __uint_as_float(rr[j + 3]);
                    *(float4*)(Crow + cb * 32 + j) = o;
                }
            }
        }
    }
    TCGEN05_FENCE_BEFORE();
    __syncthreads();
    if (wid == 0) TCGEN05_DEALLOC(tmem, 512);

#else
    // SIMT fallback: 2x2 subtiles of 128x128 with fused vt on V columns
    __shared__ float As[8][128];
    __shared__ float Ws[8][128];
    const int tid  = threadIdx.x;
    const int ty   = tid >> 4;
    const int tx   = tid & 15;
    const int lrow = tid >> 1;
    const int lk   = (tid & 1) * 4;

    for (int hm = 0; hm < 2; hm++)
    for (int hn = 0; hn < 2; hn++) {
        const int row0 = blockIdx.y * 256 + hm * 128;
        const int col0 = blockIdx.x * 256 + hn * 128;
        const float* Ap = A + (size_t)(row0 + lrow) * K + lk;
        const float* Wp = W + (size_t)(col0 + lrow) * K + lk;
        float acc[8][8];
#pragma unroll
        for (int i = 0; i < 8; i++)
#pragma unroll
            for (int j = 0; j < 8; j++) acc[i][j] = 0.0f;

        for (int k0 = 0; k0 < K; k0 += 8) {
            float4 av = *(const float4*)(Ap + k0);
            float4 wv = *(const float4*)(Wp + k0);
            As[lk + 0][lrow] = av.x; As[lk + 1][lrow] = av.y;
            As[lk + 2][lrow] = av.z; As[lk + 3][lrow] = av.w;
            Ws[lk + 0][lrow] = wv.x; Ws[lk + 1][lrow] = wv.y;
            Ws[lk + 2][lrow] = wv.z; Ws[lk + 3][lrow] = wv.w;
            __syncthreads();
#pragma unroll
            for (int k = 0; k < 8; k++) {
                float a[8], b[8];
                float4 t0 = *(const float4*)(&As[k][ty * 8 + 0]);
                float4 t1 = *(const float4*)(&As[k][ty * 8 + 4]);
                a[0]=t0.x;a[1]=t0.y;a[2]=t0.z;a[3]=t0.w;a[4]=t1.x;a[5]=t1.y;a[6]=t1.z;a[7]=t1.w;
                float4 u0 = *(const float4*)(&Ws[k][tx * 8 + 0]);
                float4 u1 = *(const float4*)(&Ws[k][tx * 8 + 4]);
                b[0]=u0.x;b[1]=u0.y;b[2]=u0.z;b[3]=u0.w;b[4]=u1.x;b[5]=u1.y;b[6]=u1.z;b[7]=u1.w;
#pragma unroll
                for (int i = 0; i < 8; i++)
#pragma unroll
                    for (int j = 0; j < 8; j++) acc[i][j] += a[i] * b[j];
            }
            __syncthreads();
        }
#pragma unroll
        for (int i = 0; i < 8; i++) {
            const size_t grow = (size_t)(row0 + ty * 8 + i);
#pragma unroll
            for (int j = 0; j < 8; j++) {
                const int cc = col0 + tx * 8 + j;
                if (vtb && cc >= DIM) {
                    const int s  = (int)(grow & (SEQ - 1));
                    const int bq = (int)(grow >> 13);
                    vtb[((size_t)bq * NHEADS * HDIM + (cc - DIM)) * SEQ + s] =
                        __uint_as_float(f2tf32(acc[i][j]));
                } else {
                    C[grow * N + cc] = acc[i][j];
                }
            }
        }
        __syncthreads();
    }
#endif
}

// =================================================================
// Tensor-core flash attention — round-9 version (proven 251us).
// =================================================================
#define SCHUNK 128
#define NCH (SEQ / SCHUNK)
#define ATTN_SMEM (3 * 32768 + 1024)
#define SCALE_L2E 0.18033688011112042f   // SCALE * log2(e)

__global__ __launch_bounds__(256, 2)
void attn_tc(const float* __restrict__ q, const float* __restrict__ kv,
             const float* __restrict__ vt, float* __restrict__ out)
{
#if HAS_TCGEN05
    extern __shared__ char smraw[];
    __shared__ uint64_t mbar[2];
    __shared__ uint32_t tmem_slot;
    __shared__ float ls_sh[256];

    const uint32_t smbase = (smem_u32(smraw) + 1023u) & ~1023u;
    const uint32_t QS = smbase;
    const uint32_t KS = smbase + 32768u;
    const uint32_t VS = smbase + 65536u;
    const uint32_t barQK = smem_u32(&mbar[0]);
    const uint32_t barPV = smem_u32(&mbar[1]);
    const uint32_t slot  = smem_u32(&tmem_slot);

    const int tid = threadIdx.x;
    const int wid = tid >> 5;
    const int lid = tid & 31;
    const int bh  = blockIdx.x >> 2;
    const int lt  = blockIdx.x & 3;
    const int b   = bh >> 4, h = bh & 15;
    const int l0  = lt * 128;

    if (wid == 0) TCGEN05_ALLOC(slot, 256);
    if (tid == 0) { MBARRIER_INIT(barQK, 1); MBARRIER_INIT(barPV, 1); }
    __syncthreads();
    uint32_t tmem;
    asm volatile("ld.shared.b32 %0, [%1];" : "=r"(tmem) : "r"(slot));
    if (wid == 0) TCGEN05_RELINQ();
    const uint32_t tmem_SP = tmem;
    const uint32_t tmem_O  = tmem + 128;

    const uint32_t IDESC_S = (1u << 4) | (2u << 7) | (2u << 10)
                           | ((128u / 8) << 17) | ((128u / 16) << 24);
    const uint32_t IDESC_O = (1u << 4) | (2u << 7) | (2u << 10)
                           | ((64u / 8) << 17) | ((128u / 16) << 24);

    const float* kbase = kv + (size_t)b * SEQ * (2 * DIM) + h * HDIM;
    const float* vbase = vt + ((size_t)bh * HDIM) * SEQ;

    const float* qbase = q + ((size_t)b * LAT + l0) * DIM + h * HDIM;
#pragma unroll
    for (int it = 0; it < 8; it++) {
        int i = tid + it * 256;
        int row = i >> 4, f = i & 15;
        int kc = f >> 3, fo = f & 7;
        float4 v = *(const float4*)(qbase + (size_t)row * DIM + f * 4);
        uint32_t r0 = f2tf32(v.x * SCALE_L2E), r1 = f2tf32(v.y * SCALE_L2E);
        uint32_t r2 = f2tf32(v.z * SCALE_L2E), r3 = f2tf32(v.w * SCALE_L2E);
        uint32_t dst = QS + kc * 16384u + sw128((uint32_t)(row * 128 + fo * 16));
        asm volatile("st.shared.v4.b32 [%0], {%1,%2,%3,%4};"
                     :: "r"(dst), "r"(r0), "r"(r1), "r"(r2), "r"(r3) : "memory");
    }

    auto loadK = [&](int ci) {
        const int s0 = ci * SCHUNK;
#pragma unroll
        for (int it = 0; it < 8; it++) {
            int i = tid + it * 256;
            int kr = i >> 4, f = i & 15;
            int kc = f >> 3, fo = f & 7;
            float4 v = *(const float4*)(kbase + (size_t)(s0 + kr) * (2 * DIM) + f * 4);
            uint32_t r0 = f2tf32(v.x), r1 = f2tf32(v.y),
                     r2 = f2tf32(v.z), r3 = f2tf32(v.w);
            uint32_t dst = KS + kc * 16384u + sw128((uint32_t)(kr * 128 + fo * 16));
            asm volatile("st.shared.v4.b32 [%0], {%1,%2,%3,%4};"
                         :: "r"(dst), "r"(r0), "r"(r1), "r"(r2), "r"(r3) : "memory");
        }
    };
    auto loadVT = [&](int ci) {
        const int s0 = ci * SCHUNK;
#pragma unroll
        for (int it = 0; it < 8; it++) {
            int i = tid + it * 256;
            int d = i >> 5, f = i & 31;
            int sc = f >> 3, fo = f & 7;
            float4 v = *(const float4*)(vbase + (size_t)d * SEQ + s0 + f * 4);
            uint32_t dst = VS + sc * 8192u + sw128((uint32_t)(d * 128 + fo * 16));
            asm volatile("st.shared.v4.b32 [%0], {%1,%2,%3,%4};"
                         :: "r"(dst), "r"(__float_as_uint(v.x)), "r"(__float_as_uint(v.y)),
                            "r"(__float_as_uint(v.z)), "r"(__float_as_uint(v.w)) : "memory");
        }
    };

    const uint64_t dQ0 = DESC_BASE | ((uint64_t)(QS >> 4) & 0x3FFF);
    const uint64_t dQ1 = DESC_BASE | ((uint64_t)((QS + 16384u) >> 4) & 0x3FFF);
    const uint64_t dK0 = DESC_BASE | ((uint64_t)(KS >> 4) & 0x3FFF);
    const uint64_t dK1 = DESC_BASE | ((uint64_t)((KS + 16384u) >> 4) & 0x3FFF);

    float lsum = 0.0f;
    int phQK = 0, phPV = 0;

    loadK(0);
    loadVT(0);
    __syncthreads();

    for (int ci = 0; ci < NCH; ci++) {
        if (wid == 0 && elect_one()) {
            FENCE_ASYNC();
#pragma unroll
            for (int blk = 0; blk < 2; blk++) {
                const uint64_t dq = blk ? dQ1 : dQ0;
                const uint64_t dk = blk ? dK1 : dK0;
#pragma unroll
                for (int ks = 0; ks < 4; ks++)
                    mma_tf32_ss(tmem_SP, dq + ks * 2, dk + ks * 2, IDESC_S,
                                (blk > 0 || ks > 0) ? 1u : 0u);
            }
            TCGEN05_COMMIT(barQK);
        }
        MBARRIER_WAIT_PARITY(barQK, phQK); phQK ^= 1;
        TCGEN05_FENCE_AFTER();

        {
            const uint32_t colofs = (uint32_t)(wid >> 2) * 64u;
            const uint32_t wlane  = (uint32_t)(wid & 3) << 21;
#pragma unroll
            for (int blk = 0; blk < 2; blk++) {
                uint32_t rr[32];
                TCGEN05_LD_X32(rr, tmem_SP + colofs + blk * 32);
                TCGEN05_WAIT_LD();
#pragma unroll
                for (int j = 0; j < 32; j++) {
                    float p;
                    asm("ex2.approx.f32 %0, %1;" : "=f"(p) : "f"(__uint_as_float(rr[j])));
                    lsum += p;
                    rr[j] = f2tf32(p);
                }
                TCGEN05_ST_X32(tmem_SP + wlane + colofs + blk * 32, rr);
            }
            TCGEN05_WAIT_ST();
        }
        TCGEN05_FENCE_BEFORE();
        __syncthreads();

        if (wid == 0 && elect_one()) {
            TCGEN05_FENCE_AFTER();
            FENCE_ASYNC();
#pragma unroll
            for (int st = 0; st < 16; st++) {
                const uint64_t dV = DESC_BASE
                    | ((uint64_t)((VS + (st >> 2) * 8192u) >> 4) & 0x3FFF);
                mma_tf32_ts(tmem_O, tmem_SP + st * 8, dV + (st & 3) * 2, IDESC_O,
                            (ci > 0 || st > 0) ? 1u : 0u);
            }
            TCGEN05_COMMIT(barPV);
        }

        if (ci + 1 < NCH) loadK(ci + 1);
        MBARRIER_WAIT_PARITY(barPV, phPV); phPV ^= 1;
        if (ci + 1 < NCH) loadVT(ci + 1);
        __syncthreads();
    }

    TCGEN05_FENCE_AFTER();

    ls_sh[tid] = lsum;
    __syncthreads();

    if (wid < 4) {
        const int r = wid * 32 + lid;
        const float inv = 1.0f / (ls_sh[tid] + ls_sh[tid + 128]);
        float* op = out + ((size_t)b * LAT + l0 + r) * DIM + h * HDIM;
#pragma unroll
        for (int cb = 0; cb < 2; cb++) {
            uint32_t rr[32];
            TCGEN05_LD_X32(rr, tmem_O + cb * 32);
            TCGEN05_WAIT_LD();
#pragma unroll
            for (int j = 0; j < 32; j += 4) {
                float4 o;
                o.x = __uint_as_float(rr[j + 0]) * inv;
                o.y = __uint_as_float(rr[j + 1]) * inv;
                o.z = __uint_as_float(rr[j + 2]) * inv;
                o.w = __uint_as_float(rr[j + 3]) * inv;
                *(float4*)(op + cb * 32 + j) = o;
            }
        }
    }
    TCGEN05_FENCE_BEFORE();
    __syncthreads();
    if (wid == 0) TCGEN05_DEALLOC(tmem, 256);

#else
    // SIMT fallback (thread-per-row; never runs on GB300)
    const int tid = threadIdx.x;
    const int bh  = blockIdx.x >> 2;
    const int lt  = blockIdx.x & 3;
    const int b   = bh >> 4, h = bh & 15;
    const int l0  = lt * 128;
    if (tid < 128) {
        const float* qrow = q + ((size_t)b * LAT + l0 + tid) * DIM + h * HDIM;
        const float* kb = kv + (size_t)b * SEQ * (2 * DIM) + h * HDIM;
        const float* vb = vt + ((size_t)bh * HDIM) * SEQ;
        float qr[64];
#pragma unroll
        for (int d = 0; d < 64; d++) qr[d] = qrow[d] * SCALE;
        float O[64];
#pragma unroll
        for (int d = 0; d < 64; d++) O[d] = 0.0f;
        float l = 0.0f;
        for (int s = 0; s < SEQ; s++) {
            const float* kr = kb + (size_t)s * (2 * DIM);
            float sv = 0.0f;
#pragma unroll 16
            for (int d = 0; d < 64; d++) sv += qr[d] * kr[d];
            float p = __expf(sv);
            l += p;
#pragma unroll 16
            for (int d = 0; d < 64; d++) O[d] += p * vb[(size_t)d * SEQ + s];
        }
        float* op = out + ((size_t)b * LAT + l0 + tid) * DIM + h * HDIM;
        float inv = 1.0f / l;
#pragma unroll
        for (int d = 0; d < 64; d++) op[d] = O[d] * inv;
    }
#endif
}

// =================================================================
// launch
// =================================================================
extern "C" void kernel_launch(void* const* d_in, const int* in_sizes, int n_in,
                              void* d_out, int out_size)
{
    const float* x       = (const float*)d_in[0];
    const float* latents = (const float*)d_in[1];
    if (in_sizes[0] != BATCH * SEQ * DIM) {
        x       = (const float*)d_in[1];
        latents = (const float*)d_in[0];
    }
    const float* w_q   = (const float*)d_in[2];
    const float* w_kv  = (const float*)d_in[3];
    const float* w_out = (const float*)d_in[4];
    const float* b_out = (const float*)d_in[5];
    float* out = (float*)d_out;

    float *q, *kvbuf, *att, *vt;
    cudaGetSymbolAddress((void**)&q,     g_q);
    cudaGetSymbolAddress((void**)&kvbuf, g_kv);
    cudaGetSymbolAddress((void**)&att,   g_att);
    cudaGetSymbolAddress((void**)&vt,    g_vt);

    const int M_q  = BATCH * LAT;    // 2048
    const int M_kv = BATCH * SEQ;    // 32768

    cudaFuncSetAttribute(gemm_tc128, cudaFuncAttributeMaxDynamicSharedMemorySize, GEMM128_SMEM);
    cudaFuncSetAttribute(gemm_tc_kv, cudaFuncAttributeMaxDynamicSharedMemorySize, GEMMKV_SMEM);
    cudaFuncSetAttribute(attn_tc,    cudaFuncAttributeMaxDynamicSharedMemorySize, ATTN_SMEM);

    // 1) q = latents @ w_q^T        (2048 x 1024), 128 CTAs, reg-staged
    gemm_tc128<<<dim3(DIM / 128, M_q / 128), 256, GEMM128_SMEM>>>(
        latents, w_q, q, nullptr, M_q, DIM, DIM);
    // 2) kv = x @ w_kv^T            (32768 x 2048), 1024 CTAs, 2-stage,
    //    register-staged loads; V half goes straight to vt (tf32, transposed)
    gemm_tc_kv<<<dim3(2 * DIM / 256, M_kv / 256), 256, GEMMKV_SMEM>>>(
        x, w_kv, kvbuf, vt, M_kv, 2 * DIM, DIM);
    // 3) attention
    attn_tc<<<BATCH * NHEADS * (LAT / 128), 256, ATTN_SMEM>>>(q, kvbuf, vt, att);
    // 4) out = att @ w_out^T + b_out, 128 CTAs, reg-staged
    gemm_tc128<<<dim3(DIM / 128, M_q / 128), 256, GEMM128_SMEM>>>(
        att, w_out, out, b_out, M_q, DIM, DIM);
}

// round 17
// speedup vs baseline: 1.3023x; 1.0283x over previous
#include <cuda_runtime.h>
#include <cstdint>
#include <math.h>

#define DIM       1024
#define NHEADS    16
#define HDIM      64
#define BATCH     4
#define SEQ       8192
#define LAT       512
#define SCALE     0.125f   // 64^-0.5

#if defined(__CUDA_ARCH_FEAT_SM103_ALL) || defined(__CUDA_ARCH_FEAT_SM100_ALL) || \
    (defined(__CUDA_ARCH_SPECIFIC__) && (__CUDA_ARCH_SPECIFIC__ >= 1000))
#define HAS_TCGEN05 1
#else
#define HAS_TCGEN05 0
#endif

// -------- scratch (device globals; no allocation allowed) --------
__device__ float g_q  [(size_t)BATCH * LAT * DIM];                    // 8 MB
__device__ float g_kv [(size_t)BATCH * SEQ * 2 * DIM];                // 268 MB (V half unused)
__device__ float g_att[(size_t)BATCH * LAT * DIM];                    // 8 MB
__device__ float g_vt [(size_t)BATCH * NHEADS * HDIM * SEQ];          // 134 MB (V^T, tf32)

// ================= helpers =================
__device__ __forceinline__ uint32_t smem_u32(const void* p) {
    uint32_t a;
    asm("{ .reg .u64 t; cvta.to.shared.u64 t, %1; cvt.u32.u64 %0, t; }"
        : "=r"(a) : "l"(p));
    return a;
}
__device__ __forceinline__ uint32_t f2tf32(float f) {
    uint32_t r;
    asm("cvt.rna.tf32.f32 %0, %1;" : "=r"(r) : "f"(f));
    return r;
}

#if HAS_TCGEN05
__device__ __forceinline__ uint32_t elect_one() {
    uint32_t p;
    asm volatile("{ .reg .pred p; elect.sync _|p, 0xFFFFFFFF; selp.b32 %0,1,0,p; }"
                 : "=r"(p));
    return p;
}

#define MBARRIER_INIT(addr, cnt) \
    asm volatile("mbarrier.init.shared.b64 [%0], %1;" :: "r"(addr), "r"(cnt) : "memory")

#define MBARRIER_WAIT_PARITY(mbar, par) do {                                   \
    uint32_t _m = (mbar); uint32_t _p = (par); uint32_t _done;                 \
    asm volatile("{\n\t.reg .pred p;\n\t"                                      \
        "mbarrier.try_wait.parity.acquire.cta.shared::cta.b64 p, [%1], %2;\n\t"\
        "selp.b32 %0, 1, 0, p;\n\t}"                                           \
        : "=r"(_done) : "r"(_m), "r"(_p) : "memory");                          \
    if (!_done) {                                                              \
        asm volatile("{\n\t.reg .pred P1;\n\t"                                 \
            "WL_%=:\n\t"                                                       \
            "mbarrier.try_wait.parity.acquire.cta.shared::cta.b64 P1, [%0], %1, 0x989680;\n\t" \
            "@P1 bra.uni WD_%=;\n\t"                                           \
            "bra.uni WL_%=;\n\t"                                               \
            "WD_%=:\n\t}"                                                      \
            :: "r"(_m), "r"(_p) : "memory");                                   \
    }                                                                          \
} while (0)

#define TCGEN05_ALLOC(slot, n) \
    asm volatile("tcgen05.alloc.cta_group::1.sync.aligned.shared::cta.b32 [%0], %1;" \
                 :: "r"(slot), "r"(n) : "memory")
#define TCGEN05_DEALLOC(tm, n) \
    asm volatile("tcgen05.dealloc.cta_group::1.sync.aligned.b32 %0, %1;" :: "r"(tm), "r"(n))
#define TCGEN05_RELINQ() \
    asm volatile("tcgen05.relinquish_alloc_permit.cta_group::1.sync.aligned;")
#define TCGEN05_COMMIT(mbar) \
    asm volatile("tcgen05.commit.cta_group::1.mbarrier::arrive::one.shared::cluster.b64 [%0];" \
                 :: "r"(mbar) : "memory")
#define TCGEN05_WAIT_LD() asm volatile("tcgen05.wait::ld.sync.aligned;" ::: "memory")
#define TCGEN05_WAIT_ST() asm volatile("tcgen05.wait::st.sync.aligned;" ::: "memory")
#define TCGEN05_FENCE_AFTER() asm volatile("tcgen05.fence::after_thread_sync;" ::: "memory")
#define TCGEN05_FENCE_BEFORE() asm volatile("tcgen05.fence::before_thread_sync;" ::: "memory")
#define FENCE_ASYNC() asm volatile("fence.proxy.async.shared::cta;" ::: "memory")

#define TCGEN05_LD_X32(r, addr)                                                \
    asm volatile("tcgen05.ld.sync.aligned.32x32b.x32.b32 "                     \
        "{%0,%1,%2,%3,%4,%5,%6,%7,%8,%9,%10,%11,%12,%13,%14,%15,"              \
        "%16,%17,%18,%19,%20,%21,%22,%23,%24,%25,%26,%27,%28,%29,%30,%31}, [%32];" \
        : "=r"((r)[0]),"=r"((r)[1]),"=r"((r)[2]),"=r"((r)[3]),                 \
          "=r"((r)[4]),"=r"((r)[5]),"=r"((r)[6]),"=r"((r)[7]),                 \
          "=r"((r)[8]),"=r"((r)[9]),"=r"((r)[10]),"=r"((r)[11]),               \
          "=r"((r)[12]),"=r"((r)[13]),"=r"((r)[14]),"=r"((r)[15]),             \
          "=r"((r)[16]),"=r"((r)[17]),"=r"((r)[18]),"=r"((r)[19]),             \
          "=r"((r)[20]),"=r"((r)[21]),"=r"((r)[22]),"=r"((r)[23]),             \
          "=r"((r)[24]),"=r"((r)[25]),"=r"((r)[26]),"=r"((r)[27]),             \
          "=r"((r)[28]),"=r"((r)[29]),"=r"((r)[30]),"=r"((r)[31])              \
        : "r"(addr))

#define TCGEN05_ST_X32(addr, r)                                                \
    asm volatile("tcgen05.st.sync.aligned.32x32b.x32.b32 [%0], "               \
        "{%1,%2,%3,%4,%5,%6,%7,%8,%9,%10,%11,%12,%13,%14,%15,%16,"             \
        "%17,%18,%19,%20,%21,%22,%23,%24,%25,%26,%27,%28,%29,%30,%31,%32};"    \
        :: "r"(addr),                                                          \
           "r"((r)[0]),"r"((r)[1]),"r"((r)[2]),"r"((r)[3]),                    \
           "r"((r)[4]),"r"((r)[5]),"r"((r)[6]),"r"((r)[7]),                    \
           "r"((r)[8]),"r"((r)[9]),"r"((r)[10]),"r"((r)[11]),                  \
           "r"((r)[12]),"r"((r)[13]),"r"((r)[14]),"r"((r)[15]),                \
           "r"((r)[16]),"r"((r)[17]),"r"((r)[18]),"r"((r)[19]),                \
           "r"((r)[20]),"r"((r)[21]),"r"((r)[22]),"r"((r)[23]),                \
           "r"((r)[24]),"r"((r)[25]),"r"((r)[26]),"r"((r)[27]),                \
           "r"((r)[28]),"r"((r)[29]),"r"((r)[30]),"r"((r)[31])                 \
        : "memory")

__device__ __forceinline__ void mma_tf32_ss(uint32_t d_tmem, uint64_t a_desc,
                                            uint64_t b_desc, uint32_t idesc,
                                            uint32_t enable) {
    asm volatile(
        "{\n\t.reg .pred p;\n\t"
        "setp.ne.u32 p, %4, 0;\n\t"
        "tcgen05.mma.cta_group::1.kind::tf32 [%0], %1, %2, %3, {%5,%5,%5,%5}, p;\n\t}"
        :: "r"(d_tmem), "l"(a_desc), "l"(b_desc), "r"(idesc), "r"(enable), "r"(0u)
        : "memory");
}
__device__ __forceinline__ void mma_tf32_ts(uint32_t d_tmem, uint32_t a_tmem,
                                            uint64_t b_desc, uint32_t idesc,
                                            uint32_t enable) {
    asm volatile(
        "{\n\t.reg .pred p;\n\t"
        "setp.ne.u32 p, %4, 0;\n\t"
        "tcgen05.mma.cta_group::1.kind::tf32 [%0], [%1], %2, %3, {%5,%5,%5,%5}, p;\n\t}"
        :: "r"(d_tmem), "r"(a_tmem), "l"(b_desc), "r"(idesc), "r"(enable), "r"(0u)
        : "memory");
}
#endif  // HAS_TCGEN05

// SW128 K-major descriptor base: layout=SW128(2), version=1, SBO=64, LBO=1
static constexpr uint64_t DESC_BASE =
    (2ull << 61) | (1ull << 46) | (64ull << 32) | (1ull << 16);

__device__ __forceinline__ uint32_t sw128(uint32_t off) {
    return off ^ ((off >> 3) & 0x70);
}

#define GK 32

// =================================================================
// GEMM (128x128 tile, GK=64, register-staged) — small projections.
// Two 16KB K-blocks per operand (attention-proven layout); NC=16
// halves per-chunk fixed costs. grid 128 < 148 SMs so occ-1 is free.
// =================================================================
#define GK2 64
#define G128_STAGE 65536                      // A 2x16K + B 2x16K
#define GEMM128_SMEM (2 * G128_STAGE + 1024)  // 132KB

__global__ __launch_bounds__(256, 1)
void gemm_tc128(const float* __restrict__ A, const float* __restrict__ W,
                float* __restrict__ C, const float* __restrict__ bias,
                int M, int N, int K)
{
#if HAS_TCGEN05
    extern __shared__ char smraw[];
    __shared__ uint64_t mbar[2];
    __shared__ uint32_t tmem_slot;

    const uint32_t smbase = (smem_u32(smraw) + 1023u) & ~1023u;
    const uint32_t bar0 = smem_u32(&mbar[0]);
    const uint32_t bar1 = smem_u32(&mbar[1]);
    const uint32_t slot = smem_u32(&tmem_slot);

    const int tid = threadIdx.x;
    const int wid = tid >> 5;
    const int lid = tid & 31;
    const int m0 = blockIdx.y * 128;
    const int n0 = blockIdx.x * 128;

    if (wid == 0) TCGEN05_ALLOC(slot, 128);
    if (tid == 0) { MBARRIER_INIT(bar0, 1); MBARRIER_INIT(bar1, 1); }
    __syncthreads();
    uint32_t tmem;
    asm volatile("ld.shared.b32 %0, [%1];" : "=r"(tmem) : "r"(slot));
    if (wid == 0) TCGEN05_RELINQ();

    const uint32_t IDESC = (1u << 4) | (2u << 7) | (2u << 10)
                         | ((128u / 8) << 17) | ((128u / 16) << 24);

    const int NC = K / GK2;                    // 16
    int ph0 = 0, ph1 = 0;

    // per-thread indices: i = tid + it*256; row = i>>4, f = i&15
    const int row_ = tid >> 4;                 // + it*16
    const int f_   = tid & 15;
    const int kc_  = f_ >> 3;                  // K-block (0/1)
    const int fo_  = f_ & 7;                   // float4 within 128B row
    const uint32_t sofs_ = (uint32_t)kc_ * 16384u;

    float4 ra[8], rb[8];
    // preload chunk 0 (64 floats per gemm-row; f_*4 = col)
    {
        const float* Ap = A + (size_t)m0 * K + f_ * 4;
        const float* Wp = W + (size_t)n0 * K + f_ * 4;
#pragma unroll
        for (int it = 0; it < 8; it++) {
            int row = row_ + it * 16;
            ra[it] = *(const float4*)(Ap + (size_t)row * K);
            rb[it] = *(const float4*)(Wp + (size_t)row * K);
        }
    }

    for (int c = 0; c < NC; c++) {
        const int buf = c & 1;
        const uint32_t barb = buf ? bar1 : bar0;
        if (c >= 2) {
            MBARRIER_WAIT_PARITY(barb, (buf ? ph1 : ph0));
            if (buf) ph1 ^= 1; else ph0 ^= 1;
        }
        const uint32_t sb = smbase + buf * G128_STAGE;

        // cvt+STS staged registers (A blocks @0/16K, B blocks @32K/48K)
#pragma unroll
        for (int it = 0; it < 8; it++) {
            int row = row_ + it * 16;
            float4 v = ra[it];
            uint32_t r0 = f2tf32(v.x), r1 = f2tf32(v.y),
                     r2 = f2tf32(v.z), r3 = f2tf32(v.w);
            uint32_t dst = sb + sofs_ + sw128((uint32_t)(row * 128 + fo_ * 16));
            asm volatile("st.shared.v4.b32 [%0], {%1,%2,%3,%4};"
                         :: "r"(dst), "r"(r0), "r"(r1), "r"(r2), "r"(r3) : "memory");
        }
#pragma unroll
        for (int it = 0; it < 8; it++) {
            int row = row_ + it * 16;
            float4 v = rb[it];
            uint32_t r0 = f2tf32(v.x), r1 = f2tf32(v.y),
                     r2 = f2tf32(v.z), r3 = f2tf32(v.w);
            uint32_t dst = sb + 32768u + sofs_ + sw128((uint32_t)(row * 128 + fo_ * 16));
            asm volatile("st.shared.v4.b32 [%0], {%1,%2,%3,%4};"
                         :: "r"(dst), "r"(r0), "r"(r1), "r"(r2), "r"(r3) : "memory");
        }

        // prefetch chunk c+1 — latency hides under MMA(c)
        if (c + 1 < NC) {
            const float* Ap = A + (size_t)m0 * K + (c + 1) * GK2 + f_ * 4;
            const float* Wp = W + (size_t)n0 * K + (c + 1) * GK2 + f_ * 4;
#pragma unroll
            for (int it = 0; it < 8; it++) {
                int row = row_ + it * 16;
                ra[it] = *(const float4*)(Ap + (size_t)row * K);
                rb[it] = *(const float4*)(Wp + (size_t)row * K);
            }
        }

        __syncthreads();

        if (wid == 0 && elect_one()) {
            FENCE_ASYNC();
#pragma unroll
            for (int kb = 0; kb < 2; kb++) {
                const uint64_t dA = DESC_BASE
                    | ((uint64_t)((sb + kb * 16384u) >> 4) & 0x3FFF);
                const uint64_t dB = DESC_BASE
                    | ((uint64_t)((sb + 32768u + kb * 16384u) >> 4) & 0x3FFF);
#pragma unroll
                for (int k = 0; k < 4; k++) {
                    uint32_t en = (c > 0 || kb > 0 || k > 0) ? 1u : 0u;
                    mma_tf32_ss(tmem, dA + k * 2, dB + k * 2, IDESC, en);
                }
            }
            TCGEN05_COMMIT(barb);
        }
    }

    MBARRIER_WAIT_PARITY(bar0, ph0);
    MBARRIER_WAIT_PARITY(bar1, ph1);
    TCGEN05_FENCE_AFTER();

    {
        const int colh = wid >> 2;
        const int sub  = wid & 3;
        const int r = sub * 32 + lid;
        float* Crow = C + (size_t)(m0 + r) * N + n0 + colh * 64;
        const float* bp = bias ? (bias + n0 + colh * 64) : nullptr;
#pragma unroll
        for (int half = 0; half < 2; half++) {
            uint32_t rr[32];
            TCGEN05_LD_X32(rr, tmem + colh * 64 + half * 32);
            TCGEN05_WAIT_LD();
#pragma unroll
            for (int j = 0; j < 32; j += 4) {
                float4 o;
                o.x = __uint_as_float(rr[j + 0]);
                o.y = __uint_as_float(rr[j + 1]);
                o.z = __uint_as_float(rr[j + 2]);
                o.w = __uint_as_float(rr[j + 3]);
                if (bp) {
                    o.x += bp[half * 32 + j + 0]; o.y += bp[half * 32 + j + 1];
                    o.z += bp[half * 32 + j + 2]; o.w += bp[half * 32 + j + 3];
                }
                *(float4*)(Crow + half * 32 + j) = o;
            }
        }
    }
    TCGEN05_FENCE_BEFORE();
    __syncthreads();
    if (wid == 0) TCGEN05_DEALLOC(tmem, 128);

#else
    __shared__ float As[8][128];
    __shared__ float Ws[8][128];
    const int tid  = threadIdx.x;
    const int ty   = tid >> 4;
    const int tx   = tid & 15;
    const int row0 = blockIdx.y * 128;
    const int col0 = blockIdx.x * 128;
    const int lrow = tid >> 1;
    const int lk   = (tid & 1) * 4;

    const float* Ap = A + (size_t)(row0 + lrow) * K + lk;
    const float* Wp = W + (size_t)(col0 + lrow) * K + lk;
    float acc[8][8];
#pragma unroll
    for (int i = 0; i < 8; i++)
#pragma unroll
        for (int j = 0; j < 8; j++) acc[i][j] = 0.0f;

    for (int k0 = 0; k0 < K; k0 += 8) {
        float4 av = *(const float4*)(Ap + k0);
        float4 wv = *(const float4*)(Wp + k0);
        As[lk + 0][lrow] = av.x; As[lk + 1][lrow] = av.y;
        As[lk + 2][lrow] = av.z; As[lk + 3][lrow] = av.w;
        Ws[lk + 0][lrow] = wv.x; Ws[lk + 1][lrow] = wv.y;
        Ws[lk + 2][lrow] = wv.z; Ws[lk + 3][lrow] = wv.w;
        __syncthreads();
#pragma unroll
        for (int k = 0; k < 8; k++) {
            float a[8], b[8];
            float4 t0 = *(const float4*)(&As[k][ty * 8 + 0]);
            float4 t1 = *(const float4*)(&As[k][ty * 8 + 4]);
            a[0]=t0.x;a[1]=t0.y;a[2]=t0.z;a[3]=t0.w;a[4]=t1.x;a[5]=t1.y;a[6]=t1.z;a[7]=t1.w;
            float4 u0 = *(const float4*)(&Ws[k][tx * 8 + 0]);
            float4 u1 = *(const float4*)(&Ws[k][tx * 8 + 4]);
            b[0]=u0.x;b[1]=u0.y;b[2]=u0.z;b[3]=u0.w;b[4]=u1.x;b[5]=u1.y;b[6]=u1.z;b[7]=u1.w;
#pragma unroll
            for (int i = 0; i < 8; i++)
#pragma unroll
                for (int j = 0; j < 8; j++) acc[i][j] += a[i] * b[j];
        }
        __syncthreads();
    }
#pragma unroll
    for (int i = 0; i < 8; i++) {
        const size_t r = (size_t)(row0 + ty * 8 + i);
#pragma unroll
        for (int j = 0; j < 8; j++) {
            const int cc = col0 + tx * 8 + j;
            float v = acc[i][j];
            if (bias) v += bias[cc];
            C[r * N + cc] = v;
        }
    }
#endif
}

// =================================================================
// GEMM (256x256 tile, 2-stage, register-staged loads) — kv projection
// with fused V^T epilogue (r15-proven, ~275us). Byte-identical.
// =================================================================
#define A256_BYTES 32768
#define B256_BYTES 32768
#define STAGE256 (A256_BYTES + B256_BYTES)       // 64KB
#define GEMMKV_SMEM (2 * STAGE256 + 1024)        // 129KB

__global__ __launch_bounds__(256, 1)
void gemm_tc_kv(const float* __restrict__ A, const float* __restrict__ W,
                float* __restrict__ C, float* __restrict__ vtb,
                int M, int N, int K)
{
#if HAS_TCGEN05
    extern __shared__ char smraw[];
    __shared__ uint64_t mbar[2];
    __shared__ uint32_t tmem_slot;

    const uint32_t smbase = (smem_u32(smraw) + 1023u) & ~1023u;
    const uint32_t bar0 = smem_u32(&mbar[0]);
    const uint32_t bar1 = smem_u32(&mbar[1]);
    const uint32_t slot = smem_u32(&tmem_slot);

    const int tid = threadIdx.x;
    const int wid = tid >> 5;
    const int lid = tid & 31;
    const int m0 = blockIdx.y * 256;
    const int n0 = blockIdx.x * 256;

    if (wid == 0) TCGEN05_ALLOC(slot, 512);
    if (tid == 0) { MBARRIER_INIT(bar0, 1); MBARRIER_INIT(bar1, 1); }
    __syncthreads();
    uint32_t tmem;
    asm volatile("ld.shared.b32 %0, [%1];" : "=r"(tmem) : "r"(slot));
    if (wid == 0) TCGEN05_RELINQ();

    const uint32_t IDESC = (1u << 4) | (2u << 7) | (2u << 10)
                         | ((256u / 8) << 17) | ((128u / 16) << 24);

    const int NC = K / GK;
    int ph0 = 0, ph1 = 0;

    const int row_ = tid >> 3;
    const int fo_  = tid & 7;

    float4 ra[8], rb[8];
    {
        const float* Ap = A + (size_t)m0 * K;
        const float* Wp = W + (size_t)n0 * K;
#pragma unroll
        for (int it = 0; it < 8; it++) {
            int row = row_ + it * 32;
            ra[it] = *(const float4*)(Ap + (size_t)row * K + fo_ * 4);
            rb[it] = *(const float4*)(Wp + (size_t)row * K + fo_ * 4);
        }
    }

    for (int c = 0; c < NC; c++) {
        const int buf = c & 1;
        const uint32_t barb = buf ? bar1 : bar0;
        if (c >= 2) {
            MBARRIER_WAIT_PARITY(barb, (buf ? ph1 : ph0));
            if (buf) ph1 ^= 1; else ph0 ^= 1;
        }
        const uint32_t sb = smbase + buf * STAGE256;

#pragma unroll
        for (int it = 0; it < 8; it++) {
            int row = row_ + it * 32;
            float4 v = ra[it];
            uint32_t r0 = f2tf32(v.x), r1 = f2tf32(v.y),
                     r2 = f2tf32(v.z), r3 = f2tf32(v.w);
            uint32_t off = sw128((uint32_t)((row & 127) * 128 + fo_ * 16));
            uint32_t dst = sb + ((row < 128) ? 0u : 16384u) + off;
            asm volatile("st.shared.v4.b32 [%0], {%1,%2,%3,%4};"
                         :: "r"(dst), "r"(r0), "r"(r1), "r"(r2), "r"(r3) : "memory");
        }
#pragma unroll
        for (int it = 0; it < 8; it++) {
            int row = row_ + it * 32;
            float4 v = rb[it];
            uint32_t r0 = f2tf32(v.x), r1 = f2tf32(v.y),
                     r2 = f2tf32(v.z), r3 = f2tf32(v.w);
            uint32_t dst = sb + A256_BYTES + sw128((uint32_t)(row * 128 + fo_ * 16));
            asm volatile("st.shared.v4.b32 [%0], {%1,%2,%3,%4};"
                         :: "r"(dst), "r"(r0), "r"(r1), "r"(r2), "r"(r3) : "memory");
        }

        if (c + 1 < NC) {
            const float* Ap = A + (size_t)m0 * K + (c + 1) * GK;
            const float* Wp = W + (size_t)n0 * K + (c + 1) * GK;
#pragma unroll
            for (int it = 0; it < 8; it++) {
                int row = row_ + it * 32;
                ra[it] = *(const float4*)(Ap + (size_t)row * K + fo_ * 4);
                rb[it] = *(const float4*)(Wp + (size_t)row * K + fo_ * 4);
            }
        }

        __syncthreads();

        if (wid == 0 && elect_one()) {
            FENCE_ASYNC();
            const uint64_t dA0 = DESC_BASE | ((uint64_t)(sb >> 4) & 0x3FFF);
            const uint64_t dA1 = DESC_BASE | ((uint64_t)((sb + 16384u) >> 4) & 0x3FFF);
            const uint64_t dB  = DESC_BASE | ((uint64_t)((sb + A256_BYTES) >> 4) & 0x3FFF);
#pragma unroll
            for (int k = 0; k < 4; k++) {
                uint32_t en = (c > 0 || k > 0) ? 1u : 0u;
                mma_tf32_ss(tmem,       dA0 + k * 2, dB + k * 2, IDESC, en);
                mma_tf32_ss(tmem + 256, dA1 + k * 2, dB + k * 2, IDESC, en);
            }
            TCGEN05_COMMIT(barb);
        }
    }

    MBARRIER_WAIT_PARITY(bar0, ph0);
    MBARRIER_WAIT_PARITY(bar1, ph1);
    TCGEN05_FENCE_AFTER();

    {
        const int tile = wid >> 2;
        const uint32_t dbase = tmem + tile * 256;
        const int rowl = (wid & 3) * 32 + lid;
        const size_t grow = (size_t)m0 + tile * 128 + rowl;    // global row = b*SEQ + s

        if (vtb && n0 >= DIM) {
            const int s  = (int)(grow & (SEQ - 1));
            const int bq = (int)(grow >> 13);
            const size_t vb0 = (size_t)bq * NHEADS * HDIM;
#pragma unroll
            for (int cb = 0; cb < 8; cb++) {
                uint32_t rr[32];
                TCGEN05_LD_X32(rr, dbase + cb * 32);
                TCGEN05_WAIT_LD();
#pragma unroll
                for (int j = 0; j < 32; j++) {
                    const int dcol = (n0 - DIM) + cb * 32 + j;
                    vtb[(vb0 + (size_t)dcol) * SEQ + s] =
                        __uint_as_float(f2tf32(__uint_as_float(rr[j])));
                }
            }
        } else {
            float* Crow = C + grow * N + n0;
#pragma unroll
            for (int cb = 0; cb < 8; cb++) {
                uint32_t rr[32];
                TCGEN05_LD_X32(rr, dbase + cb * 32);
                TCGEN05_WAIT_LD();
#pragma unroll
                for (int j = 0; j < 32; j += 4) {
                    float4 o;
                    o.x = __uint_as_float(rr[j + 0]);
                    o.y = __uint_as_float(rr[j + 1]);
                    o.z = __uint_as_float(rr[j + 2]);
                    o.w = __uint_as_float(rr[j + 3]);
                    *(float4*)(Crow + cb * 32 + j) = o;
                }
            }
        }
    }
    TCGEN05_FENCE_BEFORE();
    __syncthreads();
    if (wid == 0) TCGEN05_DEALLOC(tmem, 512);

#else
    // SIMT fallback: 2x2 subtiles of 128x128 with fused vt on V columns
    __shared__ float As[8][128];
    __shared__ float Ws[8][128];
    const int tid  = threadIdx.x;
    const int ty   = tid >> 4;
    const int tx   = tid & 15;
    const int lrow = tid >> 1;
    const int lk   = (tid & 1) * 4;

    for (int hm = 0; hm < 2; hm++)
    for (int hn = 0; hn < 2; hn++) {
        const int row0 = blockIdx.y * 256 + hm * 128;
        const int col0 = blockIdx.x * 256 + hn * 128;
        const float* Ap = A + (size_t)(row0 + lrow) * K + lk;
        const float* Wp = W + (size_t)(col0 + lrow) * K + lk;
        float acc[8][8];
#pragma unroll
        for (int i = 0; i < 8; i++)
#pragma unroll
            for (int j = 0; j < 8; j++) acc[i][j] = 0.0f;

        for (int k0 = 0; k0 < K; k0 += 8) {
            float4 av = *(const float4*)(Ap + k0);
            float4 wv = *(const float4*)(Wp + k0);
            As[lk + 0][lrow] = av.x; As[lk + 1][lrow] = av.y;
            As[lk + 2][lrow] = av.z; As[lk + 3][lrow] = av.w;
            Ws[lk + 0][lrow] = wv.x; Ws[lk + 1][lrow] = wv.y;
            Ws[lk + 2][lrow] = wv.z; Ws[lk + 3][lrow] = wv.w;
            __syncthreads();
#pragma unroll
            for (int k = 0; k < 8; k++) {
                float a[8], b[8];
                float4 t0 = *(const float4*)(&As[k][ty * 8 + 0]);
                float4 t1 = *(const float4*)(&As[k][ty * 8 + 4]);
                a[0]=t0.x;a[1]=t0.y;a[2]=t0.z;a[3]=t0.w;a[4]=t1.x;a[5]=t1.y;a[6]=t1.z;a[7]=t1.w;
                float4 u0 = *(const float4*)(&Ws[k][tx * 8 + 0]);
                float4 u1 = *(const float4*)(&Ws[k][tx * 8 + 4]);
                b[0]=u0.x;b[1]=u0.y;b[2]=u0.z;b[3]=u0.w;b[4]=u1.x;b[5]=u1.y;b[6]=u1.z;b[7]=u1.w;
#pragma unroll
                for (int i = 0; i < 8; i++)
#pragma unroll
                    for (int j = 0; j < 8; j++) acc[i][j] += a[i] * b[j];
            }
            __syncthreads();
        }
#pragma unroll
        for (int i = 0; i < 8; i++) {
            const size_t grow = (size_t)(row0 + ty * 8 + i);
#pragma unroll
            for (int j = 0; j < 8; j++) {
                const int cc = col0 + tx * 8 + j;
                if (vtb && cc >= DIM) {
                    const int s  = (int)(grow & (SEQ - 1));
                    const int bq = (int)(grow >> 13);
                    vtb[((size_t)bq * NHEADS * HDIM + (cc - DIM)) * SEQ + s] =
                        __uint_as_float(f2tf32(acc[i][j]));
                } else {
                    C[grow * N + cc] = acc[i][j];
                }
            }
        }
        __syncthreads();
    }
#endif
}

// =================================================================
// Tensor-core flash attention — round-9 version (proven 251us).
// =================================================================
#define SCHUNK 128
#define NCH (SEQ / SCHUNK)
#define ATTN_SMEM (3 * 32768 + 1024)
#define SCALE_L2E 0.18033688011112042f   // SCALE * log2(e)

__global__ __launch_bounds__(256, 2)
void attn_tc(const float* __restrict__ q, const float* __restrict__ kv,
             const float* __restrict__ vt, float* __restrict__ out)
{
#if HAS_TCGEN05
    extern __shared__ char smraw[];
    __shared__ uint64_t mbar[2];
    __shared__ uint32_t tmem_slot;
    __shared__ float ls_sh[256];

    const uint32_t smbase = (smem_u32(smraw) + 1023u) & ~1023u;
    const uint32_t QS = smbase;
    const uint32_t KS = smbase + 32768u;
    const uint32_t VS = smbase + 65536u;
    const uint32_t barQK = smem_u32(&mbar[0]);
    const uint32_t barPV = smem_u32(&mbar[1]);
    const uint32_t slot  = smem_u32(&tmem_slot);

    const int tid = threadIdx.x;
    const int wid = tid >> 5;
    const int lid = tid & 31;
    const int bh  = blockIdx.x >> 2;
    const int lt  = blockIdx.x & 3;
    const int b   = bh >> 4, h = bh & 15;
    const int l0  = lt * 128;

    if (wid == 0) TCGEN05_ALLOC(slot, 256);
    if (tid == 0) { MBARRIER_INIT(barQK, 1); MBARRIER_INIT(barPV, 1); }
    __syncthreads();
    uint32_t tmem;
    asm volatile("ld.shared.b32 %0, [%1];" : "=r"(tmem) : "r"(slot));
    if (wid == 0) TCGEN05_RELINQ();
    const uint32_t tmem_SP = tmem;
    const uint32_t tmem_O  = tmem + 128;

    const uint32_t IDESC_S = (1u << 4) | (2u << 7) | (2u << 10)
                           | ((128u / 8) << 17) | ((128u / 16) << 24);
    const uint32_t IDESC_O = (1u << 4) | (2u << 7) | (2u << 10)
                           | ((64u / 8) << 17) | ((128u / 16) << 24);

    const float* kbase = kv + (size_t)b * SEQ * (2 * DIM) + h * HDIM;
    const float* vbase = vt + ((size_t)bh * HDIM) * SEQ;

    const float* qbase = q + ((size_t)b * LAT + l0) * DIM + h * HDIM;
#pragma unroll
    for (int it = 0; it < 8; it++) {
        int i = tid + it * 256;
        int row = i >> 4, f = i & 15;
        int kc = f >> 3, fo = f & 7;
        float4 v = *(const float4*)(qbase + (size_t)row * DIM + f * 4);
        uint32_t r0 = f2tf32(v.x * SCALE_L2E), r1 = f2tf32(v.y * SCALE_L2E);
        uint32_t r2 = f2tf32(v.z * SCALE_L2E), r3 = f2tf32(v.w * SCALE_L2E);
        uint32_t dst = QS + kc * 16384u + sw128((uint32_t)(row * 128 + fo * 16));
        asm volatile("st.shared.v4.b32 [%0], {%1,%2,%3,%4};"
                     :: "r"(dst), "r"(r0), "r"(r1), "r"(r2), "r"(r3) : "memory");
    }

    auto loadK = [&](int ci) {
        const int s0 = ci * SCHUNK;
#pragma unroll
        for (int it = 0; it < 8; it++) {
            int i = tid + it * 256;
            int kr = i >> 4, f = i & 15;
            int kc = f >> 3, fo = f & 7;
            float4 v = *(const float4*)(kbase + (size_t)(s0 + kr) * (2 * DIM) + f * 4);
            uint32_t r0 = f2tf32(v.x), r1 = f2tf32(v.y),
                     r2 = f2tf32(v.z), r3 = f2tf32(v.w);
            uint32_t dst = KS + kc * 16384u + sw128((uint32_t)(kr * 128 + fo * 16));
            asm volatile("st.shared.v4.b32 [%0], {%1,%2,%3,%4};"
                         :: "r"(dst), "r"(r0), "r"(r1), "r"(r2), "r"(r3) : "memory");
        }
    };
    auto loadVT = [&](int ci) {
        const int s0 = ci * SCHUNK;
#pragma unroll
        for (int it = 0; it < 8; it++) {
            int i = tid + it * 256;
            int d = i >> 5, f = i & 31;
            int sc = f >> 3, fo = f & 7;
            float4 v = *(const float4*)(vbase + (size_t)d * SEQ + s0 + f * 4);
            uint32_t dst = VS + sc * 8192u + sw128((uint32_t)(d * 128 + fo * 16));
            asm volatile("st.shared.v4.b32 [%0], {%1,%2,%3,%4};"
                         :: "r"(dst), "r"(__float_as_uint(v.x)), "r"(__float_as_uint(v.y)),
                            "r"(__float_as_uint(v.z)), "r"(__float_as_uint(v.w)) : "memory");
        }
    };

    const uint64_t dQ0 = DESC_BASE | ((uint64_t)(QS >> 4) & 0x3FFF);
    const uint64_t dQ1 = DESC_BASE | ((uint64_t)((QS + 16384u) >> 4) & 0x3FFF);
    const uint64_t dK0 = DESC_BASE | ((uint64_t)(KS >> 4) & 0x3FFF);
    const uint64_t dK1 = DESC_BASE | ((uint64_t)((KS + 16384u) >> 4) & 0x3FFF);

    float lsum = 0.0f;
    int phQK = 0, phPV = 0;

    loadK(0);
    loadVT(0);
    __syncthreads();

    for (int ci = 0; ci < NCH; ci++) {
        if (wid == 0 && elect_one()) {
            FENCE_ASYNC();
#pragma unroll
            for (int blk = 0; blk < 2; blk++) {
                const uint64_t dq = blk ? dQ1 : dQ0;
                const uint64_t dk = blk ? dK1 : dK0;
#pragma unroll
                for (int ks = 0; ks < 4; ks++)
                    mma_tf32_ss(tmem_SP, dq + ks * 2, dk + ks * 2, IDESC_S,
                                (blk > 0 || ks > 0) ? 1u : 0u);
            }
            TCGEN05_COMMIT(barQK);
        }
        MBARRIER_WAIT_PARITY(barQK, phQK); phQK ^= 1;
        TCGEN05_FENCE_AFTER();

        {
            const uint32_t colofs = (uint32_t)(wid >> 2) * 64u;
            const uint32_t wlane  = (uint32_t)(wid & 3) << 21;
#pragma unroll
            for (int blk = 0; blk < 2; blk++) {
                uint32_t rr[32];
                TCGEN05_LD_X32(rr, tmem_SP + colofs + blk * 32);
                TCGEN05_WAIT_LD();
#pragma unroll
                for (int j = 0; j < 32; j++) {
                    float p;
                    asm("ex2.approx.f32 %0, %1;" : "=f"(p) : "f"(__uint_as_float(rr[j])));
                    lsum += p;
                    rr[j] = f2tf32(p);
                }
                TCGEN05_ST_X32(tmem_SP + wlane + colofs + blk * 32, rr);
            }
            TCGEN05_WAIT_ST();
        }
        TCGEN05_FENCE_BEFORE();
        __syncthreads();

        if (wid == 0 && elect_one()) {
            TCGEN05_FENCE_AFTER();
            FENCE_ASYNC();
#pragma unroll
            for (int st = 0; st < 16; st++) {
                const uint64_t dV = DESC_BASE
                    | ((uint64_t)((VS + (st >> 2) * 8192u) >> 4) & 0x3FFF);
                mma_tf32_ts(tmem_O, tmem_SP + st * 8, dV + (st & 3) * 2, IDESC_O,
                            (ci > 0 || st > 0) ? 1u : 0u);
            }
            TCGEN05_COMMIT(barPV);
        }

        if (ci + 1 < NCH) loadK(ci + 1);
        MBARRIER_WAIT_PARITY(barPV, phPV); phPV ^= 1;
        if (ci + 1 < NCH) loadVT(ci + 1);
        __syncthreads();
    }

    TCGEN05_FENCE_AFTER();

    ls_sh[tid] = lsum;
    __syncthreads();

    if (wid < 4) {
        const int r = wid * 32 + lid;
        const float inv = 1.0f / (ls_sh[tid] + ls_sh[tid + 128]);
        float* op = out + ((size_t)b * LAT + l0 + r) * DIM + h * HDIM;
#pragma unroll
        for (int cb = 0; cb < 2; cb++) {
            uint32_t rr[32];
            TCGEN05_LD_X32(rr, tmem_O + cb * 32);
            TCGEN05_WAIT_LD();
#pragma unroll
            for (int j = 0; j < 32; j += 4) {
                float4 o;
                o.x = __uint_as_float(rr[j + 0]) * inv;
                o.y = __uint_as_float(rr[j + 1]) * inv;
                o.z = __uint_as_float(rr[j + 2]) * inv;
                o.w = __uint_as_float(rr[j + 3]) * inv;
                *(float4*)(op + cb * 32 + j) = o;
            }
        }
    }
    TCGEN05_FENCE_BEFORE();
    __syncthreads();
    if (wid == 0) TCGEN05_DEALLOC(tmem, 256);

#else
    // SIMT fallback (thread-per-row; never runs on GB300)
    const int tid = threadIdx.x;
    const int bh  = blockIdx.x >> 2;
    const int lt  = blockIdx.x & 3;
    const int b   = bh >> 4, h = bh & 15;
    const int l0  = lt * 128;
    if (tid < 128) {
        const float* qrow = q + ((size_t)b * LAT + l0 + tid) * DIM + h * HDIM;
        const float* kb = kv + (size_t)b * SEQ * (2 * DIM) + h * HDIM;
        const float* vb = vt + ((size_t)bh * HDIM) * SEQ;
        float qr[64];
#pragma unroll
        for (int d = 0; d < 64; d++) qr[d] = qrow[d] * SCALE;
        float O[64];
#pragma unroll
        for (int d = 0; d < 64; d++) O[d] = 0.0f;
        float l = 0.0f;
        for (int s = 0; s < SEQ; s++) {
            const float* kr = kb + (size_t)s * (2 * DIM);
            float sv = 0.0f;
#pragma unroll 16
            for (int d = 0; d < 64; d++) sv += qr[d] * kr[d];
            float p = __expf(sv);
            l += p;
#pragma unroll 16
            for (int d = 0; d < 64; d++) O[d] += p * vb[(size_t)d * SEQ + s];
        }
        float* op = out + ((size_t)b * LAT + l0 + tid) * DIM + h * HDIM;
        float inv = 1.0f / l;
#pragma unroll
        for (int d = 0; d < 64; d++) op[d] = O[d] * inv;
    }
#endif
}

// =================================================================
// launch
// =================================================================
extern "C" void kernel_launch(void* const* d_in, const int* in_sizes, int n_in,
                              void* d_out, int out_size)
{
    const float* x       = (const float*)d_in[0];
    const float* latents = (const float*)d_in[1];
    if (in_sizes[0] != BATCH * SEQ * DIM) {
        x       = (const float*)d_in[1];
        latents = (const float*)d_in[0];
    }
    const float* w_q   = (const float*)d_in[2];
    const float* w_kv  = (const float*)d_in[3];
    const float* w_out = (const float*)d_in[4];
    const float* b_out = (const float*)d_in[5];
    float* out = (float*)d_out;

    float *q, *kvbuf, *att, *vt;
    cudaGetSymbolAddress((void**)&q,     g_q);
    cudaGetSymbolAddress((void**)&kvbuf, g_kv);
    cudaGetSymbolAddress((void**)&att,   g_att);
    cudaGetSymbolAddress((void**)&vt,    g_vt);

    const int M_q  = BATCH * LAT;    // 2048
    const int M_kv = BATCH * SEQ;    // 32768

    cudaFuncSetAttribute(gemm_tc128, cudaFuncAttributeMaxDynamicSharedMemorySize, GEMM128_SMEM);
    cudaFuncSetAttribute(gemm_tc_kv, cudaFuncAttributeMaxDynamicSharedMemorySize, GEMMKV_SMEM);
    cudaFuncSetAttribute(attn_tc,    cudaFuncAttributeMaxDynamicSharedMemorySize, ATTN_SMEM);

    // 1) q = latents @ w_q^T        (2048 x 1024), 128 CTAs, GK=64 reg-staged
    gemm_tc128<<<dim3(DIM / 128, M_q / 128), 256, GEMM128_SMEM>>>(
        latents, w_q, q, nullptr, M_q, DIM, DIM);
    // 2) kv = x @ w_kv^T            (32768 x 2048), 1024 CTAs, 2-stage,
    //    register-staged loads; V half goes straight to vt (tf32, transposed)
    gemm_tc_kv<<<dim3(2 * DIM / 256, M_kv / 256), 256, GEMMKV_SMEM>>>(
        x, w_kv, kvbuf, vt, M_kv, 2 * DIM, DIM);
    // 3) attention
    attn_tc<<<BATCH * NHEADS * (LAT / 128), 256, ATTN_SMEM>>>(q, kvbuf, vt, att);
    // 4) out = att @ w_out^T + b_out, 128 CTAs, GK=64 reg-staged
    gemm_tc128<<<dim3(DIM / 128, M_q / 128), 256, GEMM128_SMEM>>>(
        att, w_out, out, b_out, M_q, DIM, DIM);
}